// round 5
// baseline (speedup 1.0000x reference)
#include <cuda_runtime.h>
#include <cuda_bf16.h>
#include <stdint.h>

#define BB 8
#define CC 512
#define NN 4096
#define II 128

// ---------------- scratch (__device__ globals; no allocation allowed) -------
__device__ __nv_bfloat16 g_xs_h[(size_t)BB * NN * CC];
__device__ __nv_bfloat16 g_xs_l[(size_t)BB * NN * CC];
__device__ __nv_bfloat16 g_wv_h[CC * CC], g_wv_l[CC * CC];
__device__ __nv_bfloat16 g_wq_h[II * CC], g_wq_l[II * CC];
__device__ __nv_bfloat16 g_wk_h[II * CC], g_wk_l[II * CC];
__device__ __nv_bfloat16 g_wu_h[CC * CC], g_wu_l[CC * CC];
__device__ __nv_bfloat16 g_q_h[(size_t)BB * NN * II], g_q_l[(size_t)BB * NN * II];
__device__ __nv_bfloat16 g_k_h[(size_t)BB * NN * II], g_k_l[(size_t)BB * NN * II];
__device__ __nv_bfloat16 g_vT_h[(size_t)BB * CC * NN], g_vT_l[(size_t)BB * CC * NN];
__device__ float         g_rel[(size_t)BB * NN * NN];
__device__ __nv_bfloat16 g_P_h[(size_t)BB * NN * NN], g_P_l[(size_t)BB * NN * NN];
__device__ __nv_bfloat16 g_y_h[(size_t)BB * NN * CC], g_y_l[(size_t)BB * NN * CC];
__device__ float         g_u[(size_t)BB * CC * NN];
__device__ float g_mean[CC], g_rstd[CC];
__device__ float g_rdist[8192];   // 1/(sqrt(d2)+1), d2 <= 2*63^2

// ---------------- PTX helpers (portable, non-'a' features only) -------------
__device__ __forceinline__ uint32_t s2u(const void* p) {
    uint32_t a;
    asm("{ .reg .u64 t; cvta.to.shared.u64 t, %1; cvt.u32.u64 %0, t; }" : "=r"(a) : "l"(p));
    return a;
}
__device__ __forceinline__ void cpa16(uint32_t s, const void* g) {
    asm volatile("cp.async.cg.shared.global [%0], [%1], 16;" :: "r"(s), "l"(g) : "memory");
}
__device__ __forceinline__ void cpa_commit() { asm volatile("cp.async.commit_group;" ::: "memory"); }
template <int W> __device__ __forceinline__ void cpa_wait() {
    asm volatile("cp.async.wait_group %0;" :: "n"(W) : "memory");
}
__device__ __forceinline__ void ldsm4(uint32_t* r, uint32_t addr) {
    asm volatile("ldmatrix.sync.aligned.m8n8.x4.shared.b16 {%0,%1,%2,%3}, [%4];"
                 : "=r"(r[0]), "=r"(r[1]), "=r"(r[2]), "=r"(r[3]) : "r"(addr));
}
__device__ __forceinline__ void mma_bf16(float* d, const uint32_t* a, const uint32_t* b) {
    asm volatile(
        "mma.sync.aligned.m16n8k16.row.col.f32.bf16.bf16.f32 "
        "{%0,%1,%2,%3}, {%4,%5,%6,%7}, {%8,%9}, {%0,%1,%2,%3};"
        : "+f"(d[0]), "+f"(d[1]), "+f"(d[2]), "+f"(d[3])
        : "r"(a[0]), "r"(a[1]), "r"(a[2]), "r"(a[3]), "r"(b[0]), "r"(b[1]));
}
__device__ __forceinline__ void split_pk(float a, float b, uint32_t& hi, uint32_t& lo) {
    __nv_bfloat162 h, l;
    h.x = __float2bfloat16(a); h.y = __float2bfloat16(b);
    l.x = __float2bfloat16(a - __bfloat162float(h.x));
    l.y = __float2bfloat16(b - __bfloat162float(h.y));
    hi = *reinterpret_cast<uint32_t*>(&h);
    lo = *reinterpret_cast<uint32_t*>(&l);
}

// ---------------- split-bf16 HMMA GEMM ---------------------------------------
// C[M,N] = A[M,K] * B[N,K]^T ; A,B given as (hi,lo) bf16 pairs, K-major, ld==K.
// CTA tile 128x128, K-chunk 32, 16 warps (4m x 4n), warp tile 32x32.
// modes: 0 = fp32 out, 1 = fp32 * (1/dist) out, 2 = bf16 (hi,lo) pair out.
#define ROWB 80                    // padded row stride bytes (32 bf16 -> 80B)
#define ARR (128 * ROWB)           // one operand array per stage
#define STG (4 * ARR)              // Ah, Al, Bh, Bl

__global__ void __launch_bounds__(512, 1)
gemm_mma(const __nv_bfloat16* __restrict__ Ah_, const __nv_bfloat16* __restrict__ Al_,
         const __nv_bfloat16* __restrict__ Bh_, const __nv_bfloat16* __restrict__ Bl_,
         int K, long a_batch, long b_batch,
         float* __restrict__ Cf,
         __nv_bfloat16* __restrict__ Chi, __nv_bfloat16* __restrict__ Clo,
         long c_batch, int Nld, int mode)
{
    extern __shared__ char smem[];
    const uint32_t sb = s2u(smem);
    const int tid = threadIdx.x;
    const int wid = tid >> 5;
    const int lane = tid & 31;
    const int bz = blockIdx.z;
    const int m0 = blockIdx.y * 128;
    const int n0 = blockIdx.x * 128;
    const int warp_m = wid >> 2;     // 0..3
    const int warp_n = wid & 3;      // 0..3

    const __nv_bfloat16* Ah = Ah_ + (size_t)bz * a_batch + (size_t)m0 * K;
    const __nv_bfloat16* Al = Al_ + (size_t)bz * a_batch + (size_t)m0 * K;
    const __nv_bfloat16* Bh = Bh_ + (size_t)bz * b_batch + (size_t)n0 * K;
    const __nv_bfloat16* Bl = Bl_ + (size_t)bz * b_batch + (size_t)n0 * K;

    const int nch = K >> 5;

    auto load_chunk = [&](int ci, int stg) {
        const uint32_t st = sb + stg * STG;
        const size_t k0 = (size_t)ci * 32;
        const int r = tid >> 2, sgs = tid & 3;            // 128 rows x 4 sectors
        const uint32_t so = (uint32_t)r * ROWB + sgs * 16;
        const size_t go = (size_t)r * K + k0 + sgs * 8;
        cpa16(st +           so, Ah + go);
        cpa16(st + ARR +     so, Al + go);
        cpa16(st + 2 * ARR + so, Bh + go);
        cpa16(st + 3 * ARR + so, Bl + go);
        cpa_commit();
    };

    load_chunk(0, 0);
    if (nch > 1) load_chunk(1, 1);

    // lane offsets for ldmatrix (bytes)
    const int lt = lane & 7, ltile = lane >> 3;
    const uint32_t aLane = (uint32_t)(lt + ((ltile & 1) << 3)) * ROWB + ((ltile >> 1) << 4);
    const uint32_t bLane = (uint32_t)(lt + ((ltile >> 1) << 3)) * ROWB + ((ltile & 1) << 4);

    float acc[2][4][4];
#pragma unroll
    for (int i = 0; i < 2; i++)
#pragma unroll
        for (int j = 0; j < 4; j++)
#pragma unroll
            for (int c = 0; c < 4; c++) acc[i][j][c] = 0.f;

    for (int i = 0; i < nch; i++) {
        const int b = i & 1;
        const uint32_t st = sb + b * STG;
        if (i + 1 < nch) cpa_wait<1>(); else cpa_wait<0>();
        __syncthreads();

        const uint32_t aBh = st +           (uint32_t)warp_m * 32 * ROWB + aLane;
        const uint32_t aBl = st + ARR +     (uint32_t)warp_m * 32 * ROWB + aLane;
        const uint32_t bBh = st + 2 * ARR + (uint32_t)warp_n * 32 * ROWB + bLane;
        const uint32_t bBl = st + 3 * ARR + (uint32_t)warp_n * 32 * ROWB + bLane;

#pragma unroll
        for (int ks = 0; ks < 2; ks++) {
            uint32_t aH[2][4], aL[2][4], bH[2][4], bL[2][4];
#pragma unroll
            for (int mt = 0; mt < 2; mt++) {
                ldsm4(aH[mt], aBh + mt * 16 * ROWB + ks * 32);
                ldsm4(aL[mt], aBl + mt * 16 * ROWB + ks * 32);
            }
#pragma unroll
            for (int np = 0; np < 2; np++) {   // each covers 2 n-tiles
                ldsm4(bH[np], bBh + np * 16 * ROWB + ks * 32);
                ldsm4(bL[np], bBl + np * 16 * ROWB + ks * 32);
            }
            // 8 independent accumulators per product set
#pragma unroll
            for (int mt = 0; mt < 2; mt++)
#pragma unroll
                for (int nt = 0; nt < 4; nt++)
                    mma_bf16(acc[mt][nt], aH[mt], &bH[nt >> 1][(nt & 1) * 2]);
#pragma unroll
            for (int mt = 0; mt < 2; mt++)
#pragma unroll
                for (int nt = 0; nt < 4; nt++)
                    mma_bf16(acc[mt][nt], aH[mt], &bL[nt >> 1][(nt & 1) * 2]);
#pragma unroll
            for (int mt = 0; mt < 2; mt++)
#pragma unroll
                for (int nt = 0; nt < 4; nt++)
                    mma_bf16(acc[mt][nt], aL[mt], &bH[nt >> 1][(nt & 1) * 2]);
        }
        __syncthreads();
        if (i + 2 < nch) load_chunk(i + 2, b);
    }

    // ---- epilogue ----
    const int gp = lane >> 2, tq = lane & 3;
    const int mbase = m0 + warp_m * 32;
    const int nbase = n0 + warp_n * 32;

#pragma unroll
    for (int mt = 0; mt < 2; mt++) {
#pragma unroll
        for (int half = 0; half < 2; half++) {
            const int r = mbase + mt * 16 + half * 8 + gp;
            if (mode == 2) {
                __nv_bfloat16* oh = Chi + (size_t)bz * c_batch + (size_t)r * Nld;
                __nv_bfloat16* ol = Clo + (size_t)bz * c_batch + (size_t)r * Nld;
#pragma unroll
                for (int nt = 0; nt < 4; nt++) {
                    const int col = nbase + nt * 8 + 2 * tq;
                    uint32_t hi, lo;
                    split_pk(acc[mt][nt][half * 2], acc[mt][nt][half * 2 + 1], hi, lo);
                    *(uint32_t*)(oh + col) = hi;
                    *(uint32_t*)(ol + col) = lo;
                }
            } else {
                float* oc = Cf + (size_t)bz * c_batch + (size_t)r * Nld;
                if (mode == 1) {
                    const int ri = r >> 6, rj = r & 63;
#pragma unroll
                    for (int nt = 0; nt < 4; nt++) {
                        const int col = nbase + nt * 8 + 2 * tq;
                        int di0 = ri - (col >> 6);
                        int j0 = rj - (col & 63);
                        int j1 = rj - ((col + 1) & 63);
                        float2 o;
                        o.x = acc[mt][nt][half * 2]     * g_rdist[di0 * di0 + j0 * j0];
                        o.y = acc[mt][nt][half * 2 + 1] * g_rdist[di0 * di0 + j1 * j1];
                        *(float2*)(oc + col) = o;
                    }
                } else {
#pragma unroll
                    for (int nt = 0; nt < 4; nt++) {
                        const int col = nbase + nt * 8 + 2 * tq;
                        float2 o;
                        o.x = acc[mt][nt][half * 2];
                        o.y = acc[mt][nt][half * 2 + 1];
                        *(float2*)(oc + col) = o;
                    }
                }
            }
        }
    }
}

// ---------------- prep kernels ----------------------------------------------
__global__ void init_rdist() {
    int i = blockIdx.x * 256 + threadIdx.x;
    if (i < 8192) g_rdist[i] = 1.0f / (sqrtf((float)i) + 1.0f);
}

__global__ void split_w(const float* __restrict__ w, __nv_bfloat16* __restrict__ h,
                        __nv_bfloat16* __restrict__ l, int n) {
    int i = blockIdx.x * 256 + threadIdx.x;
    if (i < n) {
        float v = w[i];
        __nv_bfloat16 hh = __float2bfloat16(v);
        h[i] = hh;
        l[i] = __float2bfloat16(v - __bfloat162float(hh));
    }
}

// x[b][c][n] -> xs[b][n][c] as bf16 hi/lo
__global__ void split_transpose(const float* __restrict__ x) {
    __shared__ float t[32][33];
    const int b = blockIdx.z;
    const int n0 = blockIdx.x << 5, c0 = blockIdx.y << 5;
    const int tx = threadIdx.x, ty = threadIdx.y;
    const float* xp = x + ((size_t)b * CC + c0) * NN + n0;
#pragma unroll
    for (int i = 0; i < 4; i++) t[ty + i * 8][tx] = xp[(size_t)(ty + i * 8) * NN + tx];
    __syncthreads();
    const size_t ob = ((size_t)b * NN + n0) * CC + c0;
#pragma unroll
    for (int i = 0; i < 4; i++) {
        float v = t[tx][ty + i * 8];
        __nv_bfloat16 h = __float2bfloat16(v);
        size_t o = ob + (size_t)(ty + i * 8) * CC + tx;
        g_xs_h[o] = h;
        g_xs_l[o] = __float2bfloat16(v - __bfloat162float(h));
    }
}

// row softmax, fp32 in -> bf16 pair out
__global__ void softmax_bf16(const float* __restrict__ rel) {
    __shared__ float red1[8], red2[8];
    const size_t row = blockIdx.x;
    const float4* p = (const float4*)(rel + row * (size_t)NN);
    const int tid = threadIdx.x;

    float4 v[4];
    float mx = -3.0e38f;
#pragma unroll
    for (int i = 0; i < 4; i++) {
        v[i] = p[tid + i * 256];
        mx = fmaxf(mx, fmaxf(fmaxf(v[i].x, v[i].y), fmaxf(v[i].z, v[i].w)));
    }
#pragma unroll
    for (int o = 16; o > 0; o >>= 1) mx = fmaxf(mx, __shfl_xor_sync(0xffffffffu, mx, o));
    if ((tid & 31) == 0) red1[tid >> 5] = mx;
    __syncthreads();
    mx = red1[0];
#pragma unroll
    for (int w = 1; w < 8; w++) mx = fmaxf(mx, red1[w]);

    float s = 0.f;
#pragma unroll
    for (int i = 0; i < 4; i++) {
        v[i].x = __expf(v[i].x - mx); v[i].y = __expf(v[i].y - mx);
        v[i].z = __expf(v[i].z - mx); v[i].w = __expf(v[i].w - mx);
        s += v[i].x + v[i].y + v[i].z + v[i].w;
    }
#pragma unroll
    for (int o = 16; o > 0; o >>= 1) s += __shfl_xor_sync(0xffffffffu, s, o);
    if ((tid & 31) == 0) red2[tid >> 5] = s;
    __syncthreads();
    s = 0.f;
#pragma unroll
    for (int w = 0; w < 8; w++) s += red2[w];
    const float inv = 1.0f / s;

    uint2* H = (uint2*)(g_P_h + row * (size_t)NN);
    uint2* L = (uint2*)(g_P_l + row * (size_t)NN);
#pragma unroll
    for (int i = 0; i < 4; i++) {
        float f0 = v[i].x * inv, f1 = v[i].y * inv, f2 = v[i].z * inv, f3 = v[i].w * inv;
        uint2 hh, ll;
        split_pk(f0, f1, hh.x, ll.x);
        split_pk(f2, f3, hh.y, ll.y);
        H[tid + i * 256] = hh;
        L[tid + i * 256] = ll;
    }
}

// ---------------- BN ---------------------------------------------------------
__global__ void bn_stats(const float* __restrict__ u) {
    __shared__ float rs[8], rs2[8];
    const int c = blockIdx.x;
    const int tid = threadIdx.x;
    float s = 0.f, s2 = 0.f;
    for (int b = 0; b < BB; b++) {
        const float* up = u + ((size_t)b * CC + c) * NN;
        for (int n = tid; n < NN; n += 256) {
            float t = up[n];
            s += t; s2 += t * t;
        }
    }
#pragma unroll
    for (int o = 16; o > 0; o >>= 1) {
        s  += __shfl_xor_sync(0xffffffffu, s, o);
        s2 += __shfl_xor_sync(0xffffffffu, s2, o);
    }
    if ((tid & 31) == 0) { rs[tid >> 5] = s; rs2[tid >> 5] = s2; }
    __syncthreads();
    if (tid == 0) {
        float S = 0.f, S2 = 0.f;
#pragma unroll
        for (int w = 0; w < 8; w++) { S += rs[w]; S2 += rs2[w]; }
        const float cnt = (float)(BB * NN);
        float mean = S / cnt;
        float var = S2 / cnt - mean * mean;
        g_mean[c] = mean;
        g_rstd[c] = rsqrtf(var + 1e-5f);
    }
}

__global__ void bn_relu_kernel(const float* __restrict__ u, const float* __restrict__ x,
                               const float* __restrict__ gamma, const float* __restrict__ beta,
                               float* __restrict__ out) {
    size_t i4 = (size_t)blockIdx.x * blockDim.x + threadIdx.x;
    int c = (int)((i4 * 4 / NN) % CC);
    float m = g_mean[c];
    float r = g_rstd[c] * gamma[c];
    float bt = beta[c];
    float4 uu = ((const float4*)u)[i4];
    float4 xx = ((const float4*)x)[i4];
    float4 o;
    o.x = fmaxf((uu.x - m) * r + bt + xx.x, 0.f);
    o.y = fmaxf((uu.y - m) * r + bt + xx.y, 0.f);
    o.z = fmaxf((uu.z - m) * r + bt + xx.z, 0.f);
    o.w = fmaxf((uu.w - m) * r + bt + xx.w, 0.f);
    ((float4*)out)[i4] = o;
}

// ---------------- launch ------------------------------------------------------
extern "C" void kernel_launch(void* const* d_in, const int* in_sizes, int n_in,
                              void* d_out, int out_size)
{
    const float* x     = (const float*)d_in[0];
    const float* Wv    = (const float*)d_in[1];
    const float* Wq    = (const float*)d_in[2];
    const float* Wk    = (const float*)d_in[3];
    const float* Wu    = (const float*)d_in[4];
    const float* gamma = (const float*)d_in[5];
    const float* beta  = (const float*)d_in[6];
    float* out = (float*)d_out;

    __nv_bfloat16 *xs_h, *xs_l, *wv_h, *wv_l, *wq_h, *wq_l, *wk_h, *wk_l, *wu_h, *wu_l;
    __nv_bfloat16 *q_h, *q_l, *k_h, *k_l, *vT_h, *vT_l, *P_h, *P_l, *y_h, *y_l;
    float *rel, *u;
    cudaGetSymbolAddress((void**)&xs_h, g_xs_h); cudaGetSymbolAddress((void**)&xs_l, g_xs_l);
    cudaGetSymbolAddress((void**)&wv_h, g_wv_h); cudaGetSymbolAddress((void**)&wv_l, g_wv_l);
    cudaGetSymbolAddress((void**)&wq_h, g_wq_h); cudaGetSymbolAddress((void**)&wq_l, g_wq_l);
    cudaGetSymbolAddress((void**)&wk_h, g_wk_h); cudaGetSymbolAddress((void**)&wk_l, g_wk_l);
    cudaGetSymbolAddress((void**)&wu_h, g_wu_h); cudaGetSymbolAddress((void**)&wu_l, g_wu_l);
    cudaGetSymbolAddress((void**)&q_h,  g_q_h);  cudaGetSymbolAddress((void**)&q_l,  g_q_l);
    cudaGetSymbolAddress((void**)&k_h,  g_k_h);  cudaGetSymbolAddress((void**)&k_l,  g_k_l);
    cudaGetSymbolAddress((void**)&vT_h, g_vT_h); cudaGetSymbolAddress((void**)&vT_l, g_vT_l);
    cudaGetSymbolAddress((void**)&P_h,  g_P_h);  cudaGetSymbolAddress((void**)&P_l,  g_P_l);
    cudaGetSymbolAddress((void**)&y_h,  g_y_h);  cudaGetSymbolAddress((void**)&y_l,  g_y_l);
    cudaGetSymbolAddress((void**)&rel,  g_rel);
    cudaGetSymbolAddress((void**)&u,    g_u);

    const int SMEM = 2 * STG;   // 81920 bytes
    cudaFuncSetAttribute(gemm_mma, cudaFuncAttributeMaxDynamicSharedMemorySize, SMEM);

    // ---- prep, ordered so the ncu capture (0-based launch #3) hits v-GEMM ----
    split_transpose<<<dim3(NN / 32, CC / 32, BB), dim3(32, 8)>>>(x);        // 0
    split_w<<<(CC * CC + 255) / 256, 256>>>(Wv, wv_h, wv_l, CC * CC);       // 1
    init_rdist<<<32, 256>>>();                                              // 2

    // 3: vT[b][o][m] = Wv[o][:] . xT[m][:]     M=CC, N=NN, K=CC   <- ncu target
    gemm_mma<<<dim3(32, 4, BB), 512, SMEM>>>(
        wv_h, wv_l, xs_h, xs_l, CC, 0L, (long)NN * CC,
        nullptr, vT_h, vT_l, (long)CC * NN, NN, 2);

    split_w<<<(II * CC + 255) / 256, 256>>>(Wq, wq_h, wq_l, II * CC);       // 4
    split_w<<<(II * CC + 255) / 256, 256>>>(Wk, wk_h, wk_l, II * CC);       // 5
    split_w<<<(CC * CC + 255) / 256, 256>>>(Wu, wu_h, wu_l, CC * CC);       // 6

    // q[b][n][i] = xT[n][:] . Wq[i][:]      M=NN, N=II, K=CC
    gemm_mma<<<dim3(1, 32, BB), 512, SMEM>>>(
        xs_h, xs_l, wq_h, wq_l, CC, (long)NN * CC, 0L,
        nullptr, q_h, q_l, (long)NN * II, II, 2);
    // k[b][m][i]
    gemm_mma<<<dim3(1, 32, BB), 512, SMEM>>>(
        xs_h, xs_l, wk_h, wk_l, CC, (long)NN * CC, 0L,
        nullptr, k_h, k_l, (long)NN * II, II, 2);
    // rel[b][n][m] = (q[n].k[m]) / dist     M=NN, N=NN, K=II
    gemm_mma<<<dim3(32, 32, BB), 512, SMEM>>>(
        q_h, q_l, k_h, k_l, II, (long)NN * II, (long)NN * II,
        rel, nullptr, nullptr, (long)NN * NN, NN, 1);
    // softmax rows -> P (bf16 pair)
    softmax_bf16<<<BB * NN, 256>>>(rel);
    // y[b][n][o] = P[n][:] . vT[o][:]       M=NN, N=CC, K=NN
    gemm_mma<<<dim3(4, 32, BB), 512, SMEM>>>(
        P_h, P_l, vT_h, vT_l, NN, (long)NN * NN, (long)CC * NN,
        nullptr, y_h, y_l, (long)NN * CC, CC, 2);
    // u[b][o][n] = Wu[o][:] . y[n][:]       M=CC, N=NN, K=CC
    gemm_mma<<<dim3(32, 4, BB), 512, SMEM>>>(
        wu_h, wu_l, y_h, y_l, CC, 0L, (long)NN * CC,
        u, nullptr, nullptr, (long)CC * NN, NN, 0);

    bn_stats<<<CC, 256>>>(u);
    bn_relu_kernel<<<(int)(((size_t)BB * CC * NN / 4) / 256), 256>>>(u, x, gamma, beta, out);
}

// round 6
// speedup vs baseline: 1.0704x; 1.0704x over previous
#include <cuda_runtime.h>
#include <cuda_bf16.h>
#include <stdint.h>

#define BB 8
#define CC 512
#define NN 4096
#define II 128

// ---------------- scratch (__device__ globals; no allocation allowed) -------
__device__ __nv_bfloat16 g_xs_h[(size_t)BB * NN * CC];
__device__ __nv_bfloat16 g_xs_l[(size_t)BB * NN * CC];
__device__ __nv_bfloat16 g_wv_h[CC * CC], g_wv_l[CC * CC];
__device__ __nv_bfloat16 g_wqk_h[2 * II * CC], g_wqk_l[2 * II * CC];  // Wq rows 0..127, Wk rows 128..255
__device__ __nv_bfloat16 g_wu_h[CC * CC], g_wu_l[CC * CC];
__device__ __nv_bfloat16 g_qk_h[(size_t)BB * NN * 256], g_qk_l[(size_t)BB * NN * 256];
__device__ __nv_bfloat16 g_vT_h[(size_t)BB * CC * NN], g_vT_l[(size_t)BB * CC * NN];
__device__ float         g_rel[(size_t)BB * NN * NN];
__device__ __nv_bfloat16 g_P_h[(size_t)BB * NN * NN], g_P_l[(size_t)BB * NN * NN];
__device__ __nv_bfloat16 g_y_h[(size_t)BB * NN * CC], g_y_l[(size_t)BB * NN * CC];
__device__ float         g_u[(size_t)BB * CC * NN];
__device__ float g_mean[CC], g_rstd[CC];
__device__ float g_rdist[8192];   // 1/(sqrt(d2)+1), d2 <= 2*63^2

// ---------------- PTX helpers (portable, non-'a' features only) -------------
__device__ __forceinline__ uint32_t s2u(const void* p) {
    uint32_t a;
    asm("{ .reg .u64 t; cvta.to.shared.u64 t, %1; cvt.u32.u64 %0, t; }" : "=r"(a) : "l"(p));
    return a;
}
__device__ __forceinline__ void cpa16(uint32_t s, const void* g) {
    asm volatile("cp.async.cg.shared.global [%0], [%1], 16;" :: "r"(s), "l"(g) : "memory");
}
__device__ __forceinline__ void cpa_commit() { asm volatile("cp.async.commit_group;" ::: "memory"); }
template <int W> __device__ __forceinline__ void cpa_wait() {
    asm volatile("cp.async.wait_group %0;" :: "n"(W) : "memory");
}
__device__ __forceinline__ void ldsm4(uint32_t* r, uint32_t addr) {
    asm volatile("ldmatrix.sync.aligned.m8n8.x4.shared.b16 {%0,%1,%2,%3}, [%4];"
                 : "=r"(r[0]), "=r"(r[1]), "=r"(r[2]), "=r"(r[3]) : "r"(addr));
}
__device__ __forceinline__ void mma_bf16(float* d, const uint32_t* a, const uint32_t* b) {
    asm volatile(
        "mma.sync.aligned.m16n8k16.row.col.f32.bf16.bf16.f32 "
        "{%0,%1,%2,%3}, {%4,%5,%6,%7}, {%8,%9}, {%0,%1,%2,%3};"
        : "+f"(d[0]), "+f"(d[1]), "+f"(d[2]), "+f"(d[3])
        : "r"(a[0]), "r"(a[1]), "r"(a[2]), "r"(a[3]), "r"(b[0]), "r"(b[1]));
}
__device__ __forceinline__ void split_pk(float a, float b, uint32_t& hi, uint32_t& lo) {
    __nv_bfloat162 h, l;
    h.x = __float2bfloat16(a); h.y = __float2bfloat16(b);
    l.x = __float2bfloat16(a - __bfloat162float(h.x));
    l.y = __float2bfloat16(b - __bfloat162float(h.y));
    hi = *reinterpret_cast<uint32_t*>(&h);
    lo = *reinterpret_cast<uint32_t*>(&l);
}

// ---------------- split-bf16 HMMA GEMM ---------------------------------------
// C[M,N] = A[M,K] * B[N,K]^T ; A,B given as (hi,lo) bf16 pairs, K-major,
// arbitrary leading dims lda/ldb. CTA tile 128x256, K-chunk 32,
// 8 warps (2m x 4n), warp tile 64x64, single barrier per chunk.
// modes: 0 = fp32 out, 1 = fp32 * (1/dist) out, 2 = bf16 (hi,lo) pair out.
#define ROWB 80                      // padded row stride (32 bf16 = 64B -> 80B)
#define A_ARR (128 * ROWB)           // 10240
#define B_ARR (256 * ROWB)           // 20480
#define STGB (2 * A_ARR + 2 * B_ARR) // 61440 per stage; x2 stages = 122880

__global__ void __launch_bounds__(256)
gemm_mma(const __nv_bfloat16* __restrict__ Ah_, const __nv_bfloat16* __restrict__ Al_,
         const __nv_bfloat16* __restrict__ Bh_, const __nv_bfloat16* __restrict__ Bl_,
         int K, int lda, int ldb, long a_batch, long b_batch,
         float* __restrict__ Cf,
         __nv_bfloat16* __restrict__ Chi, __nv_bfloat16* __restrict__ Clo,
         long c_batch, int Nld, int mode)
{
    extern __shared__ char smem[];
    const uint32_t sb = s2u(smem);
    const int tid = threadIdx.x;
    const int wid = tid >> 5;
    const int lane = tid & 31;
    const int bz = blockIdx.z;
    const int m0 = blockIdx.y * 128;
    const int n0 = blockIdx.x * 256;
    const int warp_m = wid >> 2;     // 0..1 -> 64 rows each
    const int warp_n = wid & 3;      // 0..3 -> 64 cols each

    const __nv_bfloat16* Ah = Ah_ + (size_t)bz * a_batch + (size_t)m0 * lda;
    const __nv_bfloat16* Al = Al_ + (size_t)bz * a_batch + (size_t)m0 * lda;
    const __nv_bfloat16* Bh = Bh_ + (size_t)bz * b_batch + (size_t)n0 * ldb;
    const __nv_bfloat16* Bl = Bl_ + (size_t)bz * b_batch + (size_t)n0 * ldb;

    const int nch = K >> 5;

    auto load_chunk = [&](int ci, int stg) {
        const uint32_t st = sb + stg * STGB;
        const size_t k0 = (size_t)ci * 32;
#pragma unroll
        for (int p = 0; p < 2; p++) {            // A: 128 rows x 4 sectors
            int f = tid + p * 256;
            int r = f >> 2, s = f & 3;
            uint32_t so = (uint32_t)r * ROWB + s * 16;
            size_t go = (size_t)r * lda + k0 + s * 8;
            cpa16(st + so,          Ah + go);
            cpa16(st + A_ARR + so,  Al + go);
        }
#pragma unroll
        for (int p = 0; p < 4; p++) {            // B: 256 rows x 4 sectors
            int f = tid + p * 256;
            int r = f >> 2, s = f & 3;
            uint32_t so = (uint32_t)r * ROWB + s * 16;
            size_t go = (size_t)r * ldb + k0 + s * 8;
            cpa16(st + 2 * A_ARR + so,          Bh + go);
            cpa16(st + 2 * A_ARR + B_ARR + so,  Bl + go);
        }
        cpa_commit();
    };

    load_chunk(0, 0);

    // lane offsets for ldmatrix (bytes)
    const int lt = lane & 7, ltile = lane >> 3;
    const uint32_t aLane = (uint32_t)(lt + ((ltile & 1) << 3)) * ROWB + ((ltile >> 1) << 4);
    const uint32_t bLane = (uint32_t)(lt + ((ltile >> 1) << 3)) * ROWB + ((ltile & 1) << 4);

    float acc[4][8][4];
#pragma unroll
    for (int i = 0; i < 4; i++)
#pragma unroll
        for (int j = 0; j < 8; j++)
#pragma unroll
            for (int c = 0; c < 4; c++) acc[i][j][c] = 0.f;

    for (int i = 0; i < nch; i++) {
        const int b = i & 1;
        const uint32_t st = sb + b * STGB;
        cpa_wait<0>();
        __syncthreads();
        // safe: buffer (i+1)&1 was last read at iter i-1; barrier above covers it
        if (i + 1 < nch) load_chunk(i + 1, (i + 1) & 1);

        const uint32_t aBh = st +             (uint32_t)warp_m * 64 * ROWB + aLane;
        const uint32_t aBl = st + A_ARR +     (uint32_t)warp_m * 64 * ROWB + aLane;
        const uint32_t bBh = st + 2 * A_ARR +         (uint32_t)warp_n * 64 * ROWB + bLane;
        const uint32_t bBl = st + 2 * A_ARR + B_ARR + (uint32_t)warp_n * 64 * ROWB + bLane;

#pragma unroll
        for (int ks = 0; ks < 2; ks++) {
            const uint32_t ko = ks * 32;
            uint32_t aH[4][4], bH[4][4];
#pragma unroll
            for (int mt = 0; mt < 4; mt++) ldsm4(aH[mt], aBh + mt * 16 * ROWB + ko);
#pragma unroll
            for (int np = 0; np < 4; np++) ldsm4(bH[np], bBh + np * 16 * ROWB + ko);
#pragma unroll
            for (int mt = 0; mt < 4; mt++)
#pragma unroll
                for (int nt = 0; nt < 8; nt++)
                    mma_bf16(acc[mt][nt], aH[mt], &bH[nt >> 1][(nt & 1) * 2]);
            {
                uint32_t aL[4][4];
#pragma unroll
                for (int mt = 0; mt < 4; mt++) ldsm4(aL[mt], aBl + mt * 16 * ROWB + ko);
#pragma unroll
                for (int mt = 0; mt < 4; mt++)
#pragma unroll
                    for (int nt = 0; nt < 8; nt++)
                        mma_bf16(acc[mt][nt], aL[mt], &bH[nt >> 1][(nt & 1) * 2]);
            }
            {
                uint32_t bL[4][4];
#pragma unroll
                for (int np = 0; np < 4; np++) ldsm4(bL[np], bBl + np * 16 * ROWB + ko);
#pragma unroll
                for (int mt = 0; mt < 4; mt++)
#pragma unroll
                    for (int nt = 0; nt < 8; nt++)
                        mma_bf16(acc[mt][nt], aH[mt], &bL[nt >> 1][(nt & 1) * 2]);
            }
        }
    }

    // ---- epilogue ----
    const int gp = lane >> 2, tq = lane & 3;
    const int mbase = m0 + warp_m * 64;
    const int nbase = n0 + warp_n * 64;

#pragma unroll
    for (int mt = 0; mt < 4; mt++) {
#pragma unroll
        for (int half = 0; half < 2; half++) {
            const int r = mbase + mt * 16 + half * 8 + gp;
            if (mode == 2) {
                __nv_bfloat16* oh = Chi + (size_t)bz * c_batch + (size_t)r * Nld;
                __nv_bfloat16* ol = Clo + (size_t)bz * c_batch + (size_t)r * Nld;
#pragma unroll
                for (int nt = 0; nt < 8; nt++) {
                    const int col = nbase + nt * 8 + 2 * tq;
                    uint32_t hi, lo;
                    split_pk(acc[mt][nt][half * 2], acc[mt][nt][half * 2 + 1], hi, lo);
                    *(uint32_t*)(oh + col) = hi;
                    *(uint32_t*)(ol + col) = lo;
                }
            } else {
                float* oc = Cf + (size_t)bz * c_batch + (size_t)r * Nld;
                if (mode == 1) {
                    const int ri = r >> 6, rj = r & 63;
#pragma unroll
                    for (int nt = 0; nt < 8; nt++) {
                        const int col = nbase + nt * 8 + 2 * tq;
                        int di0 = ri - (col >> 6);
                        int j0 = rj - (col & 63);
                        int j1 = rj - ((col + 1) & 63);
                        float2 o;
                        o.x = acc[mt][nt][half * 2]     * g_rdist[di0 * di0 + j0 * j0];
                        o.y = acc[mt][nt][half * 2 + 1] * g_rdist[di0 * di0 + j1 * j1];
                        *(float2*)(oc + col) = o;
                    }
                } else {
#pragma unroll
                    for (int nt = 0; nt < 8; nt++) {
                        const int col = nbase + nt * 8 + 2 * tq;
                        float2 o;
                        o.x = acc[mt][nt][half * 2];
                        o.y = acc[mt][nt][half * 2 + 1];
                        *(float2*)(oc + col) = o;
                    }
                }
            }
        }
    }
}

// ---------------- prep kernels ----------------------------------------------
__global__ void init_rdist() {
    int i = blockIdx.x * 256 + threadIdx.x;
    if (i < 8192) g_rdist[i] = 1.0f / (sqrtf((float)i) + 1.0f);
}

__global__ void split_w(const float* __restrict__ w, __nv_bfloat16* __restrict__ h,
                        __nv_bfloat16* __restrict__ l, int n) {
    int i = blockIdx.x * 256 + threadIdx.x;
    if (i < n) {
        float v = w[i];
        __nv_bfloat16 hh = __float2bfloat16(v);
        h[i] = hh;
        l[i] = __float2bfloat16(v - __bfloat162float(hh));
    }
}

// x[b][c][n] -> xs[b][n][c] as bf16 hi/lo
__global__ void split_transpose(const float* __restrict__ x) {
    __shared__ float t[32][33];
    const int b = blockIdx.z;
    const int n0 = blockIdx.x << 5, c0 = blockIdx.y << 5;
    const int tx = threadIdx.x, ty = threadIdx.y;
    const float* xp = x + ((size_t)b * CC + c0) * NN + n0;
#pragma unroll
    for (int i = 0; i < 4; i++) t[ty + i * 8][tx] = xp[(size_t)(ty + i * 8) * NN + tx];
    __syncthreads();
    const size_t ob = ((size_t)b * NN + n0) * CC + c0;
#pragma unroll
    for (int i = 0; i < 4; i++) {
        float v = t[tx][ty + i * 8];
        __nv_bfloat16 h = __float2bfloat16(v);
        size_t o = ob + (size_t)(ty + i * 8) * CC + tx;
        g_xs_h[o] = h;
        g_xs_l[o] = __float2bfloat16(v - __bfloat162float(h));
    }
}

// row softmax, fp32 in -> bf16 pair out
__global__ void softmax_bf16(const float* __restrict__ rel) {
    __shared__ float red1[8], red2[8];
    const size_t row = blockIdx.x;
    const float4* p = (const float4*)(rel + row * (size_t)NN);
    const int tid = threadIdx.x;

    float4 v[4];
    float mx = -3.0e38f;
#pragma unroll
    for (int i = 0; i < 4; i++) {
        v[i] = p[tid + i * 256];
        mx = fmaxf(mx, fmaxf(fmaxf(v[i].x, v[i].y), fmaxf(v[i].z, v[i].w)));
    }
#pragma unroll
    for (int o = 16; o > 0; o >>= 1) mx = fmaxf(mx, __shfl_xor_sync(0xffffffffu, mx, o));
    if ((tid & 31) == 0) red1[tid >> 5] = mx;
    __syncthreads();
    mx = red1[0];
#pragma unroll
    for (int w = 1; w < 8; w++) mx = fmaxf(mx, red1[w]);

    float s = 0.f;
#pragma unroll
    for (int i = 0; i < 4; i++) {
        v[i].x = __expf(v[i].x - mx); v[i].y = __expf(v[i].y - mx);
        v[i].z = __expf(v[i].z - mx); v[i].w = __expf(v[i].w - mx);
        s += v[i].x + v[i].y + v[i].z + v[i].w;
    }
#pragma unroll
    for (int o = 16; o > 0; o >>= 1) s += __shfl_xor_sync(0xffffffffu, s, o);
    if ((tid & 31) == 0) red2[tid >> 5] = s;
    __syncthreads();
    s = 0.f;
#pragma unroll
    for (int w = 0; w < 8; w++) s += red2[w];
    const float inv = 1.0f / s;

    uint2* H = (uint2*)(g_P_h + row * (size_t)NN);
    uint2* L = (uint2*)(g_P_l + row * (size_t)NN);
#pragma unroll
    for (int i = 0; i < 4; i++) {
        float f0 = v[i].x * inv, f1 = v[i].y * inv, f2 = v[i].z * inv, f3 = v[i].w * inv;
        uint2 hh, ll;
        split_pk(f0, f1, hh.x, ll.x);
        split_pk(f2, f3, hh.y, ll.y);
        H[tid + i * 256] = hh;
        L[tid + i * 256] = ll;
    }
}

// ---------------- BN ---------------------------------------------------------
__global__ void bn_stats(const float* __restrict__ u) {
    __shared__ float rs[8], rs2[8];
    const int c = blockIdx.x;
    const int tid = threadIdx.x;
    float s = 0.f, s2 = 0.f;
    for (int b = 0; b < BB; b++) {
        const float* up = u + ((size_t)b * CC + c) * NN;
        for (int n = tid; n < NN; n += 256) {
            float t = up[n];
            s += t; s2 += t * t;
        }
    }
#pragma unroll
    for (int o = 16; o > 0; o >>= 1) {
        s  += __shfl_xor_sync(0xffffffffu, s, o);
        s2 += __shfl_xor_sync(0xffffffffu, s2, o);
    }
    if ((tid & 31) == 0) { rs[tid >> 5] = s; rs2[tid >> 5] = s2; }
    __syncthreads();
    if (tid == 0) {
        float S = 0.f, S2 = 0.f;
#pragma unroll
        for (int w = 0; w < 8; w++) { S += rs[w]; S2 += rs2[w]; }
        const float cnt = (float)(BB * NN);
        float mean = S / cnt;
        float var = S2 / cnt - mean * mean;
        g_mean[c] = mean;
        g_rstd[c] = rsqrtf(var + 1e-5f);
    }
}

__global__ void bn_relu_kernel(const float* __restrict__ u, const float* __restrict__ x,
                               const float* __restrict__ gamma, const float* __restrict__ beta,
                               float* __restrict__ out) {
    size_t i4 = (size_t)blockIdx.x * blockDim.x + threadIdx.x;
    int c = (int)((i4 * 4 / NN) % CC);
    float m = g_mean[c];
    float r = g_rstd[c] * gamma[c];
    float bt = beta[c];
    float4 uu = ((const float4*)u)[i4];
    float4 xx = ((const float4*)x)[i4];
    float4 o;
    o.x = fmaxf((uu.x - m) * r + bt + xx.x, 0.f);
    o.y = fmaxf((uu.y - m) * r + bt + xx.y, 0.f);
    o.z = fmaxf((uu.z - m) * r + bt + xx.z, 0.f);
    o.w = fmaxf((uu.w - m) * r + bt + xx.w, 0.f);
    ((float4*)out)[i4] = o;
}

// ---------------- launch ------------------------------------------------------
extern "C" void kernel_launch(void* const* d_in, const int* in_sizes, int n_in,
                              void* d_out, int out_size)
{
    const float* x     = (const float*)d_in[0];
    const float* Wv    = (const float*)d_in[1];
    const float* Wq    = (const float*)d_in[2];
    const float* Wk    = (const float*)d_in[3];
    const float* Wu    = (const float*)d_in[4];
    const float* gamma = (const float*)d_in[5];
    const float* beta  = (const float*)d_in[6];
    float* out = (float*)d_out;

    __nv_bfloat16 *xs_h, *xs_l, *wv_h, *wv_l, *wqk_h, *wqk_l, *wu_h, *wu_l;
    __nv_bfloat16 *qk_h, *qk_l, *vT_h, *vT_l, *P_h, *P_l, *y_h, *y_l;
    float *rel, *u;
    cudaGetSymbolAddress((void**)&xs_h,  g_xs_h);  cudaGetSymbolAddress((void**)&xs_l,  g_xs_l);
    cudaGetSymbolAddress((void**)&wv_h,  g_wv_h);  cudaGetSymbolAddress((void**)&wv_l,  g_wv_l);
    cudaGetSymbolAddress((void**)&wqk_h, g_wqk_h); cudaGetSymbolAddress((void**)&wqk_l, g_wqk_l);
    cudaGetSymbolAddress((void**)&wu_h,  g_wu_h);  cudaGetSymbolAddress((void**)&wu_l,  g_wu_l);
    cudaGetSymbolAddress((void**)&qk_h,  g_qk_h);  cudaGetSymbolAddress((void**)&qk_l,  g_qk_l);
    cudaGetSymbolAddress((void**)&vT_h,  g_vT_h);  cudaGetSymbolAddress((void**)&vT_l,  g_vT_l);
    cudaGetSymbolAddress((void**)&P_h,   g_P_h);   cudaGetSymbolAddress((void**)&P_l,   g_P_l);
    cudaGetSymbolAddress((void**)&y_h,   g_y_h);   cudaGetSymbolAddress((void**)&y_l,   g_y_l);
    cudaGetSymbolAddress((void**)&rel,   g_rel);
    cudaGetSymbolAddress((void**)&u,     g_u);

    const int SMEM = 2 * STGB;   // 122880 bytes
    cudaFuncSetAttribute(gemm_mma, cudaFuncAttributeMaxDynamicSharedMemorySize, SMEM);

    // ---- prep, ordered so the ncu capture (0-based launch #3) hits v-GEMM ----
    split_transpose<<<dim3(NN / 32, CC / 32, BB), dim3(32, 8)>>>(x);        // 0
    split_w<<<(CC * CC + 255) / 256, 256>>>(Wv, wv_h, wv_l, CC * CC);       // 1
    init_rdist<<<32, 256>>>();                                              // 2

    // 3: vT[b][o][m] = Wv[o][:] . xs[m][:]   M=CC, N=NN, K=CC   <- ncu target
    gemm_mma<<<dim3(NN / 256, CC / 128, BB), 256, SMEM>>>(
        wv_h, wv_l, xs_h, xs_l, CC, CC, CC, 0L, (long)NN * CC,
        nullptr, vT_h, vT_l, (long)CC * NN, NN, 2);

    split_w<<<(II * CC + 255) / 256, 256>>>(Wq, wqk_h, wqk_l, II * CC);                 // rows 0..127
    split_w<<<(II * CC + 255) / 256, 256>>>(Wk, wqk_h + II * CC, wqk_l + II * CC, II * CC); // rows 128..255
    split_w<<<(CC * CC + 255) / 256, 256>>>(Wu, wu_h, wu_l, CC * CC);

    // qk[b][n][0:128]=q, [128:256]=k   M=NN, N=256, K=CC
    gemm_mma<<<dim3(1, NN / 128, BB), 256, SMEM>>>(
        xs_h, xs_l, wqk_h, wqk_l, CC, CC, CC, (long)NN * CC, 0L,
        nullptr, qk_h, qk_l, (long)NN * 256, 256, 2);

    // rel[b][n][m] = (q[n].k[m]) / dist   M=NN, N=NN, K=II
    gemm_mma<<<dim3(NN / 256, NN / 128, BB), 256, SMEM>>>(
        qk_h, qk_l, qk_h + II, qk_l + II, II, 256, 256,
        (long)NN * 256, (long)NN * 256,
        rel, nullptr, nullptr, (long)NN * NN, NN, 1);

    // softmax rows -> P (bf16 pair)
    softmax_bf16<<<BB * NN, 256>>>(rel);

    // y[b][n][o] = P[n][:] . vT[o][:]   M=NN, N=CC, K=NN
    gemm_mma<<<dim3(CC / 256, NN / 128, BB), 256, SMEM>>>(
        P_h, P_l, vT_h, vT_l, NN, NN, NN, (long)NN * NN, (long)CC * NN,
        nullptr, y_h, y_l, (long)NN * CC, CC, 2);

    // u[b][o][n] = Wu[o][:] . y[n][:]   M=CC, N=NN, K=CC
    gemm_mma<<<dim3(NN / 256, CC / 128, BB), 256, SMEM>>>(
        wu_h, wu_l, y_h, y_l, CC, CC, CC, 0L, (long)NN * CC,
        u, nullptr, nullptr, (long)CC * NN, NN, 0);

    bn_stats<<<CC, 256>>>(u);
    bn_relu_kernel<<<(int)(((size_t)BB * CC * NN / 4) / 256), 256>>>(u, x, gamma, beta, out);
}

// round 7
// speedup vs baseline: 1.2965x; 1.2112x over previous
#include <cuda_runtime.h>
#include <cuda_fp16.h>
#include <stdint.h>

#define BB 8
#define CC 512
#define NN 4096
#define II 128

// ---------------- scratch (__device__ globals; no allocation allowed) -------
__device__ __half g_xs_h[(size_t)BB * NN * CC];
__device__ __half g_xs_l[(size_t)BB * NN * CC];
__device__ __half g_wv[CC * CC];                       // single fp16
__device__ __half g_wqk_h[2 * II * CC], g_wqk_l[2 * II * CC];  // Wq rows 0..127, Wk 128..255
__device__ __half g_wu[CC * CC];                       // single fp16
__device__ __half g_qk_h[(size_t)BB * NN * 256], g_qk_l[(size_t)BB * NN * 256];
__device__ __half g_vT_h[(size_t)BB * CC * NN], g_vT_l[(size_t)BB * CC * NN];
__device__ float  g_rel[(size_t)BB * NN * NN];
__device__ __half g_P[(size_t)BB * NN * NN];           // single fp16 probabilities
__device__ __half g_y_h[(size_t)BB * NN * CC], g_y_l[(size_t)BB * NN * CC];
__device__ float  g_u[(size_t)BB * CC * NN];
__device__ float g_mean[CC], g_rstd[CC];
__device__ float g_rdist[8192];   // 1/(sqrt(d2)+1), d2 <= 2*63^2

// ---------------- PTX helpers (portable, non-'a' features only) -------------
__device__ __forceinline__ uint32_t s2u(const void* p) {
    uint32_t a;
    asm("{ .reg .u64 t; cvta.to.shared.u64 t, %1; cvt.u32.u64 %0, t; }" : "=r"(a) : "l"(p));
    return a;
}
__device__ __forceinline__ void cpa16(uint32_t s, const void* g) {
    asm volatile("cp.async.cg.shared.global [%0], [%1], 16;" :: "r"(s), "l"(g) : "memory");
}
__device__ __forceinline__ void cpa_commit() { asm volatile("cp.async.commit_group;" ::: "memory"); }
template <int W> __device__ __forceinline__ void cpa_wait() {
    asm volatile("cp.async.wait_group %0;" :: "n"(W) : "memory");
}
__device__ __forceinline__ void ldsm4(uint32_t* r, uint32_t addr) {
    asm volatile("ldmatrix.sync.aligned.m8n8.x4.shared.b16 {%0,%1,%2,%3}, [%4];"
                 : "=r"(r[0]), "=r"(r[1]), "=r"(r[2]), "=r"(r[3]) : "r"(addr));
}
__device__ __forceinline__ void mma_f16(float* d, const uint32_t* a, const uint32_t* b) {
    asm volatile(
        "mma.sync.aligned.m16n8k16.row.col.f32.f16.f16.f32 "
        "{%0,%1,%2,%3}, {%4,%5,%6,%7}, {%8,%9}, {%0,%1,%2,%3};"
        : "+f"(d[0]), "+f"(d[1]), "+f"(d[2]), "+f"(d[3])
        : "r"(a[0]), "r"(a[1]), "r"(a[2]), "r"(a[3]), "r"(b[0]), "r"(b[1]));
}
__device__ __forceinline__ void split_pk(float a, float b, uint32_t& hi, uint32_t& lo) {
    __half2 h, l;
    h.x = __float2half(a); h.y = __float2half(b);
    l.x = __float2half(a - __half2float(h.x));
    l.y = __float2half(b - __half2float(h.y));
    hi = *reinterpret_cast<uint32_t*>(&h);
    lo = *reinterpret_cast<uint32_t*>(&l);
}

// ---------------- split-fp16 HMMA GEMM ---------------------------------------
// C[M,N] = A[M,K] * B[N,K]^T ; operands fp16, K-major, leading dims lda/ldb.
// A is (hi,lo) pair when nprod==3; A hi only when nprod==2. B always (hi,lo).
// nprod==3: aH*bH + aH*bL + aL*bH (residual 2^-22)
// nprod==2: aH*bH + aH*bL        (A single fp16)
// CTA tile 128x256, K-chunk 32, 8 warps (2m x 4n), warp tile 64x64.
// modes: 0 = fp32 out, 1 = fp32 * (1/dist) out, 2 = fp16 (hi,lo) pair out.
#define ROWB 80                      // padded row stride (32 fp16 = 64B -> 80B)
#define A_ARR (128 * ROWB)           // 10240
#define B_ARR (256 * ROWB)           // 20480
#define STGB (2 * A_ARR + 2 * B_ARR) // 61440 per stage; x2 stages = 122880

__global__ void __launch_bounds__(256)
gemm_mma(const __half* __restrict__ Ah_, const __half* __restrict__ Al_,
         const __half* __restrict__ Bh_, const __half* __restrict__ Bl_,
         int K, int lda, int ldb, long a_batch, long b_batch,
         float* __restrict__ Cf,
         __half* __restrict__ Chi, __half* __restrict__ Clo,
         long c_batch, int Nld, int mode, int nprod)
{
    extern __shared__ char smem[];
    const uint32_t sb = s2u(smem);
    const int tid = threadIdx.x;
    const int wid = tid >> 5;
    const int lane = tid & 31;
    const int bz = blockIdx.z;
    const int m0 = blockIdx.y * 128;
    const int n0 = blockIdx.x * 256;
    const int warp_m = wid >> 2;     // 0..1 -> 64 rows each
    const int warp_n = wid & 3;      // 0..3 -> 64 cols each

    const __half* Ah = Ah_ + (size_t)bz * a_batch + (size_t)m0 * lda;
    const __half* Al = Al_ + (size_t)bz * a_batch + (size_t)m0 * lda;
    const __half* Bh = Bh_ + (size_t)bz * b_batch + (size_t)n0 * ldb;
    const __half* Bl = Bl_ + (size_t)bz * b_batch + (size_t)n0 * ldb;

    const int nch = K >> 5;

    auto load_chunk = [&](int ci, int stg) {
        const uint32_t st = sb + stg * STGB;
        const size_t k0 = (size_t)ci * 32;
#pragma unroll
        for (int p = 0; p < 2; p++) {            // A: 128 rows x 4 sectors
            int f = tid + p * 256;
            int r = f >> 2, s = f & 3;
            uint32_t so = (uint32_t)r * ROWB + s * 16;
            size_t go = (size_t)r * lda + k0 + s * 8;
            cpa16(st + so, Ah + go);
            if (nprod == 3) cpa16(st + A_ARR + so, Al + go);
        }
#pragma unroll
        for (int p = 0; p < 4; p++) {            // B: 256 rows x 4 sectors
            int f = tid + p * 256;
            int r = f >> 2, s = f & 3;
            uint32_t so = (uint32_t)r * ROWB + s * 16;
            size_t go = (size_t)r * ldb + k0 + s * 8;
            cpa16(st + 2 * A_ARR + so,          Bh + go);
            cpa16(st + 2 * A_ARR + B_ARR + so,  Bl + go);
        }
        cpa_commit();
    };

    load_chunk(0, 0);

    // lane offsets for ldmatrix (bytes)
    const int lt = lane & 7, ltile = lane >> 3;
    const uint32_t aLane = (uint32_t)(lt + ((ltile & 1) << 3)) * ROWB + ((ltile >> 1) << 4);
    const uint32_t bLane = (uint32_t)(lt + ((ltile >> 1) << 3)) * ROWB + ((ltile & 1) << 4);

    float acc[4][8][4];
#pragma unroll
    for (int i = 0; i < 4; i++)
#pragma unroll
        for (int j = 0; j < 8; j++)
#pragma unroll
            for (int c = 0; c < 4; c++) acc[i][j][c] = 0.f;

    for (int i = 0; i < nch; i++) {
        const int b = i & 1;
        const uint32_t st = sb + b * STGB;
        cpa_wait<0>();
        __syncthreads();
        if (i + 1 < nch) load_chunk(i + 1, (i + 1) & 1);

        const uint32_t aBh = st +             (uint32_t)warp_m * 64 * ROWB + aLane;
        const uint32_t aBl = st + A_ARR +     (uint32_t)warp_m * 64 * ROWB + aLane;
        const uint32_t bBh = st + 2 * A_ARR +         (uint32_t)warp_n * 64 * ROWB + bLane;
        const uint32_t bBl = st + 2 * A_ARR + B_ARR + (uint32_t)warp_n * 64 * ROWB + bLane;

#pragma unroll
        for (int ks = 0; ks < 2; ks++) {
            const uint32_t ko = ks * 32;
            uint32_t aH[4][4], bH[4][4];
#pragma unroll
            for (int mt = 0; mt < 4; mt++) ldsm4(aH[mt], aBh + mt * 16 * ROWB + ko);
#pragma unroll
            for (int np = 0; np < 4; np++) ldsm4(bH[np], bBh + np * 16 * ROWB + ko);
#pragma unroll
            for (int mt = 0; mt < 4; mt++)
#pragma unroll
                for (int nt = 0; nt < 8; nt++)
                    mma_f16(acc[mt][nt], aH[mt], &bH[nt >> 1][(nt & 1) * 2]);
            if (nprod == 3) {
                uint32_t aL[4][4];
#pragma unroll
                for (int mt = 0; mt < 4; mt++) ldsm4(aL[mt], aBl + mt * 16 * ROWB + ko);
#pragma unroll
                for (int mt = 0; mt < 4; mt++)
#pragma unroll
                    for (int nt = 0; nt < 8; nt++)
                        mma_f16(acc[mt][nt], aL[mt], &bH[nt >> 1][(nt & 1) * 2]);
            }
            {
                uint32_t bL[4][4];
#pragma unroll
                for (int np = 0; np < 4; np++) ldsm4(bL[np], bBl + np * 16 * ROWB + ko);
#pragma unroll
                for (int mt = 0; mt < 4; mt++)
#pragma unroll
                    for (int nt = 0; nt < 8; nt++)
                        mma_f16(acc[mt][nt], aH[mt], &bL[nt >> 1][(nt & 1) * 2]);
            }
        }
    }

    // ---- epilogue ----
    const int gp = lane >> 2, tq = lane & 3;
    const int mbase = m0 + warp_m * 64;
    const int nbase = n0 + warp_n * 64;

#pragma unroll
    for (int mt = 0; mt < 4; mt++) {
#pragma unroll
        for (int half = 0; half < 2; half++) {
            const int r = mbase + mt * 16 + half * 8 + gp;
            if (mode == 2) {
                __half* oh = Chi + (size_t)bz * c_batch + (size_t)r * Nld;
                __half* ol = Clo + (size_t)bz * c_batch + (size_t)r * Nld;
#pragma unroll
                for (int nt = 0; nt < 8; nt++) {
                    const int col = nbase + nt * 8 + 2 * tq;
                    uint32_t hi, lo;
                    split_pk(acc[mt][nt][half * 2], acc[mt][nt][half * 2 + 1], hi, lo);
                    *(uint32_t*)(oh + col) = hi;
                    *(uint32_t*)(ol + col) = lo;
                }
            } else {
                float* oc = Cf + (size_t)bz * c_batch + (size_t)r * Nld;
                if (mode == 1) {
                    const int ri = r >> 6, rj = r & 63;
#pragma unroll
                    for (int nt = 0; nt < 8; nt++) {
                        const int col = nbase + nt * 8 + 2 * tq;
                        int di0 = ri - (col >> 6);
                        int j0 = rj - (col & 63);
                        int j1 = rj - ((col + 1) & 63);
                        float2 o;
                        o.x = acc[mt][nt][half * 2]     * g_rdist[di0 * di0 + j0 * j0];
                        o.y = acc[mt][nt][half * 2 + 1] * g_rdist[di0 * di0 + j1 * j1];
                        *(float2*)(oc + col) = o;
                    }
                } else {
#pragma unroll
                    for (int nt = 0; nt < 8; nt++) {
                        const int col = nbase + nt * 8 + 2 * tq;
                        float2 o;
                        o.x = acc[mt][nt][half * 2];
                        o.y = acc[mt][nt][half * 2 + 1];
                        *(float2*)(oc + col) = o;
                    }
                }
            }
        }
    }
}

// ---------------- prep kernels ----------------------------------------------
__global__ void init_rdist() {
    int i = blockIdx.x * 256 + threadIdx.x;
    if (i < 8192) g_rdist[i] = 1.0f / (sqrtf((float)i) + 1.0f);
}

// fp32 -> single fp16
__global__ void cvt_w(const float* __restrict__ w, __half* __restrict__ h, int n) {
    int i = blockIdx.x * 256 + threadIdx.x;
    if (i < n) h[i] = __float2half(w[i]);
}

// fp32 -> fp16 pair
__global__ void split_w(const float* __restrict__ w, __half* __restrict__ h,
                        __half* __restrict__ l, int n) {
    int i = blockIdx.x * 256 + threadIdx.x;
    if (i < n) {
        float v = w[i];
        __half hh = __float2half(v);
        h[i] = hh;
        l[i] = __float2half(v - __half2float(hh));
    }
}

// x[b][c][n] -> xs[b][n][c] as fp16 hi/lo
__global__ void split_transpose(const float* __restrict__ x) {
    __shared__ float t[32][33];
    const int b = blockIdx.z;
    const int n0 = blockIdx.x << 5, c0 = blockIdx.y << 5;
    const int tx = threadIdx.x, ty = threadIdx.y;
    const float* xp = x + ((size_t)b * CC + c0) * NN + n0;
#pragma unroll
    for (int i = 0; i < 4; i++) t[ty + i * 8][tx] = xp[(size_t)(ty + i * 8) * NN + tx];
    __syncthreads();
    const size_t ob = ((size_t)b * NN + n0) * CC + c0;
#pragma unroll
    for (int i = 0; i < 4; i++) {
        float v = t[tx][ty + i * 8];
        __half h = __float2half(v);
        size_t o = ob + (size_t)(ty + i * 8) * CC + tx;
        g_xs_h[o] = h;
        g_xs_l[o] = __float2half(v - __half2float(h));
    }
}

// row softmax, fp32 in -> single fp16 out
__global__ void softmax_f16(const float* __restrict__ rel) {
    __shared__ float red1[8], red2[8];
    const size_t row = blockIdx.x;
    const float4* p = (const float4*)(rel + row * (size_t)NN);
    const int tid = threadIdx.x;

    float4 v[4];
    float mx = -3.0e38f;
#pragma unroll
    for (int i = 0; i < 4; i++) {
        v[i] = p[tid + i * 256];
        mx = fmaxf(mx, fmaxf(fmaxf(v[i].x, v[i].y), fmaxf(v[i].z, v[i].w)));
    }
#pragma unroll
    for (int o = 16; o > 0; o >>= 1) mx = fmaxf(mx, __shfl_xor_sync(0xffffffffu, mx, o));
    if ((tid & 31) == 0) red1[tid >> 5] = mx;
    __syncthreads();
    mx = red1[0];
#pragma unroll
    for (int w = 1; w < 8; w++) mx = fmaxf(mx, red1[w]);

    float s = 0.f;
#pragma unroll
    for (int i = 0; i < 4; i++) {
        v[i].x = __expf(v[i].x - mx); v[i].y = __expf(v[i].y - mx);
        v[i].z = __expf(v[i].z - mx); v[i].w = __expf(v[i].w - mx);
        s += v[i].x + v[i].y + v[i].z + v[i].w;
    }
#pragma unroll
    for (int o = 16; o > 0; o >>= 1) s += __shfl_xor_sync(0xffffffffu, s, o);
    if ((tid & 31) == 0) red2[tid >> 5] = s;
    __syncthreads();
    s = 0.f;
#pragma unroll
    for (int w = 0; w < 8; w++) s += red2[w];
    const float inv = 1.0f / s;

    uint2* P = (uint2*)(g_P + row * (size_t)NN);
#pragma unroll
    for (int i = 0; i < 4; i++) {
        __half2 a, b;
        a.x = __float2half(v[i].x * inv); a.y = __float2half(v[i].y * inv);
        b.x = __float2half(v[i].z * inv); b.y = __float2half(v[i].w * inv);
        uint2 o;
        o.x = *reinterpret_cast<uint32_t*>(&a);
        o.y = *reinterpret_cast<uint32_t*>(&b);
        P[tid + i * 256] = o;
    }
}

// ---------------- BN ---------------------------------------------------------
__global__ void bn_stats(const float* __restrict__ u) {
    __shared__ float rs[8], rs2[8];
    const int c = blockIdx.x;
    const int tid = threadIdx.x;
    float s = 0.f, s2 = 0.f;
    for (int b = 0; b < BB; b++) {
        const float* up = u + ((size_t)b * CC + c) * NN;
        for (int n = tid; n < NN; n += 256) {
            float t = up[n];
            s += t; s2 += t * t;
        }
    }
#pragma unroll
    for (int o = 16; o > 0; o >>= 1) {
        s  += __shfl_xor_sync(0xffffffffu, s, o);
        s2 += __shfl_xor_sync(0xffffffffu, s2, o);
    }
    if ((tid & 31) == 0) { rs[tid >> 5] = s; rs2[tid >> 5] = s2; }
    __syncthreads();
    if (tid == 0) {
        float S = 0.f, S2 = 0.f;
#pragma unroll
        for (int w = 0; w < 8; w++) { S += rs[w]; S2 += rs2[w]; }
        const float cnt = (float)(BB * NN);
        float mean = S / cnt;
        float var = S2 / cnt - mean * mean;
        g_mean[c] = mean;
        g_rstd[c] = rsqrtf(var + 1e-5f);
    }
}

__global__ void bn_relu_kernel(const float* __restrict__ u, const float* __restrict__ x,
                               const float* __restrict__ gamma, const float* __restrict__ beta,
                               float* __restrict__ out) {
    size_t i4 = (size_t)blockIdx.x * blockDim.x + threadIdx.x;
    int c = (int)((i4 * 4 / NN) % CC);
    float m = g_mean[c];
    float r = g_rstd[c] * gamma[c];
    float bt = beta[c];
    float4 uu = ((const float4*)u)[i4];
    float4 xx = ((const float4*)x)[i4];
    float4 o;
    o.x = fmaxf((uu.x - m) * r + bt + xx.x, 0.f);
    o.y = fmaxf((uu.y - m) * r + bt + xx.y, 0.f);
    o.z = fmaxf((uu.z - m) * r + bt + xx.z, 0.f);
    o.w = fmaxf((uu.w - m) * r + bt + xx.w, 0.f);
    ((float4*)out)[i4] = o;
}

// ---------------- launch ------------------------------------------------------
extern "C" void kernel_launch(void* const* d_in, const int* in_sizes, int n_in,
                              void* d_out, int out_size)
{
    const float* x     = (const float*)d_in[0];
    const float* Wv    = (const float*)d_in[1];
    const float* Wq    = (const float*)d_in[2];
    const float* Wk    = (const float*)d_in[3];
    const float* Wu    = (const float*)d_in[4];
    const float* gamma = (const float*)d_in[5];
    const float* beta  = (const float*)d_in[6];
    float* out = (float*)d_out;

    __half *xs_h, *xs_l, *wv, *wqk_h, *wqk_l, *wu;
    __half *qk_h, *qk_l, *vT_h, *vT_l, *P, *y_h, *y_l;
    float *rel, *u;
    cudaGetSymbolAddress((void**)&xs_h,  g_xs_h);  cudaGetSymbolAddress((void**)&xs_l,  g_xs_l);
    cudaGetSymbolAddress((void**)&wv,    g_wv);
    cudaGetSymbolAddress((void**)&wqk_h, g_wqk_h); cudaGetSymbolAddress((void**)&wqk_l, g_wqk_l);
    cudaGetSymbolAddress((void**)&wu,    g_wu);
    cudaGetSymbolAddress((void**)&qk_h,  g_qk_h);  cudaGetSymbolAddress((void**)&qk_l,  g_qk_l);
    cudaGetSymbolAddress((void**)&vT_h,  g_vT_h);  cudaGetSymbolAddress((void**)&vT_l,  g_vT_l);
    cudaGetSymbolAddress((void**)&P,     g_P);
    cudaGetSymbolAddress((void**)&y_h,   g_y_h);   cudaGetSymbolAddress((void**)&y_l,   g_y_l);
    cudaGetSymbolAddress((void**)&rel,   g_rel);
    cudaGetSymbolAddress((void**)&u,     g_u);

    const int SMEM = 2 * STGB;   // 122880 bytes
    cudaFuncSetAttribute(gemm_mma, cudaFuncAttributeMaxDynamicSharedMemorySize, SMEM);

    // ---- prep, ordered so the ncu capture (0-based launch #3) hits v-GEMM ----
    split_transpose<<<dim3(NN / 32, CC / 32, BB), dim3(32, 8)>>>(x);        // 0
    cvt_w<<<(CC * CC + 255) / 256, 256>>>(Wv, wv, CC * CC);                 // 1
    init_rdist<<<32, 256>>>();                                              // 2

    // 3: vT[b][o][m] = Wv[o][:] . xs[m][:]   M=CC, N=NN, K=CC  (2-product) <- ncu
    gemm_mma<<<dim3(NN / 256, CC / 128, BB), 256, SMEM>>>(
        wv, wv, xs_h, xs_l, CC, CC, CC, 0L, (long)NN * CC,
        nullptr, vT_h, vT_l, (long)CC * NN, NN, 2, 2);

    split_w<<<(II * CC + 255) / 256, 256>>>(Wq, wqk_h, wqk_l, II * CC);
    split_w<<<(II * CC + 255) / 256, 256>>>(Wk, wqk_h + II * CC, wqk_l + II * CC, II * CC);
    cvt_w<<<(CC * CC + 255) / 256, 256>>>(Wu, wu, CC * CC);

    // qk[b][n][0:128]=q, [128:256]=k   M=NN, N=256, K=CC  (3-product)
    gemm_mma<<<dim3(1, NN / 128, BB), 256, SMEM>>>(
        xs_h, xs_l, wqk_h, wqk_l, CC, CC, CC, (long)NN * CC, 0L,
        nullptr, qk_h, qk_l, (long)NN * 256, 256, 2, 3);

    // rel[b][n][m] = (q[n].k[m]) / dist   M=NN, N=NN, K=II  (3-product)
    gemm_mma<<<dim3(NN / 256, NN / 128, BB), 256, SMEM>>>(
        qk_h, qk_l, qk_h + II, qk_l + II, II, 256, 256,
        (long)NN * 256, (long)NN * 256,
        rel, nullptr, nullptr, (long)NN * NN, NN, 1, 3);

    // softmax rows -> P (single fp16)
    softmax_f16<<<BB * NN, 256>>>(rel);

    // y[b][n][o] = P[n][:] . vT[o][:]   M=NN, N=CC, K=NN  (2-product)
    gemm_mma<<<dim3(CC / 256, NN / 128, BB), 256, SMEM>>>(
        P, P, vT_h, vT_l, NN, NN, NN, (long)NN * NN, (long)CC * NN,
        nullptr, y_h, y_l, (long)NN * CC, CC, 2, 2);

    // u[b][o][n] = Wu[o][:] . y[n][:]   M=CC, N=NN, K=CC  (2-product)
    gemm_mma<<<dim3(NN / 256, CC / 128, BB), 256, SMEM>>>(
        wu, wu, y_h, y_l, CC, CC, CC, 0L, (long)NN * CC,
        u, nullptr, nullptr, (long)CC * NN, NN, 0, 2);

    bn_stats<<<CC, 256>>>(u);
    bn_relu_kernel<<<(int)(((size_t)BB * CC * NN / 4) / 256), 256>>>(u, x, gamma, beta, out);
}

// round 8
// speedup vs baseline: 1.3045x; 1.0062x over previous
#include <cuda_runtime.h>
#include <cuda_fp16.h>
#include <stdint.h>

#define BB 8
#define CC 512
#define NN 4096
#define II 128

// ---------------- scratch (__device__ globals; no allocation allowed) -------
__device__ __half g_xs_h[(size_t)BB * NN * CC];
__device__ __half g_xs_l[(size_t)BB * NN * CC];
__device__ __half g_wv[CC * CC];                       // single fp16
__device__ __half g_wqk_h[2 * II * CC], g_wqk_l[2 * II * CC];  // Wq rows 0..127, Wk 128..255
__device__ __half g_wu[CC * CC];                       // single fp16
__device__ __half g_qk_h[(size_t)BB * NN * 256], g_qk_l[(size_t)BB * NN * 256];
__device__ __half g_vT_h[(size_t)BB * CC * NN], g_vT_l[(size_t)BB * CC * NN];
__device__ float  g_rel[(size_t)BB * NN * NN];
__device__ __half g_P[(size_t)BB * NN * NN];           // single fp16 probabilities
__device__ __half g_y_h[(size_t)BB * NN * CC], g_y_l[(size_t)BB * NN * CC];
__device__ float  g_u[(size_t)BB * CC * NN];
__device__ float g_mean[CC], g_rstd[CC];
__device__ float g_rdist[8192];   // 1/(sqrt(d2)+1), d2 <= 2*63^2

// ---------------- PTX helpers (portable, non-'a' features only) -------------
__device__ __forceinline__ uint32_t s2u(const void* p) {
    uint32_t a;
    asm("{ .reg .u64 t; cvta.to.shared.u64 t, %1; cvt.u32.u64 %0, t; }" : "=r"(a) : "l"(p));
    return a;
}
__device__ __forceinline__ void cpa16(uint32_t s, const void* g) {
    asm volatile("cp.async.cg.shared.global [%0], [%1], 16;" :: "r"(s), "l"(g) : "memory");
}
__device__ __forceinline__ void cpa_commit() { asm volatile("cp.async.commit_group;" ::: "memory"); }
template <int W> __device__ __forceinline__ void cpa_wait() {
    asm volatile("cp.async.wait_group %0;" :: "n"(W) : "memory");
}
__device__ __forceinline__ void ldsm4(uint32_t* r, uint32_t addr) {
    asm volatile("ldmatrix.sync.aligned.m8n8.x4.shared.b16 {%0,%1,%2,%3}, [%4];"
                 : "=r"(r[0]), "=r"(r[1]), "=r"(r[2]), "=r"(r[3]) : "r"(addr));
}
__device__ __forceinline__ void mma_f16(float* d, const uint32_t* a, const uint32_t* b) {
    asm volatile(
        "mma.sync.aligned.m16n8k16.row.col.f32.f16.f16.f32 "
        "{%0,%1,%2,%3}, {%4,%5,%6,%7}, {%8,%9}, {%0,%1,%2,%3};"
        : "+f"(d[0]), "+f"(d[1]), "+f"(d[2]), "+f"(d[3])
        : "r"(a[0]), "r"(a[1]), "r"(a[2]), "r"(a[3]), "r"(b[0]), "r"(b[1]));
}
__device__ __forceinline__ void split_pk(float a, float b, uint32_t& hi, uint32_t& lo) {
    __half2 h, l;
    h.x = __float2half(a); h.y = __float2half(b);
    l.x = __float2half(a - __half2float(h.x));
    l.y = __float2half(b - __half2float(h.y));
    hi = *reinterpret_cast<uint32_t*>(&h);
    lo = *reinterpret_cast<uint32_t*>(&l);
}

// ---------------- split-fp16 HMMA GEMM ---------------------------------------
// C[M,N] = A[M,K] * B[N,K]^T ; operands fp16, K-major, leading dims lda/ldb.
// nprod==3: aH*bH + aH*bL + aL*bH ; nprod==2: aH*bH + aH*bL (A single fp16).
// CTA tile 128x256, K-chunk 32, 8 warps (2m x 4n), warp tile 64x64.
// 3-stage cp.async pipeline, wait_group<1> (2 loads in flight).
// modes: 0 = fp32 out, 1 = fp32 * (1/dist) out, 2 = fp16 (hi,lo) pair out.
#define ROWB 80                      // padded row stride (32 fp16 = 64B -> 80B)
#define A_ARR (128 * ROWB)           // 10240
#define B_ARR (256 * ROWB)           // 20480
#define STGB (2 * A_ARR + 2 * B_ARR) // 61440 per stage; x3 stages = 184320

__global__ void __launch_bounds__(256)
gemm_mma(const __half* __restrict__ Ah_, const __half* __restrict__ Al_,
         const __half* __restrict__ Bh_, const __half* __restrict__ Bl_,
         int K, int lda, int ldb, long a_batch, long b_batch,
         float* __restrict__ Cf,
         __half* __restrict__ Chi, __half* __restrict__ Clo,
         long c_batch, int Nld, int mode, int nprod)
{
    extern __shared__ char smem[];
    const uint32_t sb = s2u(smem);
    const int tid = threadIdx.x;
    const int wid = tid >> 5;
    const int lane = tid & 31;
    const int bz = blockIdx.z;
    const int m0 = blockIdx.y * 128;
    const int n0 = blockIdx.x * 256;
    const int warp_m = wid >> 2;     // 0..1 -> 64 rows each
    const int warp_n = wid & 3;      // 0..3 -> 64 cols each

    const __half* Ah = Ah_ + (size_t)bz * a_batch + (size_t)m0 * lda;
    const __half* Al = Al_ + (size_t)bz * a_batch + (size_t)m0 * lda;
    const __half* Bh = Bh_ + (size_t)bz * b_batch + (size_t)n0 * ldb;
    const __half* Bl = Bl_ + (size_t)bz * b_batch + (size_t)n0 * ldb;

    const int nch = K >> 5;

    auto load_chunk = [&](int ci, int stg) {
        const uint32_t st = sb + stg * STGB;
        const size_t k0 = (size_t)ci * 32;
#pragma unroll
        for (int p = 0; p < 2; p++) {            // A: 128 rows x 4 sectors
            int f = tid + p * 256;
            int r = f >> 2, s = f & 3;
            uint32_t so = (uint32_t)r * ROWB + s * 16;
            size_t go = (size_t)r * lda + k0 + s * 8;
            cpa16(st + so, Ah + go);
            if (nprod == 3) cpa16(st + A_ARR + so, Al + go);
        }
#pragma unroll
        for (int p = 0; p < 4; p++) {            // B: 256 rows x 4 sectors
            int f = tid + p * 256;
            int r = f >> 2, s = f & 3;
            uint32_t so = (uint32_t)r * ROWB + s * 16;
            size_t go = (size_t)r * ldb + k0 + s * 8;
            cpa16(st + 2 * A_ARR + so,          Bh + go);
            cpa16(st + 2 * A_ARR + B_ARR + so,  Bl + go);
        }
        cpa_commit();
    };

    load_chunk(0, 0);
    load_chunk(1, 1);      // nch >= 4 for all our shapes

    // lane offsets for ldmatrix (bytes)
    const int lt = lane & 7, ltile = lane >> 3;
    const uint32_t aLane = (uint32_t)(lt + ((ltile & 1) << 3)) * ROWB + ((ltile >> 1) << 4);
    const uint32_t bLane = (uint32_t)(lt + ((ltile >> 1) << 3)) * ROWB + ((ltile & 1) << 4);

    float acc[4][8][4];
#pragma unroll
    for (int i = 0; i < 4; i++)
#pragma unroll
        for (int j = 0; j < 8; j++)
#pragma unroll
            for (int c = 0; c < 4; c++) acc[i][j][c] = 0.f;

    for (int i = 0; i < nch; i++) {
        const uint32_t st = sb + (i % 3) * STGB;
        // chunk i must be complete; newer groups (if any) may stay in flight
        if (i + 1 < nch) cpa_wait<1>(); else cpa_wait<0>();
        __syncthreads();
        // stage (i+2)%3 held chunk i-1; the barrier above covers its readers
        if (i + 2 < nch) load_chunk(i + 2, (i + 2) % 3);

        const uint32_t aBh = st +             (uint32_t)warp_m * 64 * ROWB + aLane;
        const uint32_t aBl = st + A_ARR +     (uint32_t)warp_m * 64 * ROWB + aLane;
        const uint32_t bBh = st + 2 * A_ARR +         (uint32_t)warp_n * 64 * ROWB + bLane;
        const uint32_t bBl = st + 2 * A_ARR + B_ARR + (uint32_t)warp_n * 64 * ROWB + bLane;

#pragma unroll
        for (int ks = 0; ks < 2; ks++) {
            const uint32_t ko = ks * 32;
            uint32_t aH[4][4], bH[4][4];
#pragma unroll
            for (int mt = 0; mt < 4; mt++) ldsm4(aH[mt], aBh + mt * 16 * ROWB + ko);
#pragma unroll
            for (int np = 0; np < 4; np++) ldsm4(bH[np], bBh + np * 16 * ROWB + ko);
#pragma unroll
            for (int mt = 0; mt < 4; mt++)
#pragma unroll
                for (int nt = 0; nt < 8; nt++)
                    mma_f16(acc[mt][nt], aH[mt], &bH[nt >> 1][(nt & 1) * 2]);
            if (nprod == 3) {
                uint32_t aL[4][4];
#pragma unroll
                for (int mt = 0; mt < 4; mt++) ldsm4(aL[mt], aBl + mt * 16 * ROWB + ko);
#pragma unroll
                for (int mt = 0; mt < 4; mt++)
#pragma unroll
                    for (int nt = 0; nt < 8; nt++)
                        mma_f16(acc[mt][nt], aL[mt], &bH[nt >> 1][(nt & 1) * 2]);
            }
            {
                uint32_t bL[4][4];
#pragma unroll
                for (int np = 0; np < 4; np++) ldsm4(bL[np], bBl + np * 16 * ROWB + ko);
#pragma unroll
                for (int mt = 0; mt < 4; mt++)
#pragma unroll
                    for (int nt = 0; nt < 8; nt++)
                        mma_f16(acc[mt][nt], aH[mt], &bL[nt >> 1][(nt & 1) * 2]);
            }
        }
    }

    // ---- epilogue ----
    const int gp = lane >> 2, tq = lane & 3;
    const int mbase = m0 + warp_m * 64;
    const int nbase = n0 + warp_n * 64;

#pragma unroll
    for (int mt = 0; mt < 4; mt++) {
#pragma unroll
        for (int half = 0; half < 2; half++) {
            const int r = mbase + mt * 16 + half * 8 + gp;
            if (mode == 2) {
                __half* oh = Chi + (size_t)bz * c_batch + (size_t)r * Nld;
                __half* ol = Clo + (size_t)bz * c_batch + (size_t)r * Nld;
#pragma unroll
                for (int nt = 0; nt < 8; nt++) {
                    const int col = nbase + nt * 8 + 2 * tq;
                    uint32_t hi, lo;
                    split_pk(acc[mt][nt][half * 2], acc[mt][nt][half * 2 + 1], hi, lo);
                    *(uint32_t*)(oh + col) = hi;
                    *(uint32_t*)(ol + col) = lo;
                }
            } else {
                float* oc = Cf + (size_t)bz * c_batch + (size_t)r * Nld;
                if (mode == 1) {
                    const int ri = r >> 6, rj = r & 63;
#pragma unroll
                    for (int nt = 0; nt < 8; nt++) {
                        const int col = nbase + nt * 8 + 2 * tq;
                        int di0 = ri - (col >> 6);
                        int j0 = rj - (col & 63);
                        int j1 = rj - ((col + 1) & 63);
                        float2 o;
                        o.x = acc[mt][nt][half * 2]     * g_rdist[di0 * di0 + j0 * j0];
                        o.y = acc[mt][nt][half * 2 + 1] * g_rdist[di0 * di0 + j1 * j1];
                        *(float2*)(oc + col) = o;
                    }
                } else {
#pragma unroll
                    for (int nt = 0; nt < 8; nt++) {
                        const int col = nbase + nt * 8 + 2 * tq;
                        float2 o;
                        o.x = acc[mt][nt][half * 2];
                        o.y = acc[mt][nt][half * 2 + 1];
                        *(float2*)(oc + col) = o;
                    }
                }
            }
        }
    }
}

// ---------------- prep kernels ----------------------------------------------
__global__ void init_rdist() {
    int i = blockIdx.x * 256 + threadIdx.x;
    if (i < 8192) g_rdist[i] = 1.0f / (sqrtf((float)i) + 1.0f);
}

// fp32 -> single fp16
__global__ void cvt_w(const float* __restrict__ w, __half* __restrict__ h, int n) {
    int i = blockIdx.x * 256 + threadIdx.x;
    if (i < n) h[i] = __float2half(w[i]);
}

// fp32 -> fp16 pair
__global__ void split_w(const float* __restrict__ w, __half* __restrict__ h,
                        __half* __restrict__ l, int n) {
    int i = blockIdx.x * 256 + threadIdx.x;
    if (i < n) {
        float v = w[i];
        __half hh = __float2half(v);
        h[i] = hh;
        l[i] = __float2half(v - __half2float(hh));
    }
}

// x[b][c][n] -> xs[b][n][c] as fp16 hi/lo
__global__ void split_transpose(const float* __restrict__ x) {
    __shared__ float t[32][33];
    const int b = blockIdx.z;
    const int n0 = blockIdx.x << 5, c0 = blockIdx.y << 5;
    const int tx = threadIdx.x, ty = threadIdx.y;
    const float* xp = x + ((size_t)b * CC + c0) * NN + n0;
#pragma unroll
    for (int i = 0; i < 4; i++) t[ty + i * 8][tx] = xp[(size_t)(ty + i * 8) * NN + tx];
    __syncthreads();
    const size_t ob = ((size_t)b * NN + n0) * CC + c0;
#pragma unroll
    for (int i = 0; i < 4; i++) {
        float v = t[tx][ty + i * 8];
        __half h = __float2half(v);
        size_t o = ob + (size_t)(ty + i * 8) * CC + tx;
        g_xs_h[o] = h;
        g_xs_l[o] = __float2half(v - __half2float(h));
    }
}

// row softmax, fp32 in -> single fp16 out
__global__ void softmax_f16(const float* __restrict__ rel) {
    __shared__ float red1[8], red2[8];
    const size_t row = blockIdx.x;
    const float4* p = (const float4*)(rel + row * (size_t)NN);
    const int tid = threadIdx.x;

    float4 v[4];
    float mx = -3.0e38f;
#pragma unroll
    for (int i = 0; i < 4; i++) {
        v[i] = p[tid + i * 256];
        mx = fmaxf(mx, fmaxf(fmaxf(v[i].x, v[i].y), fmaxf(v[i].z, v[i].w)));
    }
#pragma unroll
    for (int o = 16; o > 0; o >>= 1) mx = fmaxf(mx, __shfl_xor_sync(0xffffffffu, mx, o));
    if ((tid & 31) == 0) red1[tid >> 5] = mx;
    __syncthreads();
    mx = red1[0];
#pragma unroll
    for (int w = 1; w < 8; w++) mx = fmaxf(mx, red1[w]);

    float s = 0.f;
#pragma unroll
    for (int i = 0; i < 4; i++) {
        v[i].x = __expf(v[i].x - mx); v[i].y = __expf(v[i].y - mx);
        v[i].z = __expf(v[i].z - mx); v[i].w = __expf(v[i].w - mx);
        s += v[i].x + v[i].y + v[i].z + v[i].w;
    }
#pragma unroll
    for (int o = 16; o > 0; o >>= 1) s += __shfl_xor_sync(0xffffffffu, s, o);
    if ((tid & 31) == 0) red2[tid >> 5] = s;
    __syncthreads();
    s = 0.f;
#pragma unroll
    for (int w = 0; w < 8; w++) s += red2[w];
    const float inv = 1.0f / s;

    uint2* P = (uint2*)(g_P + row * (size_t)NN);
#pragma unroll
    for (int i = 0; i < 4; i++) {
        __half2 a, b;
        a.x = __float2half(v[i].x * inv); a.y = __float2half(v[i].y * inv);
        b.x = __float2half(v[i].z * inv); b.y = __float2half(v[i].w * inv);
        uint2 o;
        o.x = *reinterpret_cast<uint32_t*>(&a);
        o.y = *reinterpret_cast<uint32_t*>(&b);
        P[tid + i * 256] = o;
    }
}

// ---------------- BN ---------------------------------------------------------
__global__ void bn_stats(const float* __restrict__ u) {
    __shared__ float rs[8], rs2[8];
    const int c = blockIdx.x;
    const int tid = threadIdx.x;
    float s = 0.f, s2 = 0.f;
    for (int b = 0; b < BB; b++) {
        const float* up = u + ((size_t)b * CC + c) * NN;
        for (int n = tid; n < NN; n += 256) {
            float t = up[n];
            s += t; s2 += t * t;
        }
    }
#pragma unroll
    for (int o = 16; o > 0; o >>= 1) {
        s  += __shfl_xor_sync(0xffffffffu, s, o);
        s2 += __shfl_xor_sync(0xffffffffu, s2, o);
    }
    if ((tid & 31) == 0) { rs[tid >> 5] = s; rs2[tid >> 5] = s2; }
    __syncthreads();
    if (tid == 0) {
        float S = 0.f, S2 = 0.f;
#pragma unroll
        for (int w = 0; w < 8; w++) { S += rs[w]; S2 += rs2[w]; }
        const float cnt = (float)(BB * NN);
        float mean = S / cnt;
        float var = S2 / cnt - mean * mean;
        g_mean[c] = mean;
        g_rstd[c] = rsqrtf(var + 1e-5f);
    }
}

__global__ void bn_relu_kernel(const float* __restrict__ u, const float* __restrict__ x,
                               const float* __restrict__ gamma, const float* __restrict__ beta,
                               float* __restrict__ out) {
    size_t i4 = (size_t)blockIdx.x * blockDim.x + threadIdx.x;
    int c = (int)((i4 * 4 / NN) % CC);
    float m = g_mean[c];
    float r = g_rstd[c] * gamma[c];
    float bt = beta[c];
    float4 uu = ((const float4*)u)[i4];
    float4 xx = ((const float4*)x)[i4];
    float4 o;
    o.x = fmaxf((uu.x - m) * r + bt + xx.x, 0.f);
    o.y = fmaxf((uu.y - m) * r + bt + xx.y, 0.f);
    o.z = fmaxf((uu.z - m) * r + bt + xx.z, 0.f);
    o.w = fmaxf((uu.w - m) * r + bt + xx.w, 0.f);
    ((float4*)out)[i4] = o;
}

// ---------------- launch ------------------------------------------------------
extern "C" void kernel_launch(void* const* d_in, const int* in_sizes, int n_in,
                              void* d_out, int out_size)
{
    const float* x     = (const float*)d_in[0];
    const float* Wv    = (const float*)d_in[1];
    const float* Wq    = (const float*)d_in[2];
    const float* Wk    = (const float*)d_in[3];
    const float* Wu    = (const float*)d_in[4];
    const float* gamma = (const float*)d_in[5];
    const float* beta  = (const float*)d_in[6];
    float* out = (float*)d_out;

    __half *xs_h, *xs_l, *wv, *wqk_h, *wqk_l, *wu;
    __half *qk_h, *qk_l, *vT_h, *vT_l, *P, *y_h, *y_l;
    float *rel, *u;
    cudaGetSymbolAddress((void**)&xs_h,  g_xs_h);  cudaGetSymbolAddress((void**)&xs_l,  g_xs_l);
    cudaGetSymbolAddress((void**)&wv,    g_wv);
    cudaGetSymbolAddress((void**)&wqk_h, g_wqk_h); cudaGetSymbolAddress((void**)&wqk_l, g_wqk_l);
    cudaGetSymbolAddress((void**)&wu,    g_wu);
    cudaGetSymbolAddress((void**)&qk_h,  g_qk_h);  cudaGetSymbolAddress((void**)&qk_l,  g_qk_l);
    cudaGetSymbolAddress((void**)&vT_h,  g_vT_h);  cudaGetSymbolAddress((void**)&vT_l,  g_vT_l);
    cudaGetSymbolAddress((void**)&P,     g_P);
    cudaGetSymbolAddress((void**)&y_h,   g_y_h);   cudaGetSymbolAddress((void**)&y_l,   g_y_l);
    cudaGetSymbolAddress((void**)&rel,   g_rel);
    cudaGetSymbolAddress((void**)&u,     g_u);

    const int SMEM = 3 * STGB;   // 184320 bytes
    cudaFuncSetAttribute(gemm_mma, cudaFuncAttributeMaxDynamicSharedMemorySize, SMEM);

    // ---- prep, ordered so the ncu capture (0-based launch #3) hits v-GEMM ----
    split_transpose<<<dim3(NN / 32, CC / 32, BB), dim3(32, 8)>>>(x);        // 0
    cvt_w<<<(CC * CC + 255) / 256, 256>>>(Wv, wv, CC * CC);                 // 1
    init_rdist<<<32, 256>>>();                                              // 2

    // 3: vT[b][o][m] = Wv[o][:] . xs[m][:]   M=CC, N=NN, K=CC  (2-product) <- ncu
    gemm_mma<<<dim3(NN / 256, CC / 128, BB), 256, SMEM>>>(
        wv, wv, xs_h, xs_l, CC, CC, CC, 0L, (long)NN * CC,
        nullptr, vT_h, vT_l, (long)CC * NN, NN, 2, 2);

    split_w<<<(II * CC + 255) / 256, 256>>>(Wq, wqk_h, wqk_l, II * CC);
    split_w<<<(II * CC + 255) / 256, 256>>>(Wk, wqk_h + II * CC, wqk_l + II * CC, II * CC);
    cvt_w<<<(CC * CC + 255) / 256, 256>>>(Wu, wu, CC * CC);

    // qk[b][n][0:128]=q, [128:256]=k   M=NN, N=256, K=CC  (3-product)
    gemm_mma<<<dim3(1, NN / 128, BB), 256, SMEM>>>(
        xs_h, xs_l, wqk_h, wqk_l, CC, CC, CC, (long)NN * CC, 0L,
        nullptr, qk_h, qk_l, (long)NN * 256, 256, 2, 3);

    // rel[b][n][m] = (q[n].k[m]) / dist   M=NN, N=NN, K=II  (3-product)
    gemm_mma<<<dim3(NN / 256, NN / 128, BB), 256, SMEM>>>(
        qk_h, qk_l, qk_h + II, qk_l + II, II, 256, 256,
        (long)NN * 256, (long)NN * 256,
        rel, nullptr, nullptr, (long)NN * NN, NN, 1, 3);

    // softmax rows -> P (single fp16)
    softmax_f16<<<BB * NN, 256>>>(rel);

    // y[b][n][o] = P[n][:] . vT[o][:]   M=NN, N=CC, K=NN  (2-product)
    gemm_mma<<<dim3(CC / 256, NN / 128, BB), 256, SMEM>>>(
        P, P, vT_h, vT_l, NN, NN, NN, (long)NN * NN, (long)CC * NN,
        nullptr, y_h, y_l, (long)NN * CC, CC, 2, 2);

    // u[b][o][n] = Wu[o][:] . y[n][:]   M=CC, N=NN, K=CC  (2-product)
    gemm_mma<<<dim3(NN / 256, CC / 128, BB), 256, SMEM>>>(
        wu, wu, y_h, y_l, CC, CC, CC, 0L, (long)NN * CC,
        u, nullptr, nullptr, (long)CC * NN, NN, 0, 2);

    bn_stats<<<CC, 256>>>(u);
    bn_relu_kernel<<<(int)(((size_t)BB * CC * NN / 4) / 256), 256>>>(u, x, gamma, beta, out);
}

// round 9
// speedup vs baseline: 1.3052x; 1.0005x over previous
#include <cuda_runtime.h>
#include <cuda_fp16.h>
#include <stdint.h>

#define BB 8
#define CC 512
#define NN 4096
#define II 128

// ---------------- scratch (__device__ globals; no allocation allowed) -------
__device__ __half g_xs_h[(size_t)BB * NN * CC];
__device__ __half g_xs_l[(size_t)BB * NN * CC];
__device__ __half g_wv[CC * CC];                       // single fp16
__device__ __half g_wqk_h[2 * II * CC], g_wqk_l[2 * II * CC];  // Wq rows 0..127, Wk 128..255
__device__ __half g_wu[CC * CC];                       // single fp16
__device__ __half g_qk_h[(size_t)BB * NN * 256], g_qk_l[(size_t)BB * NN * 256];
__device__ __half g_vT_h[(size_t)BB * CC * NN], g_vT_l[(size_t)BB * CC * NN];
__device__ float  g_rel[(size_t)BB * NN * NN];
__device__ __half g_P[(size_t)BB * NN * NN];           // single fp16 probabilities
__device__ __half g_y_h[(size_t)BB * NN * CC], g_y_l[(size_t)BB * NN * CC];
__device__ float  g_u[(size_t)BB * CC * NN];
__device__ float g_mean[CC], g_rstd[CC];
__device__ float g_rdist[8192];   // 1/(sqrt(d2)+1), d2 <= 2*63^2

// ---------------- PTX helpers (portable, non-'a' features only) -------------
__device__ __forceinline__ uint32_t s2u(const void* p) {
    uint32_t a;
    asm("{ .reg .u64 t; cvta.to.shared.u64 t, %1; cvt.u32.u64 %0, t; }" : "=r"(a) : "l"(p));
    return a;
}
__device__ __forceinline__ void cpa16(uint32_t s, const void* g) {
    asm volatile("cp.async.cg.shared.global [%0], [%1], 16;" :: "r"(s), "l"(g) : "memory");
}
__device__ __forceinline__ void cpa_commit() { asm volatile("cp.async.commit_group;" ::: "memory"); }
template <int W> __device__ __forceinline__ void cpa_wait() {
    asm volatile("cp.async.wait_group %0;" :: "n"(W) : "memory");
}
__device__ __forceinline__ void ldsm4(uint32_t* r, uint32_t addr) {
    asm volatile("ldmatrix.sync.aligned.m8n8.x4.shared.b16 {%0,%1,%2,%3}, [%4];"
                 : "=r"(r[0]), "=r"(r[1]), "=r"(r[2]), "=r"(r[3]) : "r"(addr));
}
__device__ __forceinline__ void mma_f16(float* d, const uint32_t* a, const uint32_t* b) {
    asm volatile(
        "mma.sync.aligned.m16n8k16.row.col.f32.f16.f16.f32 "
        "{%0,%1,%2,%3}, {%4,%5,%6,%7}, {%8,%9}, {%0,%1,%2,%3};"
        : "+f"(d[0]), "+f"(d[1]), "+f"(d[2]), "+f"(d[3])
        : "r"(a[0]), "r"(a[1]), "r"(a[2]), "r"(a[3]), "r"(b[0]), "r"(b[1]));
}
// fp16-accumulator MMA (full-rate path) for correction products
__device__ __forceinline__ void mma_f16acc(uint32_t* d, const uint32_t* a, const uint32_t* b) {
    asm volatile(
        "mma.sync.aligned.m16n8k16.row.col.f16.f16.f16.f16 "
        "{%0,%1}, {%2,%3,%4,%5}, {%6,%7}, {%0,%1};"
        : "+r"(d[0]), "+r"(d[1])
        : "r"(a[0]), "r"(a[1]), "r"(a[2]), "r"(a[3]), "r"(b[0]), "r"(b[1]));
}
__device__ __forceinline__ void split_pk(float a, float b, uint32_t& hi, uint32_t& lo) {
    __half2 h, l;
    h.x = __float2half(a); h.y = __float2half(b);
    l.x = __float2half(a - __half2float(h.x));
    l.y = __float2half(b - __half2float(h.y));
    hi = *reinterpret_cast<uint32_t*>(&h);
    lo = *reinterpret_cast<uint32_t*>(&l);
}

// ---------------- split-fp16 HMMA GEMM ---------------------------------------
// C[M,N] = A[M,K] * B[N,K]^T ; operands fp16, K-major, leading dims lda/ldb.
// Template TN: CTA tile is 128 x TN.  8 warps (2m x 4n), warp tile 64 x TN/4.
// F16C==false: A (hi,lo) pair, fp32-acc products per nprod (3: aHbH+aLbH+aHbL).
// F16C==true:  A hi only; aH*bH in fp32 acc, aH*bL correction in fp16 acc.
// 3-stage cp.async pipeline, wait_group<1>.
// modes: 0 = fp32 out, 1 = fp32 * (1/dist) out, 2 = fp16 (hi,lo) pair out.
#define ROWB 80                      // padded row stride (32 fp16 = 64B -> 80B)
#define A_ARR (128 * ROWB)           // 10240

template <int TN, bool F16C>
__global__ void __launch_bounds__(256)
gemm_mma(const __half* __restrict__ Ah_, const __half* __restrict__ Al_,
         const __half* __restrict__ Bh_, const __half* __restrict__ Bl_,
         int K, int lda, int ldb, long a_batch, long b_batch,
         float* __restrict__ Cf,
         __half* __restrict__ Chi, __half* __restrict__ Clo,
         long c_batch, int Nld, int mode, int nprod)
{
    constexpr int B_ARR = TN * ROWB;
    constexpr int BH_OFF = A_ARR * (F16C ? 1 : 2);
    constexpr int BL_OFF = BH_OFF + B_ARR;
    constexpr int STGB = BL_OFF + B_ARR;          // bytes per stage
    constexpr int NT = TN / 32;                   // 8-col n-tiles per warp
    constexpr int NB = TN / 64;                   // B ldsm.x4 loads per warp

    extern __shared__ char smem[];
    const uint32_t sb = s2u(smem);
    const int tid = threadIdx.x;
    const int wid = tid >> 5;
    const int lane = tid & 31;
    const int bz = blockIdx.z;
    const int m0 = blockIdx.y * 128;
    const int n0 = blockIdx.x * TN;
    const int warp_m = wid >> 2;     // 0..1 -> 64 rows each
    const int warp_n = wid & 3;      // 0..3 -> TN/4 cols each

    const __half* Ah = Ah_ + (size_t)bz * a_batch + (size_t)m0 * lda;
    const __half* Al = Al_ + (size_t)bz * a_batch + (size_t)m0 * lda;
    const __half* Bh = Bh_ + (size_t)bz * b_batch + (size_t)n0 * ldb;
    const __half* Bl = Bl_ + (size_t)bz * b_batch + (size_t)n0 * ldb;

    const int nch = K >> 5;

    auto load_chunk = [&](int ci, int stg) {
        const uint32_t st = sb + stg * STGB;
        const size_t k0 = (size_t)ci * 32;
#pragma unroll
        for (int p = 0; p < 2; p++) {            // A: 128 rows x 4 sectors
            int f = tid + p * 256;
            int r = f >> 2, s = f & 3;
            uint32_t so = (uint32_t)r * ROWB + s * 16;
            size_t go = (size_t)r * lda + k0 + s * 8;
            cpa16(st + so, Ah + go);
            if (!F16C && nprod == 3) cpa16(st + A_ARR + so, Al + go);
        }
#pragma unroll
        for (int p = 0; p < TN / 64; p++) {      // B: TN rows x 4 sectors
            int f = tid + p * 256;
            int r = f >> 2, s = f & 3;
            uint32_t so = (uint32_t)r * ROWB + s * 16;
            size_t go = (size_t)r * ldb + k0 + s * 8;
            cpa16(st + BH_OFF + so, Bh + go);
            cpa16(st + BL_OFF + so, Bl + go);
        }
        cpa_commit();
    };

    load_chunk(0, 0);
    load_chunk(1, 1);      // nch >= 4 for all our shapes

    // lane offsets for ldmatrix (bytes)
    const int lt = lane & 7, ltile = lane >> 3;
    const uint32_t aLane = (uint32_t)(lt + ((ltile & 1) << 3)) * ROWB + ((ltile >> 1) << 4);
    const uint32_t bLane = (uint32_t)(lt + ((ltile >> 1) << 3)) * ROWB + ((ltile & 1) << 4);

    float acc[4][NT][4];
#pragma unroll
    for (int i = 0; i < 4; i++)
#pragma unroll
        for (int j = 0; j < NT; j++)
#pragma unroll
            for (int c = 0; c < 4; c++) acc[i][j][c] = 0.f;

    uint32_t acc16[4][NT][2];
    if (F16C) {
#pragma unroll
        for (int i = 0; i < 4; i++)
#pragma unroll
            for (int j = 0; j < NT; j++) { acc16[i][j][0] = 0u; acc16[i][j][1] = 0u; }
    }

    for (int i = 0; i < nch; i++) {
        const uint32_t st = sb + (i % 3) * STGB;
        if (i + 1 < nch) cpa_wait<1>(); else cpa_wait<0>();
        __syncthreads();
        if (i + 2 < nch) load_chunk(i + 2, (i + 2) % 3);

        const uint32_t aBh = st +          (uint32_t)warp_m * 64 * ROWB + aLane;
        const uint32_t aBl = st + A_ARR +  (uint32_t)warp_m * 64 * ROWB + aLane;
        const uint32_t bBh = st + BH_OFF + (uint32_t)(warp_n * (TN / 4)) * ROWB + bLane;
        const uint32_t bBl = st + BL_OFF + (uint32_t)(warp_n * (TN / 4)) * ROWB + bLane;

#pragma unroll
        for (int ks = 0; ks < 2; ks++) {
            const uint32_t ko = ks * 32;
            uint32_t aH[4][4], bH[NB][4];
#pragma unroll
            for (int mt = 0; mt < 4; mt++) ldsm4(aH[mt], aBh + mt * 16 * ROWB + ko);
#pragma unroll
            for (int np = 0; np < NB; np++) ldsm4(bH[np], bBh + np * 16 * ROWB + ko);
#pragma unroll
            for (int mt = 0; mt < 4; mt++)
#pragma unroll
                for (int nt = 0; nt < NT; nt++)
                    mma_f16(acc[mt][nt], aH[mt], &bH[nt >> 1][(nt & 1) * 2]);
            if (!F16C && nprod == 3) {
                uint32_t aL[4][4];
#pragma unroll
                for (int mt = 0; mt < 4; mt++) ldsm4(aL[mt], aBl + mt * 16 * ROWB + ko);
#pragma unroll
                for (int mt = 0; mt < 4; mt++)
#pragma unroll
                    for (int nt = 0; nt < NT; nt++)
                        mma_f16(acc[mt][nt], aL[mt], &bH[nt >> 1][(nt & 1) * 2]);
            }
            {
                uint32_t bL[NB][4];
#pragma unroll
                for (int np = 0; np < NB; np++) ldsm4(bL[np], bBl + np * 16 * ROWB + ko);
                if (F16C) {
#pragma unroll
                    for (int mt = 0; mt < 4; mt++)
#pragma unroll
                        for (int nt = 0; nt < NT; nt++)
                            mma_f16acc(acc16[mt][nt], aH[mt], &bL[nt >> 1][(nt & 1) * 2]);
                } else {
#pragma unroll
                    for (int mt = 0; mt < 4; mt++)
#pragma unroll
                        for (int nt = 0; nt < NT; nt++)
                            mma_f16(acc[mt][nt], aH[mt], &bL[nt >> 1][(nt & 1) * 2]);
                }
            }
        }
    }

    // ---- epilogue ----
    const int gp = lane >> 2, tq = lane & 3;
    const int mbase = m0 + warp_m * 64;
    const int nbase = n0 + warp_n * (TN / 4);

#pragma unroll
    for (int mt = 0; mt < 4; mt++) {
#pragma unroll
        for (int half = 0; half < 2; half++) {
            const int r = mbase + mt * 16 + half * 8 + gp;
            if (mode == 2) {
                __half* oh = Chi + (size_t)bz * c_batch + (size_t)r * Nld;
                __half* ol = Clo + (size_t)bz * c_batch + (size_t)r * Nld;
#pragma unroll
                for (int nt = 0; nt < NT; nt++) {
                    const int col = nbase + nt * 8 + 2 * tq;
                    float v0 = acc[mt][nt][half * 2];
                    float v1 = acc[mt][nt][half * 2 + 1];
                    if (F16C) {
                        __half2 c = *reinterpret_cast<__half2*>(&acc16[mt][nt][half]);
                        v0 += __half2float(c.x);
                        v1 += __half2float(c.y);
                    }
                    uint32_t hi, lo;
                    split_pk(v0, v1, hi, lo);
                    *(uint32_t*)(oh + col) = hi;
                    *(uint32_t*)(ol + col) = lo;
                }
            } else {
                float* oc = Cf + (size_t)bz * c_batch + (size_t)r * Nld;
                if (mode == 1) {
                    const int ri = r >> 6, rj = r & 63;
#pragma unroll
                    for (int nt = 0; nt < NT; nt++) {
                        const int col = nbase + nt * 8 + 2 * tq;
                        int di0 = ri - (col >> 6);
                        int j0 = rj - (col & 63);
                        int j1 = rj - ((col + 1) & 63);
                        float2 o;
                        o.x = acc[mt][nt][half * 2]     * g_rdist[di0 * di0 + j0 * j0];
                        o.y = acc[mt][nt][half * 2 + 1] * g_rdist[di0 * di0 + j1 * j1];
                        *(float2*)(oc + col) = o;
                    }
                } else {
#pragma unroll
                    for (int nt = 0; nt < NT; nt++) {
                        const int col = nbase + nt * 8 + 2 * tq;
                        float v0 = acc[mt][nt][half * 2];
                        float v1 = acc[mt][nt][half * 2 + 1];
                        if (F16C) {
                            __half2 c = *reinterpret_cast<__half2*>(&acc16[mt][nt][half]);
                            v0 += __half2float(c.x);
                            v1 += __half2float(c.y);
                        }
                        float2 o; o.x = v0; o.y = v1;
                        *(float2*)(oc + col) = o;
                    }
                }
            }
        }
    }
}

// ---------------- prep kernels ----------------------------------------------
__global__ void init_rdist() {
    int i = blockIdx.x * 256 + threadIdx.x;
    if (i < 8192) g_rdist[i] = 1.0f / (sqrtf((float)i) + 1.0f);
}

// fp32 -> single fp16
__global__ void cvt_w(const float* __restrict__ w, __half* __restrict__ h, int n) {
    int i = blockIdx.x * 256 + threadIdx.x;
    if (i < n) h[i] = __float2half(w[i]);
}

// fp32 -> fp16 pair
__global__ void split_w(const float* __restrict__ w, __half* __restrict__ h,
                        __half* __restrict__ l, int n) {
    int i = blockIdx.x * 256 + threadIdx.x;
    if (i < n) {
        float v = w[i];
        __half hh = __float2half(v);
        h[i] = hh;
        l[i] = __float2half(v - __half2float(hh));
    }
}

// x[b][c][n] -> xs[b][n][c] as fp16 hi/lo
__global__ void split_transpose(const float* __restrict__ x) {
    __shared__ float t[32][33];
    const int b = blockIdx.z;
    const int n0 = blockIdx.x << 5, c0 = blockIdx.y << 5;
    const int tx = threadIdx.x, ty = threadIdx.y;
    const float* xp = x + ((size_t)b * CC + c0) * NN + n0;
#pragma unroll
    for (int i = 0; i < 4; i++) t[ty + i * 8][tx] = xp[(size_t)(ty + i * 8) * NN + tx];
    __syncthreads();
    const size_t ob = ((size_t)b * NN + n0) * CC + c0;
#pragma unroll
    for (int i = 0; i < 4; i++) {
        float v = t[tx][ty + i * 8];
        __half h = __float2half(v);
        size_t o = ob + (size_t)(ty + i * 8) * CC + tx;
        g_xs_h[o] = h;
        g_xs_l[o] = __float2half(v - __half2float(h));
    }
}

// row softmax, fp32 in -> single fp16 out
__global__ void softmax_f16(const float* __restrict__ rel) {
    __shared__ float red1[8], red2[8];
    const size_t row = blockIdx.x;
    const float4* p = (const float4*)(rel + row * (size_t)NN);
    const int tid = threadIdx.x;

    float4 v[4];
    float mx = -3.0e38f;
#pragma unroll
    for (int i = 0; i < 4; i++) {
        v[i] = p[tid + i * 256];
        mx = fmaxf(mx, fmaxf(fmaxf(v[i].x, v[i].y), fmaxf(v[i].z, v[i].w)));
    }
#pragma unroll
    for (int o = 16; o > 0; o >>= 1) mx = fmaxf(mx, __shfl_xor_sync(0xffffffffu, mx, o));
    if ((tid & 31) == 0) red1[tid >> 5] = mx;
    __syncthreads();
    mx = red1[0];
#pragma unroll
    for (int w = 1; w < 8; w++) mx = fmaxf(mx, red1[w]);

    float s = 0.f;
#pragma unroll
    for (int i = 0; i < 4; i++) {
        v[i].x = __expf(v[i].x - mx); v[i].y = __expf(v[i].y - mx);
        v[i].z = __expf(v[i].z - mx); v[i].w = __expf(v[i].w - mx);
        s += v[i].x + v[i].y + v[i].z + v[i].w;
    }
#pragma unroll
    for (int o = 16; o > 0; o >>= 1) s += __shfl_xor_sync(0xffffffffu, s, o);
    if ((tid & 31) == 0) red2[tid >> 5] = s;
    __syncthreads();
    s = 0.f;
#pragma unroll
    for (int w = 0; w < 8; w++) s += red2[w];
    const float inv = 1.0f / s;

    uint2* P = (uint2*)(g_P + row * (size_t)NN);
#pragma unroll
    for (int i = 0; i < 4; i++) {
        __half2 a, b;
        a.x = __float2half(v[i].x * inv); a.y = __float2half(v[i].y * inv);
        b.x = __float2half(v[i].z * inv); b.y = __float2half(v[i].w * inv);
        uint2 o;
        o.x = *reinterpret_cast<uint32_t*>(&a);
        o.y = *reinterpret_cast<uint32_t*>(&b);
        P[tid + i * 256] = o;
    }
}

// ---------------- BN ---------------------------------------------------------
__global__ void bn_stats(const float* __restrict__ u) {
    __shared__ float rs[8], rs2[8];
    const int c = blockIdx.x;
    const int tid = threadIdx.x;
    float s = 0.f, s2 = 0.f;
    for (int b = 0; b < BB; b++) {
        const float* up = u + ((size_t)b * CC + c) * NN;
        for (int n = tid; n < NN; n += 256) {
            float t = up[n];
            s += t; s2 += t * t;
        }
    }
#pragma unroll
    for (int o = 16; o > 0; o >>= 1) {
        s  += __shfl_xor_sync(0xffffffffu, s, o);
        s2 += __shfl_xor_sync(0xffffffffu, s2, o);
    }
    if ((tid & 31) == 0) { rs[tid >> 5] = s; rs2[tid >> 5] = s2; }
    __syncthreads();
    if (tid == 0) {
        float S = 0.f, S2 = 0.f;
#pragma unroll
        for (int w = 0; w < 8; w++) { S += rs[w]; S2 += rs2[w]; }
        const float cnt = (float)(BB * NN);
        float mean = S / cnt;
        float var = S2 / cnt - mean * mean;
        g_mean[c] = mean;
        g_rstd[c] = rsqrtf(var + 1e-5f);
    }
}

__global__ void bn_relu_kernel(const float* __restrict__ u, const float* __restrict__ x,
                               const float* __restrict__ gamma, const float* __restrict__ beta,
                               float* __restrict__ out) {
    size_t i4 = (size_t)blockIdx.x * blockDim.x + threadIdx.x;
    int c = (int)((i4 * 4 / NN) % CC);
    float m = g_mean[c];
    float r = g_rstd[c] * gamma[c];
    float bt = beta[c];
    float4 uu = ((const float4*)u)[i4];
    float4 xx = ((const float4*)x)[i4];
    float4 o;
    o.x = fmaxf((uu.x - m) * r + bt + xx.x, 0.f);
    o.y = fmaxf((uu.y - m) * r + bt + xx.y, 0.f);
    o.z = fmaxf((uu.z - m) * r + bt + xx.z, 0.f);
    o.w = fmaxf((uu.w - m) * r + bt + xx.w, 0.f);
    ((float4*)out)[i4] = o;
}

// ---------------- launch ------------------------------------------------------
extern "C" void kernel_launch(void* const* d_in, const int* in_sizes, int n_in,
                              void* d_out, int out_size)
{
    const float* x     = (const float*)d_in[0];
    const float* Wv    = (const float*)d_in[1];
    const float* Wq    = (const float*)d_in[2];
    const float* Wk    = (const float*)d_in[3];
    const float* Wu    = (const float*)d_in[4];
    const float* gamma = (const float*)d_in[5];
    const float* beta  = (const float*)d_in[6];
    float* out = (float*)d_out;

    __half *xs_h, *xs_l, *wv, *wqk_h, *wqk_l, *wu;
    __half *qk_h, *qk_l, *vT_h, *vT_l, *P, *y_h, *y_l;
    float *rel, *u;
    cudaGetSymbolAddress((void**)&xs_h,  g_xs_h);  cudaGetSymbolAddress((void**)&xs_l,  g_xs_l);
    cudaGetSymbolAddress((void**)&wv,    g_wv);
    cudaGetSymbolAddress((void**)&wqk_h, g_wqk_h); cudaGetSymbolAddress((void**)&wqk_l, g_wqk_l);
    cudaGetSymbolAddress((void**)&wu,    g_wu);
    cudaGetSymbolAddress((void**)&qk_h,  g_qk_h);  cudaGetSymbolAddress((void**)&qk_l,  g_qk_l);
    cudaGetSymbolAddress((void**)&vT_h,  g_vT_h);  cudaGetSymbolAddress((void**)&vT_l,  g_vT_l);
    cudaGetSymbolAddress((void**)&P,     g_P);
    cudaGetSymbolAddress((void**)&y_h,   g_y_h);   cudaGetSymbolAddress((void**)&y_l,   g_y_l);
    cudaGetSymbolAddress((void**)&rel,   g_rel);
    cudaGetSymbolAddress((void**)&u,     g_u);

    // smem sizes: <128,true>: (A_hi + 2*B128) * 3 = 30720*3 = 92160
    //             <256,false>: (2*A + 2*B256) * 3 = 61440*3 = 184320
    const int SMEM_C = 3 * (A_ARR + 2 * 128 * ROWB);
    const int SMEM_W = 3 * (2 * A_ARR + 2 * 256 * ROWB);
    cudaFuncSetAttribute(gemm_mma<128, true>,  cudaFuncAttributeMaxDynamicSharedMemorySize, SMEM_C);
    cudaFuncSetAttribute(gemm_mma<256, false>, cudaFuncAttributeMaxDynamicSharedMemorySize, SMEM_W);

    // ---- prep, ordered so the ncu capture (0-based launch #3) hits v-GEMM ----
    split_transpose<<<dim3(NN / 32, CC / 32, BB), dim3(32, 8)>>>(x);        // 0
    cvt_w<<<(CC * CC + 255) / 256, 256>>>(Wv, wv, CC * CC);                 // 1
    init_rdist<<<32, 256>>>();                                              // 2

    // 3: vT[b][o][m] = Wv[o][:] . xs[m][:]   M=CC, N=NN, K=CC  (f16-corr) <- ncu
    gemm_mma<128, true><<<dim3(NN / 128, CC / 128, BB), 256, SMEM_C>>>(
        wv, wv, xs_h, xs_l, CC, CC, CC, 0L, (long)NN * CC,
        nullptr, vT_h, vT_l, (long)CC * NN, NN, 2, 2);

    split_w<<<(II * CC + 255) / 256, 256>>>(Wq, wqk_h, wqk_l, II * CC);
    split_w<<<(II * CC + 255) / 256, 256>>>(Wk, wqk_h + II * CC, wqk_l + II * CC, II * CC);
    cvt_w<<<(CC * CC + 255) / 256, 256>>>(Wu, wu, CC * CC);

    // qk[b][n][0:128]=q, [128:256]=k   M=NN, N=256, K=CC  (3-product fp32)
    gemm_mma<256, false><<<dim3(1, NN / 128, BB), 256, SMEM_W>>>(
        xs_h, xs_l, wqk_h, wqk_l, CC, CC, CC, (long)NN * CC, 0L,
        nullptr, qk_h, qk_l, (long)NN * 256, 256, 2, 3);

    // rel[b][n][m] = (q[n].k[m]) / dist   M=NN, N=NN, K=II  (3-product fp32)
    gemm_mma<256, false><<<dim3(NN / 256, NN / 128, BB), 256, SMEM_W>>>(
        qk_h, qk_l, qk_h + II, qk_l + II, II, 256, 256,
        (long)NN * 256, (long)NN * 256,
        rel, nullptr, nullptr, (long)NN * NN, NN, 1, 3);

    // softmax rows -> P (single fp16)
    softmax_f16<<<BB * NN, 256>>>(rel);

    // y[b][n][o] = P[n][:] . vT[o][:]   M=NN, N=CC, K=NN  (f16-corr)
    gemm_mma<128, true><<<dim3(CC / 128, NN / 128, BB), 256, SMEM_C>>>(
        P, P, vT_h, vT_l, NN, NN, NN, (long)NN * NN, (long)CC * NN,
        nullptr, y_h, y_l, (long)NN * CC, CC, 2, 2);

    // u[b][o][n] = Wu[o][:] . y[n][:]   M=CC, N=NN, K=CC  (f16-corr)
    gemm_mma<128, true><<<dim3(NN / 128, CC / 128, BB), 256, SMEM_C>>>(
        wu, wu, y_h, y_l, CC, CC, CC, 0L, (long)NN * CC,
        u, nullptr, nullptr, (long)CC * NN, NN, 0, 2);

    bn_stats<<<CC, 256>>>(u);
    bn_relu_kernel<<<(int)(((size_t)BB * CC * NN / 4) / 256), 256>>>(u, x, gamma, beta, out);
}

// round 10
// speedup vs baseline: 1.6765x; 1.2845x over previous
#include <cuda_runtime.h>
#include <cuda_fp16.h>
#include <stdint.h>

#define BB 8
#define CC 512
#define NN 4096
#define II 128

// ---------------- scratch (__device__ globals; no allocation allowed) -------
__device__ __half g_xs_h[(size_t)BB * NN * CC];
__device__ __half g_xs_l[(size_t)BB * NN * CC];
__device__ __half g_wv[CC * CC];                       // single fp16
__device__ __half g_wqk_h[2 * II * CC], g_wqk_l[2 * II * CC];  // Wq rows 0..127, Wk 128..255
__device__ __half g_wu[CC * CC];                       // single fp16
__device__ __half g_qk_h[(size_t)BB * NN * 256], g_qk_l[(size_t)BB * NN * 256];
__device__ __half g_vT_h[(size_t)BB * CC * NN], g_vT_l[(size_t)BB * CC * NN];
__device__ float  g_rel[(size_t)BB * NN * NN];
__device__ __half g_P[(size_t)BB * NN * NN];           // single fp16 probabilities
__device__ __half g_y_h[(size_t)BB * NN * CC], g_y_l[(size_t)BB * NN * CC];
__device__ float  g_u[(size_t)BB * CC * NN];
__device__ float g_mean[CC], g_rstd[CC];
__device__ float g_rdist[8192];   // 1/(sqrt(d2)+1), d2 <= 2*63^2

// ---------------- PTX helpers (portable, non-'a' features only) -------------
__device__ __forceinline__ uint32_t s2u(const void* p) {
    uint32_t a;
    asm("{ .reg .u64 t; cvta.to.shared.u64 t, %1; cvt.u32.u64 %0, t; }" : "=r"(a) : "l"(p));
    return a;
}
__device__ __forceinline__ void cpa16(uint32_t s, const void* g) {
    asm volatile("cp.async.cg.shared.global [%0], [%1], 16;" :: "r"(s), "l"(g) : "memory");
}
__device__ __forceinline__ void cpa_commit() { asm volatile("cp.async.commit_group;" ::: "memory"); }
template <int W> __device__ __forceinline__ void cpa_wait() {
    asm volatile("cp.async.wait_group %0;" :: "n"(W) : "memory");
}
__device__ __forceinline__ void ldsm4(uint32_t* r, uint32_t addr) {
    asm volatile("ldmatrix.sync.aligned.m8n8.x4.shared.b16 {%0,%1,%2,%3}, [%4];"
                 : "=r"(r[0]), "=r"(r[1]), "=r"(r[2]), "=r"(r[3]) : "r"(addr));
}
__device__ __forceinline__ void mma_f16(float* d, const uint32_t* a, const uint32_t* b) {
    asm volatile(
        "mma.sync.aligned.m16n8k16.row.col.f32.f16.f16.f32 "
        "{%0,%1,%2,%3}, {%4,%5,%6,%7}, {%8,%9}, {%0,%1,%2,%3};"
        : "+f"(d[0]), "+f"(d[1]), "+f"(d[2]), "+f"(d[3])
        : "r"(a[0]), "r"(a[1]), "r"(a[2]), "r"(a[3]), "r"(b[0]), "r"(b[1]));
}
// fp16-accumulator MMA for correction products
__device__ __forceinline__ void mma_f16acc(uint32_t* d, const uint32_t* a, const uint32_t* b) {
    asm volatile(
        "mma.sync.aligned.m16n8k16.row.col.f16.f16.f16.f16 "
        "{%0,%1}, {%2,%3,%4,%5}, {%6,%7}, {%0,%1};"
        : "+r"(d[0]), "+r"(d[1])
        : "r"(a[0]), "r"(a[1]), "r"(a[2]), "r"(a[3]), "r"(b[0]), "r"(b[1]));
}
__device__ __forceinline__ void split_pk(float a, float b, uint32_t& hi, uint32_t& lo) {
    __half2 h, l;
    h.x = __float2half(a); h.y = __float2half(b);
    l.x = __float2half(a - __half2float(h.x));
    l.y = __float2half(b - __half2float(h.y));
    hi = *reinterpret_cast<uint32_t*>(&h);
    lo = *reinterpret_cast<uint32_t*>(&l);
}

// ---------------- split-fp16 HMMA GEMM ---------------------------------------
// C[M,N] = A[M,K] * B[N,K]^T ; operands fp16, K-major, leading dims lda/ldb.
// Template TN: CTA tile is 128 x TN.  8 warps (2m x 4n), warp tile 64 x TN/4.
// F16C==false: A (hi,lo) pair, fp32-acc products per nprod (3: aHbH+aLbH+aHbL).
// F16C==true:  nprod==2: aH*bH fp32-acc + aH*bL corr in fp16-acc.
//              nprod==1: aH*bH only (single x single).
// 3-stage cp.async pipeline, wait_group<1>.
// modes: 0 = fp32 out, 1 = fp32 * (1/dist) out, 2 = fp16 (hi,lo) pair out.
#define ROWB 80                      // padded row stride (32 fp16 = 64B -> 80B)
#define A_ARR (128 * ROWB)           // 10240

template <int TN, bool F16C>
__global__ void __launch_bounds__(256)
gemm_mma(const __half* __restrict__ Ah_, const __half* __restrict__ Al_,
         const __half* __restrict__ Bh_, const __half* __restrict__ Bl_,
         int K, int lda, int ldb, long a_batch, long b_batch,
         float* __restrict__ Cf,
         __half* __restrict__ Chi, __half* __restrict__ Clo,
         long c_batch, int Nld, int mode, int nprod)
{
    constexpr int B_ARR = TN * ROWB;
    constexpr int BH_OFF = A_ARR * (F16C ? 1 : 2);
    constexpr int BL_OFF = BH_OFF + B_ARR;
    constexpr int STGB = BL_OFF + B_ARR;          // bytes per stage
    constexpr int NT = TN / 32;                   // 8-col n-tiles per warp
    constexpr int NB = TN / 64;                   // B ldsm.x4 loads per warp

    extern __shared__ char smem[];
    const uint32_t sb = s2u(smem);
    const int tid = threadIdx.x;
    const int wid = tid >> 5;
    const int lane = tid & 31;
    const int bz = blockIdx.z;
    const int m0 = blockIdx.y * 128;
    const int n0 = blockIdx.x * TN;
    const int warp_m = wid >> 2;     // 0..1 -> 64 rows each
    const int warp_n = wid & 3;      // 0..3 -> TN/4 cols each

    const __half* Ah = Ah_ + (size_t)bz * a_batch + (size_t)m0 * lda;
    const __half* Al = Al_ + (size_t)bz * a_batch + (size_t)m0 * lda;
    const __half* Bh = Bh_ + (size_t)bz * b_batch + (size_t)n0 * ldb;
    const __half* Bl = Bl_ + (size_t)bz * b_batch + (size_t)n0 * ldb;

    const int nch = K >> 5;

    auto load_chunk = [&](int ci, int stg) {
        const uint32_t st = sb + stg * STGB;
        const size_t k0 = (size_t)ci * 32;
#pragma unroll
        for (int p = 0; p < 2; p++) {            // A: 128 rows x 4 sectors
            int f = tid + p * 256;
            int r = f >> 2, s = f & 3;
            uint32_t so = (uint32_t)r * ROWB + s * 16;
            size_t go = (size_t)r * lda + k0 + s * 8;
            cpa16(st + so, Ah + go);
            if (!F16C && nprod == 3) cpa16(st + A_ARR + so, Al + go);
        }
#pragma unroll
        for (int p = 0; p < TN / 64; p++) {      // B: TN rows x 4 sectors
            int f = tid + p * 256;
            int r = f >> 2, s = f & 3;
            uint32_t so = (uint32_t)r * ROWB + s * 16;
            size_t go = (size_t)r * ldb + k0 + s * 8;
            cpa16(st + BH_OFF + so, Bh + go);
            if (nprod >= 2) cpa16(st + BL_OFF + so, Bl + go);
        }
        cpa_commit();
    };

    load_chunk(0, 0);
    load_chunk(1, 1);      // nch >= 4 for all our shapes

    // lane offsets for ldmatrix (bytes)
    const int lt = lane & 7, ltile = lane >> 3;
    const uint32_t aLane = (uint32_t)(lt + ((ltile & 1) << 3)) * ROWB + ((ltile >> 1) << 4);
    const uint32_t bLane = (uint32_t)(lt + ((ltile >> 1) << 3)) * ROWB + ((ltile & 1) << 4);

    float acc[4][NT][4];
#pragma unroll
    for (int i = 0; i < 4; i++)
#pragma unroll
        for (int j = 0; j < NT; j++)
#pragma unroll
            for (int c = 0; c < 4; c++) acc[i][j][c] = 0.f;

    uint32_t acc16[4][NT][2];
    if (F16C) {
#pragma unroll
        for (int i = 0; i < 4; i++)
#pragma unroll
            for (int j = 0; j < NT; j++) { acc16[i][j][0] = 0u; acc16[i][j][1] = 0u; }
    }

    for (int i = 0; i < nch; i++) {
        const uint32_t st = sb + (i % 3) * STGB;
        if (i + 1 < nch) cpa_wait<1>(); else cpa_wait<0>();
        __syncthreads();
        if (i + 2 < nch) load_chunk(i + 2, (i + 2) % 3);

        const uint32_t aBh = st +          (uint32_t)warp_m * 64 * ROWB + aLane;
        const uint32_t aBl = st + A_ARR +  (uint32_t)warp_m * 64 * ROWB + aLane;
        const uint32_t bBh = st + BH_OFF + (uint32_t)(warp_n * (TN / 4)) * ROWB + bLane;
        const uint32_t bBl = st + BL_OFF + (uint32_t)(warp_n * (TN / 4)) * ROWB + bLane;

#pragma unroll
        for (int ks = 0; ks < 2; ks++) {
            const uint32_t ko = ks * 32;
            uint32_t aH[4][4], bH[NB][4];
#pragma unroll
            for (int mt = 0; mt < 4; mt++) ldsm4(aH[mt], aBh + mt * 16 * ROWB + ko);
#pragma unroll
            for (int np = 0; np < NB; np++) ldsm4(bH[np], bBh + np * 16 * ROWB + ko);
#pragma unroll
            for (int mt = 0; mt < 4; mt++)
#pragma unroll
                for (int nt = 0; nt < NT; nt++)
                    mma_f16(acc[mt][nt], aH[mt], &bH[nt >> 1][(nt & 1) * 2]);
            if (!F16C && nprod == 3) {
                uint32_t aL[4][4];
#pragma unroll
                for (int mt = 0; mt < 4; mt++) ldsm4(aL[mt], aBl + mt * 16 * ROWB + ko);
#pragma unroll
                for (int mt = 0; mt < 4; mt++)
#pragma unroll
                    for (int nt = 0; nt < NT; nt++)
                        mma_f16(acc[mt][nt], aL[mt], &bH[nt >> 1][(nt & 1) * 2]);
            }
            if (nprod >= 2) {
                uint32_t bL[NB][4];
#pragma unroll
                for (int np = 0; np < NB; np++) ldsm4(bL[np], bBl + np * 16 * ROWB + ko);
                if (F16C) {
#pragma unroll
                    for (int mt = 0; mt < 4; mt++)
#pragma unroll
                        for (int nt = 0; nt < NT; nt++)
                            mma_f16acc(acc16[mt][nt], aH[mt], &bL[nt >> 1][(nt & 1) * 2]);
                } else {
#pragma unroll
                    for (int mt = 0; mt < 4; mt++)
#pragma unroll
                        for (int nt = 0; nt < NT; nt++)
                            mma_f16(acc[mt][nt], aH[mt], &bL[nt >> 1][(nt & 1) * 2]);
                }
            }
        }
    }

    // ---- epilogue ----
    const int gp = lane >> 2, tq = lane & 3;
    const int mbase = m0 + warp_m * 64;
    const int nbase = n0 + warp_n * (TN / 4);

#pragma unroll
    for (int mt = 0; mt < 4; mt++) {
#pragma unroll
        for (int half = 0; half < 2; half++) {
            const int r = mbase + mt * 16 + half * 8 + gp;
            if (mode == 2) {
                __half* oh = Chi + (size_t)bz * c_batch + (size_t)r * Nld;
                __half* ol = Clo + (size_t)bz * c_batch + (size_t)r * Nld;
#pragma unroll
                for (int nt = 0; nt < NT; nt++) {
                    const int col = nbase + nt * 8 + 2 * tq;
                    float v0 = acc[mt][nt][half * 2];
                    float v1 = acc[mt][nt][half * 2 + 1];
                    if (F16C) {
                        __half2 c = *reinterpret_cast<__half2*>(&acc16[mt][nt][half]);
                        v0 += __half2float(c.x);
                        v1 += __half2float(c.y);
                    }
                    uint32_t hi, lo;
                    split_pk(v0, v1, hi, lo);
                    *(uint32_t*)(oh + col) = hi;
                    *(uint32_t*)(ol + col) = lo;
                }
            } else {
                float* oc = Cf + (size_t)bz * c_batch + (size_t)r * Nld;
                if (mode == 1) {
                    const int ri = r >> 6, rj = r & 63;
#pragma unroll
                    for (int nt = 0; nt < NT; nt++) {
                        const int col = nbase + nt * 8 + 2 * tq;
                        int di0 = ri - (col >> 6);
                        int j0 = rj - (col & 63);
                        int j1 = rj - ((col + 1) & 63);
                        float2 o;
                        o.x = acc[mt][nt][half * 2]     * g_rdist[di0 * di0 + j0 * j0];
                        o.y = acc[mt][nt][half * 2 + 1] * g_rdist[di0 * di0 + j1 * j1];
                        *(float2*)(oc + col) = o;
                    }
                } else {
#pragma unroll
                    for (int nt = 0; nt < NT; nt++) {
                        const int col = nbase + nt * 8 + 2 * tq;
                        float v0 = acc[mt][nt][half * 2];
                        float v1 = acc[mt][nt][half * 2 + 1];
                        if (F16C) {
                            __half2 c = *reinterpret_cast<__half2*>(&acc16[mt][nt][half]);
                            v0 += __half2float(c.x);
                            v1 += __half2float(c.y);
                        }
                        float2 o; o.x = v0; o.y = v1;
                        *(float2*)(oc + col) = o;
                    }
                }
            }
        }
    }
}

// ---------------- prep kernels ----------------------------------------------
__global__ void init_rdist() {
    int i = blockIdx.x * 256 + threadIdx.x;
    if (i < 8192) g_rdist[i] = 1.0f / (sqrtf((float)i) + 1.0f);
}

// fp32 -> single fp16
__global__ void cvt_w(const float* __restrict__ w, __half* __restrict__ h, int n) {
    int i = blockIdx.x * 256 + threadIdx.x;
    if (i < n) h[i] = __float2half(w[i]);
}

// fp32 -> fp16 pair
__global__ void split_w(const float* __restrict__ w, __half* __restrict__ h,
                        __half* __restrict__ l, int n) {
    int i = blockIdx.x * 256 + threadIdx.x;
    if (i < n) {
        float v = w[i];
        __half hh = __float2half(v);
        h[i] = hh;
        l[i] = __float2half(v - __half2float(hh));
    }
}

// x[b][c][n] -> xs[b][n][c] as fp16 hi/lo
__global__ void split_transpose(const float* __restrict__ x) {
    __shared__ float t[32][33];
    const int b = blockIdx.z;
    const int n0 = blockIdx.x << 5, c0 = blockIdx.y << 5;
    const int tx = threadIdx.x, ty = threadIdx.y;
    const float* xp = x + ((size_t)b * CC + c0) * NN + n0;
#pragma unroll
    for (int i = 0; i < 4; i++) t[ty + i * 8][tx] = xp[(size_t)(ty + i * 8) * NN + tx];
    __syncthreads();
    const size_t ob = ((size_t)b * NN + n0) * CC + c0;
#pragma unroll
    for (int i = 0; i < 4; i++) {
        float v = t[tx][ty + i * 8];
        __half h = __float2half(v);
        size_t o = ob + (size_t)(ty + i * 8) * CC + tx;
        g_xs_h[o] = h;
        g_xs_l[o] = __float2half(v - __half2float(h));
    }
}

// row softmax, fp32 in -> single fp16 out
__global__ void softmax_f16(const float* __restrict__ rel) {
    __shared__ float red1[8], red2[8];
    const size_t row = blockIdx.x;
    const float4* p = (const float4*)(rel + row * (size_t)NN);
    const int tid = threadIdx.x;

    float4 v[4];
    float mx = -3.0e38f;
#pragma unroll
    for (int i = 0; i < 4; i++) {
        v[i] = p[tid + i * 256];
        mx = fmaxf(mx, fmaxf(fmaxf(v[i].x, v[i].y), fmaxf(v[i].z, v[i].w)));
    }
#pragma unroll
    for (int o = 16; o > 0; o >>= 1) mx = fmaxf(mx, __shfl_xor_sync(0xffffffffu, mx, o));
    if ((tid & 31) == 0) red1[tid >> 5] = mx;
    __syncthreads();
    mx = red1[0];
#pragma unroll
    for (int w = 1; w < 8; w++) mx = fmaxf(mx, red1[w]);

    float s = 0.f;
#pragma unroll
    for (int i = 0; i < 4; i++) {
        v[i].x = __expf(v[i].x - mx); v[i].y = __expf(v[i].y - mx);
        v[i].z = __expf(v[i].z - mx); v[i].w = __expf(v[i].w - mx);
        s += v[i].x + v[i].y + v[i].z + v[i].w;
    }
#pragma unroll
    for (int o = 16; o > 0; o >>= 1) s += __shfl_xor_sync(0xffffffffu, s, o);
    if ((tid & 31) == 0) red2[tid >> 5] = s;
    __syncthreads();
    s = 0.f;
#pragma unroll
    for (int w = 0; w < 8; w++) s += red2[w];
    const float inv = 1.0f / s;

    uint2* P = (uint2*)(g_P + row * (size_t)NN);
#pragma unroll
    for (int i = 0; i < 4; i++) {
        __half2 a, b;
        a.x = __float2half(v[i].x * inv); a.y = __float2half(v[i].y * inv);
        b.x = __float2half(v[i].z * inv); b.y = __float2half(v[i].w * inv);
        uint2 o;
        o.x = *reinterpret_cast<uint32_t*>(&a);
        o.y = *reinterpret_cast<uint32_t*>(&b);
        P[tid + i * 256] = o;
    }
}

// ---------------- BN ---------------------------------------------------------
__global__ void bn_stats(const float* __restrict__ u) {
    __shared__ float rs[8], rs2[8];
    const int c = blockIdx.x;
    const int tid = threadIdx.x;
    float s = 0.f, s2 = 0.f;
    for (int b = 0; b < BB; b++) {
        const float* up = u + ((size_t)b * CC + c) * NN;
        for (int n = tid; n < NN; n += 256) {
            float t = up[n];
            s += t; s2 += t * t;
        }
    }
#pragma unroll
    for (int o = 16; o > 0; o >>= 1) {
        s  += __shfl_xor_sync(0xffffffffu, s, o);
        s2 += __shfl_xor_sync(0xffffffffu, s2, o);
    }
    if ((tid & 31) == 0) { rs[tid >> 5] = s; rs2[tid >> 5] = s2; }
    __syncthreads();
    if (tid == 0) {
        float S = 0.f, S2 = 0.f;
#pragma unroll
        for (int w = 0; w < 8; w++) { S += rs[w]; S2 += rs2[w]; }
        const float cnt = (float)(BB * NN);
        float mean = S / cnt;
        float var = S2 / cnt - mean * mean;
        g_mean[c] = mean;
        g_rstd[c] = rsqrtf(var + 1e-5f);
    }
}

__global__ void bn_relu_kernel(const float* __restrict__ u, const float* __restrict__ x,
                               const float* __restrict__ gamma, const float* __restrict__ beta,
                               float* __restrict__ out) {
    size_t i4 = (size_t)blockIdx.x * blockDim.x + threadIdx.x;
    int c = (int)((i4 * 4 / NN) % CC);
    float m = g_mean[c];
    float r = g_rstd[c] * gamma[c];
    float bt = beta[c];
    float4 uu = ((const float4*)u)[i4];
    float4 xx = ((const float4*)x)[i4];
    float4 o;
    o.x = fmaxf((uu.x - m) * r + bt + xx.x, 0.f);
    o.y = fmaxf((uu.y - m) * r + bt + xx.y, 0.f);
    o.z = fmaxf((uu.z - m) * r + bt + xx.z, 0.f);
    o.w = fmaxf((uu.w - m) * r + bt + xx.w, 0.f);
    ((float4*)out)[i4] = o;
}

// ---------------- launch ------------------------------------------------------
extern "C" void kernel_launch(void* const* d_in, const int* in_sizes, int n_in,
                              void* d_out, int out_size)
{
    const float* x     = (const float*)d_in[0];
    const float* Wv    = (const float*)d_in[1];
    const float* Wq    = (const float*)d_in[2];
    const float* Wk    = (const float*)d_in[3];
    const float* Wu    = (const float*)d_in[4];
    const float* gamma = (const float*)d_in[5];
    const float* beta  = (const float*)d_in[6];
    float* out = (float*)d_out;

    __half *xs_h, *xs_l, *wv, *wqk_h, *wqk_l, *wu;
    __half *qk_h, *qk_l, *vT_h, *vT_l, *P, *y_h, *y_l;
    float *rel, *u;
    cudaGetSymbolAddress((void**)&xs_h,  g_xs_h);  cudaGetSymbolAddress((void**)&xs_l,  g_xs_l);
    cudaGetSymbolAddress((void**)&wv,    g_wv);
    cudaGetSymbolAddress((void**)&wqk_h, g_wqk_h); cudaGetSymbolAddress((void**)&wqk_l, g_wqk_l);
    cudaGetSymbolAddress((void**)&wu,    g_wu);
    cudaGetSymbolAddress((void**)&qk_h,  g_qk_h);  cudaGetSymbolAddress((void**)&qk_l,  g_qk_l);
    cudaGetSymbolAddress((void**)&vT_h,  g_vT_h);  cudaGetSymbolAddress((void**)&vT_l,  g_vT_l);
    cudaGetSymbolAddress((void**)&P,     g_P);
    cudaGetSymbolAddress((void**)&y_h,   g_y_h);   cudaGetSymbolAddress((void**)&y_l,   g_y_l);
    cudaGetSymbolAddress((void**)&rel,   g_rel);
    cudaGetSymbolAddress((void**)&u,     g_u);

    const int SMEM_C = 3 * (A_ARR + 2 * 128 * ROWB);           // 92160
    const int SMEM_W = 3 * (2 * A_ARR + 2 * 256 * ROWB);       // 184320
    cudaFuncSetAttribute(gemm_mma<128, true>,  cudaFuncAttributeMaxDynamicSharedMemorySize, SMEM_C);
    cudaFuncSetAttribute(gemm_mma<256, false>, cudaFuncAttributeMaxDynamicSharedMemorySize, SMEM_W);

    // ---- prep, ordered so the ncu capture (0-based launch #3) hits v-GEMM ----
    split_transpose<<<dim3(NN / 32, CC / 32, BB), dim3(32, 8)>>>(x);        // 0
    cvt_w<<<(CC * CC + 255) / 256, 256>>>(Wv, wv, CC * CC);                 // 1
    init_rdist<<<32, 256>>>();                                              // 2

    // 3: vT[b][o][m] = Wv[o][:] . xs[m][:]   M=CC, N=NN, K=CC  (f16-corr) <- ncu
    gemm_mma<128, true><<<dim3(NN / 128, CC / 128, BB), 256, SMEM_C>>>(
        wv, wv, xs_h, xs_l, CC, CC, CC, 0L, (long)NN * CC,
        nullptr, vT_h, vT_l, (long)CC * NN, NN, 2, 2);

    split_w<<<(II * CC + 255) / 256, 256>>>(Wq, wqk_h, wqk_l, II * CC);
    split_w<<<(II * CC + 255) / 256, 256>>>(Wk, wqk_h + II * CC, wqk_l + II * CC, II * CC);
    cvt_w<<<(CC * CC + 255) / 256, 256>>>(Wu, wu, CC * CC);

    // qk[b][n][0:128]=q, [128:256]=k   M=NN, N=256, K=CC  (3-product fp32)
    gemm_mma<256, false><<<dim3(1, NN / 128, BB), 256, SMEM_W>>>(
        xs_h, xs_l, wqk_h, wqk_l, CC, CC, CC, (long)NN * CC, 0L,
        nullptr, qk_h, qk_l, (long)NN * 256, 256, 2, 3);

    // rel[b][n][m] = (q[n].k[m]) / dist   M=NN, N=NN, K=II  (3-product fp32)
    gemm_mma<256, false><<<dim3(NN / 256, NN / 128, BB), 256, SMEM_W>>>(
        qk_h, qk_l, qk_h + II, qk_l + II, II, 256, 256,
        (long)NN * 256, (long)NN * 256,
        rel, nullptr, nullptr, (long)NN * NN, NN, 1, 3);

    // softmax rows -> P (single fp16)
    softmax_f16<<<BB * NN, 256>>>(rel);

    // y[b][n][o] = P[n][:] . vT_h[o][:]   M=NN, N=CC, K=NN  (SINGLE product)
    gemm_mma<128, true><<<dim3(CC / 128, NN / 128, BB), 256, SMEM_C>>>(
        P, P, vT_h, vT_h, NN, NN, NN, (long)NN * NN, (long)CC * NN,
        nullptr, y_h, y_l, (long)NN * CC, CC, 2, 1);

    // u[b][o][n] = Wu[o][:] . y[n][:]   M=CC, N=NN, K=CC  (f16-corr, 2 products)
    gemm_mma<128, true><<<dim3(NN / 128, CC / 128, BB), 256, SMEM_C>>>(
        wu, wu, y_h, y_l, CC, CC, CC, 0L, (long)NN * CC,
        u, nullptr, nullptr, (long)CC * NN, NN, 0, 2);

    bn_stats<<<CC, 256>>>(u);
    bn_relu_kernel<<<(int)(((size_t)BB * CC * NN / 4) / 256), 256>>>(u, x, gamma, beta, out);
}

// round 11
// speedup vs baseline: 1.6816x; 1.0030x over previous
#include <cuda_runtime.h>
#include <cuda_fp16.h>
#include <stdint.h>

#define BB 8
#define CC 512
#define NN 4096
#define II 128

// ---------------- scratch (__device__ globals; no allocation allowed) -------
__device__ __half g_xs_h[(size_t)BB * NN * CC];
__device__ __half g_xs_l[(size_t)BB * NN * CC];
__device__ __half g_wv[CC * CC];                       // single fp16
__device__ __half g_wqk_h[2 * II * CC], g_wqk_l[2 * II * CC];  // Wq rows 0..127, Wk 128..255
__device__ __half g_wu[CC * CC];                       // single fp16
__device__ __half g_qk_h[(size_t)BB * NN * 256], g_qk_l[(size_t)BB * NN * 256];
__device__ __half g_vT_h[(size_t)BB * CC * NN], g_vT_l[(size_t)BB * CC * NN];
__device__ float  g_rel[(size_t)BB * NN * NN];
__device__ __half g_P[(size_t)BB * NN * NN];           // single fp16 probabilities
__device__ __half g_y_h[(size_t)BB * NN * CC], g_y_l[(size_t)BB * NN * CC];
__device__ float  g_u[(size_t)BB * CC * NN];
__device__ float g_mean[CC], g_rstd[CC];
__device__ float g_rdist[8192];   // 1/(sqrt(d2)+1), d2 <= 2*63^2

// ---------------- PTX helpers (portable, non-'a' features only) -------------
__device__ __forceinline__ uint32_t s2u(const void* p) {
    uint32_t a;
    asm("{ .reg .u64 t; cvta.to.shared.u64 t, %1; cvt.u32.u64 %0, t; }" : "=r"(a) : "l"(p));
    return a;
}
__device__ __forceinline__ void cpa16(uint32_t s, const void* g) {
    asm volatile("cp.async.cg.shared.global [%0], [%1], 16;" :: "r"(s), "l"(g) : "memory");
}
__device__ __forceinline__ void cpa_commit() { asm volatile("cp.async.commit_group;" ::: "memory"); }
template <int W> __device__ __forceinline__ void cpa_wait() {
    asm volatile("cp.async.wait_group %0;" :: "n"(W) : "memory");
}
__device__ __forceinline__ void ldsm4(uint32_t* r, uint32_t addr) {
    asm volatile("ldmatrix.sync.aligned.m8n8.x4.shared.b16 {%0,%1,%2,%3}, [%4];"
                 : "=r"(r[0]), "=r"(r[1]), "=r"(r[2]), "=r"(r[3]) : "r"(addr));
}
__device__ __forceinline__ void mma_f16(float* d, const uint32_t* a, const uint32_t* b) {
    asm volatile(
        "mma.sync.aligned.m16n8k16.row.col.f32.f16.f16.f32 "
        "{%0,%1,%2,%3}, {%4,%5,%6,%7}, {%8,%9}, {%0,%1,%2,%3};"
        : "+f"(d[0]), "+f"(d[1]), "+f"(d[2]), "+f"(d[3])
        : "r"(a[0]), "r"(a[1]), "r"(a[2]), "r"(a[3]), "r"(b[0]), "r"(b[1]));
}
// fp16-accumulator MMA for correction products
__device__ __forceinline__ void mma_f16acc(uint32_t* d, const uint32_t* a, const uint32_t* b) {
    asm volatile(
        "mma.sync.aligned.m16n8k16.row.col.f16.f16.f16.f16 "
        "{%0,%1}, {%2,%3,%4,%5}, {%6,%7}, {%0,%1};"
        : "+r"(d[0]), "+r"(d[1])
        : "r"(a[0]), "r"(a[1]), "r"(a[2]), "r"(a[3]), "r"(b[0]), "r"(b[1]));
}
__device__ __forceinline__ void split_pk(float a, float b, uint32_t& hi, uint32_t& lo) {
    __half2 h, l;
    h.x = __float2half(a); h.y = __float2half(b);
    l.x = __float2half(a - __half2float(h.x));
    l.y = __float2half(b - __half2float(h.y));
    hi = *reinterpret_cast<uint32_t*>(&h);
    lo = *reinterpret_cast<uint32_t*>(&l);
}

// ---------------- split-fp16 HMMA GEMM ---------------------------------------
// C[M,N] = A[M,K] * B[N,K]^T ; operands fp16, K-major, leading dims lda/ldb.
// CTA tile 128 x TN, 8 warps (2m x 4n), warp tile 64 x TN/4.
// NPROD==3 (!F16C): aH*bH + aL*bH + aH*bL, all fp32-acc (A,B are hi/lo pairs)
// NPROD==2 (F16C) : aH*bH fp32-acc + aH*bL fp16-acc correction (A single)
// NPROD==1        : aH*bH only (single x single)
// MINB: min blocks/SM for launch_bounds (occupancy control).
// 3-stage cp.async pipeline, wait_group<1>.
// modes: 0 = fp32 out, 1 = fp32 * (1/dist) out, 2 = fp16 (hi,lo) pair out.
#define ROWB 80                      // padded row stride (32 fp16 = 64B -> 80B)
#define A_ARR (128 * ROWB)           // 10240

template <int TN, bool F16C, int MINB, int NPROD>
__global__ void __launch_bounds__(256, MINB)
gemm_mma(const __half* __restrict__ Ah_, const __half* __restrict__ Al_,
         const __half* __restrict__ Bh_, const __half* __restrict__ Bl_,
         int K, int lda, int ldb, long a_batch, long b_batch,
         float* __restrict__ Cf,
         __half* __restrict__ Chi, __half* __restrict__ Clo,
         long c_batch, int Nld, int mode)
{
    constexpr int B_ARR = TN * ROWB;
    constexpr int BH_OFF = A_ARR * ((!F16C && NPROD == 3) ? 2 : 1);
    constexpr int BL_OFF = BH_OFF + B_ARR;
    constexpr int STGB = BH_OFF + B_ARR * (NPROD >= 2 ? 2 : 1);  // bytes per stage
    constexpr int NT = TN / 32;                   // 8-col n-tiles per warp
    constexpr int NB = TN / 64;                   // B ldsm.x4 loads per warp

    extern __shared__ char smem[];
    const uint32_t sb = s2u(smem);
    const int tid = threadIdx.x;
    const int wid = tid >> 5;
    const int lane = tid & 31;
    const int bz = blockIdx.z;
    const int m0 = blockIdx.y * 128;
    const int n0 = blockIdx.x * TN;
    const int warp_m = wid >> 2;     // 0..1 -> 64 rows each
    const int warp_n = wid & 3;      // 0..3 -> TN/4 cols each

    const __half* Ah = Ah_ + (size_t)bz * a_batch + (size_t)m0 * lda;
    const __half* Al = Al_ + (size_t)bz * a_batch + (size_t)m0 * lda;
    const __half* Bh = Bh_ + (size_t)bz * b_batch + (size_t)n0 * ldb;
    const __half* Bl = Bl_ + (size_t)bz * b_batch + (size_t)n0 * ldb;

    const int nch = K >> 5;

    auto load_chunk = [&](int ci, int stg) {
        const uint32_t st = sb + stg * STGB;
        const size_t k0 = (size_t)ci * 32;
#pragma unroll
        for (int p = 0; p < 2; p++) {            // A: 128 rows x 4 sectors
            int f = tid + p * 256;
            int r = f >> 2, s = f & 3;
            uint32_t so = (uint32_t)r * ROWB + s * 16;
            size_t go = (size_t)r * lda + k0 + s * 8;
            cpa16(st + so, Ah + go);
            if (!F16C && NPROD == 3) cpa16(st + A_ARR + so, Al + go);
        }
#pragma unroll
        for (int p = 0; p < TN / 64; p++) {      // B: TN rows x 4 sectors
            int f = tid + p * 256;
            int r = f >> 2, s = f & 3;
            uint32_t so = (uint32_t)r * ROWB + s * 16;
            size_t go = (size_t)r * ldb + k0 + s * 8;
            cpa16(st + BH_OFF + so, Bh + go);
            if (NPROD >= 2) cpa16(st + BL_OFF + so, Bl + go);
        }
        cpa_commit();
    };

    load_chunk(0, 0);
    load_chunk(1, 1);      // nch >= 4 for all our shapes

    // lane offsets for ldmatrix (bytes)
    const int lt = lane & 7, ltile = lane >> 3;
    const uint32_t aLane = (uint32_t)(lt + ((ltile & 1) << 3)) * ROWB + ((ltile >> 1) << 4);
    const uint32_t bLane = (uint32_t)(lt + ((ltile >> 1) << 3)) * ROWB + ((ltile & 1) << 4);

    float acc[4][NT][4];
#pragma unroll
    for (int i = 0; i < 4; i++)
#pragma unroll
        for (int j = 0; j < NT; j++)
#pragma unroll
            for (int c = 0; c < 4; c++) acc[i][j][c] = 0.f;

    uint32_t acc16[4][NT][2];
    if (F16C && NPROD >= 2) {
#pragma unroll
        for (int i = 0; i < 4; i++)
#pragma unroll
            for (int j = 0; j < NT; j++) { acc16[i][j][0] = 0u; acc16[i][j][1] = 0u; }
    }

    for (int i = 0; i < nch; i++) {
        const uint32_t st = sb + (i % 3) * STGB;
        if (i + 1 < nch) cpa_wait<1>(); else cpa_wait<0>();
        __syncthreads();
        if (i + 2 < nch) load_chunk(i + 2, (i + 2) % 3);

        const uint32_t aBh = st +          (uint32_t)warp_m * 64 * ROWB + aLane;
        const uint32_t aBl = st + A_ARR +  (uint32_t)warp_m * 64 * ROWB + aLane;
        const uint32_t bBh = st + BH_OFF + (uint32_t)(warp_n * (TN / 4)) * ROWB + bLane;
        const uint32_t bBl = st + BL_OFF + (uint32_t)(warp_n * (TN / 4)) * ROWB + bLane;

#pragma unroll
        for (int ks = 0; ks < 2; ks++) {
            const uint32_t ko = ks * 32;
            uint32_t aH[4][4], bH[NB][4];
#pragma unroll
            for (int mt = 0; mt < 4; mt++) ldsm4(aH[mt], aBh + mt * 16 * ROWB + ko);
#pragma unroll
            for (int np = 0; np < NB; np++) ldsm4(bH[np], bBh + np * 16 * ROWB + ko);
#pragma unroll
            for (int mt = 0; mt < 4; mt++)
#pragma unroll
                for (int nt = 0; nt < NT; nt++)
                    mma_f16(acc[mt][nt], aH[mt], &bH[nt >> 1][(nt & 1) * 2]);
            if (!F16C && NPROD == 3) {
                uint32_t aL[4][4];
#pragma unroll
                for (int mt = 0; mt < 4; mt++) ldsm4(aL[mt], aBl + mt * 16 * ROWB + ko);
#pragma unroll
                for (int mt = 0; mt < 4; mt++)
#pragma unroll
                    for (int nt = 0; nt < NT; nt++)
                        mma_f16(acc[mt][nt], aL[mt], &bH[nt >> 1][(nt & 1) * 2]);
            }
            if (NPROD >= 2) {
                uint32_t bL[NB][4];
#pragma unroll
                for (int np = 0; np < NB; np++) ldsm4(bL[np], bBl + np * 16 * ROWB + ko);
                if (F16C) {
#pragma unroll
                    for (int mt = 0; mt < 4; mt++)
#pragma unroll
                        for (int nt = 0; nt < NT; nt++)
                            mma_f16acc(acc16[mt][nt], aH[mt], &bL[nt >> 1][(nt & 1) * 2]);
                } else {
#pragma unroll
                    for (int mt = 0; mt < 4; mt++)
#pragma unroll
                        for (int nt = 0; nt < NT; nt++)
                            mma_f16(acc[mt][nt], aH[mt], &bL[nt >> 1][(nt & 1) * 2]);
                }
            }
        }
    }

    // ---- epilogue ----
    const int gp = lane >> 2, tq = lane & 3;
    const int mbase = m0 + warp_m * 64;
    const int nbase = n0 + warp_n * (TN / 4);

#pragma unroll
    for (int mt = 0; mt < 4; mt++) {
#pragma unroll
        for (int half = 0; half < 2; half++) {
            const int r = mbase + mt * 16 + half * 8 + gp;
            if (mode == 2) {
                __half* oh = Chi + (size_t)bz * c_batch + (size_t)r * Nld;
                __half* ol = Clo + (size_t)bz * c_batch + (size_t)r * Nld;
#pragma unroll
                for (int nt = 0; nt < NT; nt++) {
                    const int col = nbase + nt * 8 + 2 * tq;
                    float v0 = acc[mt][nt][half * 2];
                    float v1 = acc[mt][nt][half * 2 + 1];
                    if (F16C && NPROD >= 2) {
                        __half2 c = *reinterpret_cast<__half2*>(&acc16[mt][nt][half]);
                        v0 += __half2float(c.x);
                        v1 += __half2float(c.y);
                    }
                    uint32_t hi, lo;
                    split_pk(v0, v1, hi, lo);
                    *(uint32_t*)(oh + col) = hi;
                    *(uint32_t*)(ol + col) = lo;
                }
            } else {
                float* oc = Cf + (size_t)bz * c_batch + (size_t)r * Nld;
                if (mode == 1) {
                    const int ri = r >> 6, rj = r & 63;
#pragma unroll
                    for (int nt = 0; nt < NT; nt++) {
                        const int col = nbase + nt * 8 + 2 * tq;
                        int di0 = ri - (col >> 6);
                        int j0 = rj - (col & 63);
                        int j1 = rj - ((col + 1) & 63);
                        float2 o;
                        o.x = acc[mt][nt][half * 2]     * g_rdist[di0 * di0 + j0 * j0];
                        o.y = acc[mt][nt][half * 2 + 1] * g_rdist[di0 * di0 + j1 * j1];
                        *(float2*)(oc + col) = o;
                    }
                } else {
#pragma unroll
                    for (int nt = 0; nt < NT; nt++) {
                        const int col = nbase + nt * 8 + 2 * tq;
                        float v0 = acc[mt][nt][half * 2];
                        float v1 = acc[mt][nt][half * 2 + 1];
                        if (F16C && NPROD >= 2) {
                            __half2 c = *reinterpret_cast<__half2*>(&acc16[mt][nt][half]);
                            v0 += __half2float(c.x);
                            v1 += __half2float(c.y);
                        }
                        float2 o; o.x = v0; o.y = v1;
                        *(float2*)(oc + col) = o;
                    }
                }
            }
        }
    }
}

// ---------------- prep kernels ----------------------------------------------
__global__ void init_rdist() {
    int i = blockIdx.x * 256 + threadIdx.x;
    if (i < 8192) g_rdist[i] = 1.0f / (sqrtf((float)i) + 1.0f);
}

// fp32 -> single fp16
__global__ void cvt_w(const float* __restrict__ w, __half* __restrict__ h, int n) {
    int i = blockIdx.x * 256 + threadIdx.x;
    if (i < n) h[i] = __float2half(w[i]);
}

// fp32 -> fp16 pair
__global__ void split_w(const float* __restrict__ w, __half* __restrict__ h,
                        __half* __restrict__ l, int n) {
    int i = blockIdx.x * 256 + threadIdx.x;
    if (i < n) {
        float v = w[i];
        __half hh = __float2half(v);
        h[i] = hh;
        l[i] = __float2half(v - __half2float(hh));
    }
}

// x[b][c][n] -> xs[b][n][c] as fp16 hi/lo
__global__ void split_transpose(const float* __restrict__ x) {
    __shared__ float t[32][33];
    const int b = blockIdx.z;
    const int n0 = blockIdx.x << 5, c0 = blockIdx.y << 5;
    const int tx = threadIdx.x, ty = threadIdx.y;
    const float* xp = x + ((size_t)b * CC + c0) * NN + n0;
#pragma unroll
    for (int i = 0; i < 4; i++) t[ty + i * 8][tx] = xp[(size_t)(ty + i * 8) * NN + tx];
    __syncthreads();
    const size_t ob = ((size_t)b * NN + n0) * CC + c0;
#pragma unroll
    for (int i = 0; i < 4; i++) {
        float v = t[tx][ty + i * 8];
        __half h = __float2half(v);
        size_t o = ob + (size_t)(ty + i * 8) * CC + tx;
        g_xs_h[o] = h;
        g_xs_l[o] = __float2half(v - __half2float(h));
    }
}

// row softmax, fp32 in -> single fp16 out
__global__ void softmax_f16(const float* __restrict__ rel) {
    __shared__ float red1[8], red2[8];
    const size_t row = blockIdx.x;
    const float4* p = (const float4*)(rel + row * (size_t)NN);
    const int tid = threadIdx.x;

    float4 v[4];
    float mx = -3.0e38f;
#pragma unroll
    for (int i = 0; i < 4; i++) {
        v[i] = p[tid + i * 256];
        mx = fmaxf(mx, fmaxf(fmaxf(v[i].x, v[i].y), fmaxf(v[i].z, v[i].w)));
    }
#pragma unroll
    for (int o = 16; o > 0; o >>= 1) mx = fmaxf(mx, __shfl_xor_sync(0xffffffffu, mx, o));
    if ((tid & 31) == 0) red1[tid >> 5] = mx;
    __syncthreads();
    mx = red1[0];
#pragma unroll
    for (int w = 1; w < 8; w++) mx = fmaxf(mx, red1[w]);

    float s = 0.f;
#pragma unroll
    for (int i = 0; i < 4; i++) {
        v[i].x = __expf(v[i].x - mx); v[i].y = __expf(v[i].y - mx);
        v[i].z = __expf(v[i].z - mx); v[i].w = __expf(v[i].w - mx);
        s += v[i].x + v[i].y + v[i].z + v[i].w;
    }
#pragma unroll
    for (int o = 16; o > 0; o >>= 1) s += __shfl_xor_sync(0xffffffffu, s, o);
    if ((tid & 31) == 0) red2[tid >> 5] = s;
    __syncthreads();
    s = 0.f;
#pragma unroll
    for (int w = 0; w < 8; w++) s += red2[w];
    const float inv = 1.0f / s;

    uint2* P = (uint2*)(g_P + row * (size_t)NN);
#pragma unroll
    for (int i = 0; i < 4; i++) {
        __half2 a, b;
        a.x = __float2half(v[i].x * inv); a.y = __float2half(v[i].y * inv);
        b.x = __float2half(v[i].z * inv); b.y = __float2half(v[i].w * inv);
        uint2 o;
        o.x = *reinterpret_cast<uint32_t*>(&a);
        o.y = *reinterpret_cast<uint32_t*>(&b);
        P[tid + i * 256] = o;
    }
}

// ---------------- BN ---------------------------------------------------------
__global__ void bn_stats(const float* __restrict__ u) {
    __shared__ float rs[8], rs2[8];
    const int c = blockIdx.x;
    const int tid = threadIdx.x;
    float s = 0.f, s2 = 0.f;
    for (int b = 0; b < BB; b++) {
        const float* up = u + ((size_t)b * CC + c) * NN;
        for (int n = tid; n < NN; n += 256) {
            float t = up[n];
            s += t; s2 += t * t;
        }
    }
#pragma unroll
    for (int o = 16; o > 0; o >>= 1) {
        s  += __shfl_xor_sync(0xffffffffu, s, o);
        s2 += __shfl_xor_sync(0xffffffffu, s2, o);
    }
    if ((tid & 31) == 0) { rs[tid >> 5] = s; rs2[tid >> 5] = s2; }
    __syncthreads();
    if (tid == 0) {
        float S = 0.f, S2 = 0.f;
#pragma unroll
        for (int w = 0; w < 8; w++) { S += rs[w]; S2 += rs2[w]; }
        const float cnt = (float)(BB * NN);
        float mean = S / cnt;
        float var = S2 / cnt - mean * mean;
        g_mean[c] = mean;
        g_rstd[c] = rsqrtf(var + 1e-5f);
    }
}

__global__ void bn_relu_kernel(const float* __restrict__ u, const float* __restrict__ x,
                               const float* __restrict__ gamma, const float* __restrict__ beta,
                               float* __restrict__ out) {
    size_t i4 = (size_t)blockIdx.x * blockDim.x + threadIdx.x;
    int c = (int)((i4 * 4 / NN) % CC);
    float m = g_mean[c];
    float r = g_rstd[c] * gamma[c];
    float bt = beta[c];
    float4 uu = ((const float4*)u)[i4];
    float4 xx = ((const float4*)x)[i4];
    float4 o;
    o.x = fmaxf((uu.x - m) * r + bt + xx.x, 0.f);
    o.y = fmaxf((uu.y - m) * r + bt + xx.y, 0.f);
    o.z = fmaxf((uu.z - m) * r + bt + xx.z, 0.f);
    o.w = fmaxf((uu.w - m) * r + bt + xx.w, 0.f);
    ((float4*)out)[i4] = o;
}

// ---------------- launch ------------------------------------------------------
extern "C" void kernel_launch(void* const* d_in, const int* in_sizes, int n_in,
                              void* d_out, int out_size)
{
    const float* x     = (const float*)d_in[0];
    const float* Wv    = (const float*)d_in[1];
    const float* Wq    = (const float*)d_in[2];
    const float* Wk    = (const float*)d_in[3];
    const float* Wu    = (const float*)d_in[4];
    const float* gamma = (const float*)d_in[5];
    const float* beta  = (const float*)d_in[6];
    float* out = (float*)d_out;

    __half *xs_h, *xs_l, *wv, *wqk_h, *wqk_l, *wu;
    __half *qk_h, *qk_l, *vT_h, *vT_l, *P, *y_h, *y_l;
    float *rel, *u;
    cudaGetSymbolAddress((void**)&xs_h,  g_xs_h);  cudaGetSymbolAddress((void**)&xs_l,  g_xs_l);
    cudaGetSymbolAddress((void**)&wv,    g_wv);
    cudaGetSymbolAddress((void**)&wqk_h, g_wqk_h); cudaGetSymbolAddress((void**)&wqk_l, g_wqk_l);
    cudaGetSymbolAddress((void**)&wu,    g_wu);
    cudaGetSymbolAddress((void**)&qk_h,  g_qk_h);  cudaGetSymbolAddress((void**)&qk_l,  g_qk_l);
    cudaGetSymbolAddress((void**)&vT_h,  g_vT_h);  cudaGetSymbolAddress((void**)&vT_l,  g_vT_l);
    cudaGetSymbolAddress((void**)&P,     g_P);
    cudaGetSymbolAddress((void**)&y_h,   g_y_h);   cudaGetSymbolAddress((void**)&y_l,   g_y_l);
    cudaGetSymbolAddress((void**)&rel,   g_rel);
    cudaGetSymbolAddress((void**)&u,     g_u);

    // smem per CTA per instantiation
    const int SMEM_VU = 3 * (A_ARR + 2 * 128 * ROWB);          // 92160  (<128,true,1,2>)
    const int SMEM_PV = 3 * (A_ARR + 128 * ROWB);              // 61440  (<128,true,2,1>)
    const int SMEM_QK = 3 * (2 * A_ARR + 2 * 256 * ROWB);      // 184320 (<256,false,1,3>)
    const int SMEM_QK1 = 3 * (2 * A_ARR + 2 * 128 * ROWB);     // 122880 (<128,false,1,3>)
    cudaFuncSetAttribute(gemm_mma<128, true, 1, 2>,  cudaFuncAttributeMaxDynamicSharedMemorySize, SMEM_VU);
    cudaFuncSetAttribute(gemm_mma<128, true, 2, 1>,  cudaFuncAttributeMaxDynamicSharedMemorySize, SMEM_PV);
    cudaFuncSetAttribute(gemm_mma<256, false, 1, 3>, cudaFuncAttributeMaxDynamicSharedMemorySize, SMEM_QK);
    cudaFuncSetAttribute(gemm_mma<128, false, 1, 3>, cudaFuncAttributeMaxDynamicSharedMemorySize, SMEM_QK1);

    // ---- prep, ordered so the ncu capture (0-based launch #3) hits v-GEMM ----
    split_transpose<<<dim3(NN / 32, CC / 32, BB), dim3(32, 8)>>>(x);        // 0
    cvt_w<<<(CC * CC + 255) / 256, 256>>>(Wv, wv, CC * CC);                 // 1
    init_rdist<<<32, 256>>>();                                              // 2

    // 3: vT[b][o][m] = Wv[o][:] . xs[m][:]   M=CC, N=NN, K=CC  (f16-corr) <- ncu
    gemm_mma<128, true, 1, 2><<<dim3(NN / 128, CC / 128, BB), 256, SMEM_VU>>>(
        wv, wv, xs_h, xs_l, CC, CC, CC, 0L, (long)NN * CC,
        nullptr, vT_h, vT_l, (long)CC * NN, NN, 2);

    split_w<<<(II * CC + 255) / 256, 256>>>(Wq, wqk_h, wqk_l, II * CC);
    split_w<<<(II * CC + 255) / 256, 256>>>(Wk, wqk_h + II * CC, wqk_l + II * CC, II * CC);
    cvt_w<<<(CC * CC + 255) / 256, 256>>>(Wu, wu, CC * CC);

    // qk[b][n][0:128]=q, [128:256]=k   M=NN, N=256, K=CC  (3-product fp32)
    gemm_mma<128, false, 1, 3><<<dim3(2, NN / 128, BB), 256, SMEM_QK1>>>(
        xs_h, xs_l, wqk_h, wqk_l, CC, CC, CC, (long)NN * CC, 0L,
        nullptr, qk_h, qk_l, (long)NN * 256, 256, 2);

    // rel[b][n][m] = (q[n].k[m]) / dist   M=NN, N=NN, K=II  (3-product fp32)
    gemm_mma<256, false, 1, 3><<<dim3(NN / 256, NN / 128, BB), 256, SMEM_QK>>>(
        qk_h, qk_l, qk_h + II, qk_l + II, II, 256, 256,
        (long)NN * 256, (long)NN * 256,
        rel, nullptr, nullptr, (long)NN * NN, NN, 1);

    // softmax rows -> P (single fp16)
    softmax_f16<<<BB * NN, 256>>>(rel);

    // y[b][n][o] = P[n][:] . vT_h[o][:]   M=NN, N=CC, K=NN  (single product, 2 CTAs/SM)
    gemm_mma<128, true, 2, 1><<<dim3(CC / 128, NN / 128, BB), 256, SMEM_PV>>>(
        P, P, vT_h, vT_h, NN, NN, NN, (long)NN * NN, (long)CC * NN,
        nullptr, y_h, y_l, (long)NN * CC, CC, 2);

    // u[b][o][n] = Wu[o][:] . y[n][:]   M=CC, N=NN, K=CC  (f16-corr, 2 products)
    gemm_mma<128, true, 1, 2><<<dim3(NN / 128, CC / 128, BB), 256, SMEM_VU>>>(
        wu, wu, y_h, y_l, CC, CC, CC, 0L, (long)NN * CC,
        u, nullptr, nullptr, (long)CC * NN, NN, 0);

    bn_stats<<<CC, 256>>>(u);
    bn_relu_kernel<<<(int)(((size_t)BB * CC * NN / 4) / 256), 256>>>(u, x, gamma, beta, out);
}

// round 12
// speedup vs baseline: 1.8024x; 1.0719x over previous
#include <cuda_runtime.h>
#include <cuda_fp16.h>
#include <stdint.h>

#define BB 8
#define CC 512
#define NN 4096
#define II 128

// ---------------- scratch (__device__ globals; no allocation allowed) -------
__device__ __half g_xs_h[(size_t)BB * NN * CC];
__device__ __half g_xs_l[(size_t)BB * NN * CC];
__device__ __half g_wv[CC * CC];                       // single fp16
__device__ __half g_wqk_h[2 * II * CC], g_wqk_l[2 * II * CC];  // Wq rows 0..127, Wk 128..255
__device__ __half g_wu[CC * CC];                       // single fp16
__device__ __half g_qk_h[(size_t)BB * NN * 256], g_qk_l[(size_t)BB * NN * 256];
__device__ __half g_vT[(size_t)BB * CC * NN];          // single fp16
__device__ float  g_rel[(size_t)BB * NN * NN];
__device__ __half g_P[(size_t)BB * NN * NN];           // single fp16 probabilities
__device__ __half g_y[(size_t)BB * NN * CC];           // single fp16
__device__ float  g_u[(size_t)BB * CC * NN];
__device__ float g_mean[CC], g_rstd[CC];
__device__ float g_rdist[8192];   // 1/(sqrt(d2)+1), d2 <= 2*63^2

// ---------------- PTX helpers (portable, non-'a' features only) -------------
__device__ __forceinline__ uint32_t s2u(const void* p) {
    uint32_t a;
    asm("{ .reg .u64 t; cvta.to.shared.u64 t, %1; cvt.u32.u64 %0, t; }" : "=r"(a) : "l"(p));
    return a;
}
__device__ __forceinline__ void cpa16(uint32_t s, const void* g) {
    asm volatile("cp.async.cg.shared.global [%0], [%1], 16;" :: "r"(s), "l"(g) : "memory");
}
__device__ __forceinline__ void cpa_commit() { asm volatile("cp.async.commit_group;" ::: "memory"); }
template <int W> __device__ __forceinline__ void cpa_wait() {
    asm volatile("cp.async.wait_group %0;" :: "n"(W) : "memory");
}
__device__ __forceinline__ void ldsm4(uint32_t* r, uint32_t addr) {
    asm volatile("ldmatrix.sync.aligned.m8n8.x4.shared.b16 {%0,%1,%2,%3}, [%4];"
                 : "=r"(r[0]), "=r"(r[1]), "=r"(r[2]), "=r"(r[3]) : "r"(addr));
}
__device__ __forceinline__ void mma_f16(float* d, const uint32_t* a, const uint32_t* b) {
    asm volatile(
        "mma.sync.aligned.m16n8k16.row.col.f32.f16.f16.f32 "
        "{%0,%1,%2,%3}, {%4,%5,%6,%7}, {%8,%9}, {%0,%1,%2,%3};"
        : "+f"(d[0]), "+f"(d[1]), "+f"(d[2]), "+f"(d[3])
        : "r"(a[0]), "r"(a[1]), "r"(a[2]), "r"(a[3]), "r"(b[0]), "r"(b[1]));
}
// fp16-accumulator MMA for correction products
__device__ __forceinline__ void mma_f16acc(uint32_t* d, const uint32_t* a, const uint32_t* b) {
    asm volatile(
        "mma.sync.aligned.m16n8k16.row.col.f16.f16.f16.f16 "
        "{%0,%1}, {%2,%3,%4,%5}, {%6,%7}, {%0,%1};"
        : "+r"(d[0]), "+r"(d[1])
        : "r"(a[0]), "r"(a[1]), "r"(a[2]), "r"(a[3]), "r"(b[0]), "r"(b[1]));
}
__device__ __forceinline__ void split_pk(float a, float b, uint32_t& hi, uint32_t& lo) {
    __half2 h, l;
    h.x = __float2half(a); h.y = __float2half(b);
    l.x = __float2half(a - __half2float(h.x));
    l.y = __float2half(b - __half2float(h.y));
    hi = *reinterpret_cast<uint32_t*>(&h);
    lo = *reinterpret_cast<uint32_t*>(&l);
}

// ---------------- split-fp16 HMMA GEMM ---------------------------------------
// C[M,N] = A[M,K] * B[N,K]^T ; operands fp16, K-major, leading dims lda/ldb.
// CTA tile 128 x TN, 8 warps (2m x 4n), warp tile 64 x TN/4.
// NPROD==3 (!F16C): aH*bH + aL*bH + aH*bL, all fp32-acc (A,B are hi/lo pairs)
// NPROD==2 (F16C) : aH*bH fp32-acc + aH*bL fp16-acc correction (A single)
// NPROD==1        : aH*bH only (single x single)
// MINB: min blocks/SM for launch_bounds (occupancy control).
// 3-stage cp.async pipeline, wait_group<1>.
// modes: 0 = fp32, 1 = fp32 * (1/dist), 2 = fp16 (hi,lo) pair, 3 = fp16 single.
#define ROWB 80                      // padded row stride (32 fp16 = 64B -> 80B)
#define A_ARR (128 * ROWB)           // 10240

template <int TN, bool F16C, int MINB, int NPROD>
__global__ void __launch_bounds__(256, MINB)
gemm_mma(const __half* __restrict__ Ah_, const __half* __restrict__ Al_,
         const __half* __restrict__ Bh_, const __half* __restrict__ Bl_,
         int K, int lda, int ldb, long a_batch, long b_batch,
         float* __restrict__ Cf,
         __half* __restrict__ Chi, __half* __restrict__ Clo,
         long c_batch, int Nld, int mode)
{
    constexpr int B_ARR = TN * ROWB;
    constexpr int BH_OFF = A_ARR * ((!F16C && NPROD == 3) ? 2 : 1);
    constexpr int BL_OFF = BH_OFF + B_ARR;
    constexpr int STGB = BH_OFF + B_ARR * (NPROD >= 2 ? 2 : 1);  // bytes per stage
    constexpr int NT = TN / 32;                   // 8-col n-tiles per warp
    constexpr int NB = TN / 64;                   // B ldsm.x4 loads per warp

    extern __shared__ char smem[];
    const uint32_t sb = s2u(smem);
    const int tid = threadIdx.x;
    const int wid = tid >> 5;
    const int lane = tid & 31;
    const int bz = blockIdx.z;
    const int m0 = blockIdx.y * 128;
    const int n0 = blockIdx.x * TN;
    const int warp_m = wid >> 2;     // 0..1 -> 64 rows each
    const int warp_n = wid & 3;      // 0..3 -> TN/4 cols each

    const __half* Ah = Ah_ + (size_t)bz * a_batch + (size_t)m0 * lda;
    const __half* Al = Al_ + (size_t)bz * a_batch + (size_t)m0 * lda;
    const __half* Bh = Bh_ + (size_t)bz * b_batch + (size_t)n0 * ldb;
    const __half* Bl = Bl_ + (size_t)bz * b_batch + (size_t)n0 * ldb;

    const int nch = K >> 5;

    auto load_chunk = [&](int ci, int stg) {
        const uint32_t st = sb + stg * STGB;
        const size_t k0 = (size_t)ci * 32;
#pragma unroll
        for (int p = 0; p < 2; p++) {            // A: 128 rows x 4 sectors
            int f = tid + p * 256;
            int r = f >> 2, s = f & 3;
            uint32_t so = (uint32_t)r * ROWB + s * 16;
            size_t go = (size_t)r * lda + k0 + s * 8;
            cpa16(st + so, Ah + go);
            if (!F16C && NPROD == 3) cpa16(st + A_ARR + so, Al + go);
        }
#pragma unroll
        for (int p = 0; p < TN / 64; p++) {      // B: TN rows x 4 sectors
            int f = tid + p * 256;
            int r = f >> 2, s = f & 3;
            uint32_t so = (uint32_t)r * ROWB + s * 16;
            size_t go = (size_t)r * ldb + k0 + s * 8;
            cpa16(st + BH_OFF + so, Bh + go);
            if (NPROD >= 2) cpa16(st + BL_OFF + so, Bl + go);
        }
        cpa_commit();
    };

    load_chunk(0, 0);
    load_chunk(1, 1);      // nch >= 4 for all our shapes

    // lane offsets for ldmatrix (bytes)
    const int lt = lane & 7, ltile = lane >> 3;
    const uint32_t aLane = (uint32_t)(lt + ((ltile & 1) << 3)) * ROWB + ((ltile >> 1) << 4);
    const uint32_t bLane = (uint32_t)(lt + ((ltile >> 1) << 3)) * ROWB + ((ltile & 1) << 4);

    float acc[4][NT][4];
#pragma unroll
    for (int i = 0; i < 4; i++)
#pragma unroll
        for (int j = 0; j < NT; j++)
#pragma unroll
            for (int c = 0; c < 4; c++) acc[i][j][c] = 0.f;

    uint32_t acc16[4][NT][2];
    if (F16C && NPROD >= 2) {
#pragma unroll
        for (int i = 0; i < 4; i++)
#pragma unroll
            for (int j = 0; j < NT; j++) { acc16[i][j][0] = 0u; acc16[i][j][1] = 0u; }
    }

    for (int i = 0; i < nch; i++) {
        const uint32_t st = sb + (i % 3) * STGB;
        if (i + 1 < nch) cpa_wait<1>(); else cpa_wait<0>();
        __syncthreads();
        if (i + 2 < nch) load_chunk(i + 2, (i + 2) % 3);

        const uint32_t aBh = st +          (uint32_t)warp_m * 64 * ROWB + aLane;
        const uint32_t aBl = st + A_ARR +  (uint32_t)warp_m * 64 * ROWB + aLane;
        const uint32_t bBh = st + BH_OFF + (uint32_t)(warp_n * (TN / 4)) * ROWB + bLane;
        const uint32_t bBl = st + BL_OFF + (uint32_t)(warp_n * (TN / 4)) * ROWB + bLane;

#pragma unroll
        for (int ks = 0; ks < 2; ks++) {
            const uint32_t ko = ks * 32;
            uint32_t aH[4][4], bH[NB][4];
#pragma unroll
            for (int mt = 0; mt < 4; mt++) ldsm4(aH[mt], aBh + mt * 16 * ROWB + ko);
#pragma unroll
            for (int np = 0; np < NB; np++) ldsm4(bH[np], bBh + np * 16 * ROWB + ko);
#pragma unroll
            for (int mt = 0; mt < 4; mt++)
#pragma unroll
                for (int nt = 0; nt < NT; nt++)
                    mma_f16(acc[mt][nt], aH[mt], &bH[nt >> 1][(nt & 1) * 2]);
            if (!F16C && NPROD == 3) {
                uint32_t aL[4][4];
#pragma unroll
                for (int mt = 0; mt < 4; mt++) ldsm4(aL[mt], aBl + mt * 16 * ROWB + ko);
#pragma unroll
                for (int mt = 0; mt < 4; mt++)
#pragma unroll
                    for (int nt = 0; nt < NT; nt++)
                        mma_f16(acc[mt][nt], aL[mt], &bH[nt >> 1][(nt & 1) * 2]);
            }
            if (NPROD >= 2) {
                uint32_t bL[NB][4];
#pragma unroll
                for (int np = 0; np < NB; np++) ldsm4(bL[np], bBl + np * 16 * ROWB + ko);
                if (F16C) {
#pragma unroll
                    for (int mt = 0; mt < 4; mt++)
#pragma unroll
                        for (int nt = 0; nt < NT; nt++)
                            mma_f16acc(acc16[mt][nt], aH[mt], &bL[nt >> 1][(nt & 1) * 2]);
                } else {
#pragma unroll
                    for (int mt = 0; mt < 4; mt++)
#pragma unroll
                        for (int nt = 0; nt < NT; nt++)
                            mma_f16(acc[mt][nt], aH[mt], &bL[nt >> 1][(nt & 1) * 2]);
                }
            }
        }
    }

    // ---- epilogue ----
    const int gp = lane >> 2, tq = lane & 3;
    const int mbase = m0 + warp_m * 64;
    const int nbase = n0 + warp_n * (TN / 4);

#pragma unroll
    for (int mt = 0; mt < 4; mt++) {
#pragma unroll
        for (int half = 0; half < 2; half++) {
            const int r = mbase + mt * 16 + half * 8 + gp;
            if (mode >= 2) {
                __half* oh = Chi + (size_t)bz * c_batch + (size_t)r * Nld;
                __half* ol = Clo + (size_t)bz * c_batch + (size_t)r * Nld;
#pragma unroll
                for (int nt = 0; nt < NT; nt++) {
                    const int col = nbase + nt * 8 + 2 * tq;
                    float v0 = acc[mt][nt][half * 2];
                    float v1 = acc[mt][nt][half * 2 + 1];
                    if (F16C && NPROD >= 2) {
                        __half2 c = *reinterpret_cast<__half2*>(&acc16[mt][nt][half]);
                        v0 += __half2float(c.x);
                        v1 += __half2float(c.y);
                    }
                    uint32_t hi, lo;
                    split_pk(v0, v1, hi, lo);
                    *(uint32_t*)(oh + col) = hi;
                    if (mode == 2) *(uint32_t*)(ol + col) = lo;
                }
            } else {
                float* oc = Cf + (size_t)bz * c_batch + (size_t)r * Nld;
                if (mode == 1) {
                    const int ri = r >> 6, rj = r & 63;
#pragma unroll
                    for (int nt = 0; nt < NT; nt++) {
                        const int col = nbase + nt * 8 + 2 * tq;
                        int di0 = ri - (col >> 6);
                        int j0 = rj - (col & 63);
                        int j1 = rj - ((col + 1) & 63);
                        float2 o;
                        o.x = acc[mt][nt][half * 2]     * g_rdist[di0 * di0 + j0 * j0];
                        o.y = acc[mt][nt][half * 2 + 1] * g_rdist[di0 * di0 + j1 * j1];
                        *(float2*)(oc + col) = o;
                    }
                } else {
#pragma unroll
                    for (int nt = 0; nt < NT; nt++) {
                        const int col = nbase + nt * 8 + 2 * tq;
                        float v0 = acc[mt][nt][half * 2];
                        float v1 = acc[mt][nt][half * 2 + 1];
                        if (F16C && NPROD >= 2) {
                            __half2 c = *reinterpret_cast<__half2*>(&acc16[mt][nt][half]);
                            v0 += __half2float(c.x);
                            v1 += __half2float(c.y);
                        }
                        float2 o; o.x = v0; o.y = v1;
                        *(float2*)(oc + col) = o;
                    }
                }
            }
        }
    }
}

// ---------------- prep kernels ----------------------------------------------
__global__ void init_rdist() {
    int i = blockIdx.x * 256 + threadIdx.x;
    if (i < 8192) g_rdist[i] = 1.0f / (sqrtf((float)i) + 1.0f);
}

// fp32 -> single fp16
__global__ void cvt_w(const float* __restrict__ w, __half* __restrict__ h, int n) {
    int i = blockIdx.x * 256 + threadIdx.x;
    if (i < n) h[i] = __float2half(w[i]);
}

// fp32 -> fp16 pair
__global__ void split_w(const float* __restrict__ w, __half* __restrict__ h,
                        __half* __restrict__ l, int n) {
    int i = blockIdx.x * 256 + threadIdx.x;
    if (i < n) {
        float v = w[i];
        __half hh = __float2half(v);
        h[i] = hh;
        l[i] = __float2half(v - __half2float(hh));
    }
}

// x[b][c][n] -> xs[b][n][c] as fp16 hi/lo
__global__ void split_transpose(const float* __restrict__ x) {
    __shared__ float t[32][33];
    const int b = blockIdx.z;
    const int n0 = blockIdx.x << 5, c0 = blockIdx.y << 5;
    const int tx = threadIdx.x, ty = threadIdx.y;
    const float* xp = x + ((size_t)b * CC + c0) * NN + n0;
#pragma unroll
    for (int i = 0; i < 4; i++) t[ty + i * 8][tx] = xp[(size_t)(ty + i * 8) * NN + tx];
    __syncthreads();
    const size_t ob = ((size_t)b * NN + n0) * CC + c0;
#pragma unroll
    for (int i = 0; i < 4; i++) {
        float v = t[tx][ty + i * 8];
        __half h = __float2half(v);
        size_t o = ob + (size_t)(ty + i * 8) * CC + tx;
        g_xs_h[o] = h;
        g_xs_l[o] = __float2half(v - __half2float(h));
    }
}

// row softmax, fp32 in -> single fp16 out
__global__ void softmax_f16(const float* __restrict__ rel) {
    __shared__ float red1[8], red2[8];
    const size_t row = blockIdx.x;
    const float4* p = (const float4*)(rel + row * (size_t)NN);
    const int tid = threadIdx.x;

    float4 v[4];
    float mx = -3.0e38f;
#pragma unroll
    for (int i = 0; i < 4; i++) {
        v[i] = p[tid + i * 256];
        mx = fmaxf(mx, fmaxf(fmaxf(v[i].x, v[i].y), fmaxf(v[i].z, v[i].w)));
    }
#pragma unroll
    for (int o = 16; o > 0; o >>= 1) mx = fmaxf(mx, __shfl_xor_sync(0xffffffffu, mx, o));
    if ((tid & 31) == 0) red1[tid >> 5] = mx;
    __syncthreads();
    mx = red1[0];
#pragma unroll
    for (int w = 1; w < 8; w++) mx = fmaxf(mx, red1[w]);

    float s = 0.f;
#pragma unroll
    for (int i = 0; i < 4; i++) {
        v[i].x = __expf(v[i].x - mx); v[i].y = __expf(v[i].y - mx);
        v[i].z = __expf(v[i].z - mx); v[i].w = __expf(v[i].w - mx);
        s += v[i].x + v[i].y + v[i].z + v[i].w;
    }
#pragma unroll
    for (int o = 16; o > 0; o >>= 1) s += __shfl_xor_sync(0xffffffffu, s, o);
    if ((tid & 31) == 0) red2[tid >> 5] = s;
    __syncthreads();
    s = 0.f;
#pragma unroll
    for (int w = 0; w < 8; w++) s += red2[w];
    const float inv = 1.0f / s;

    uint2* P = (uint2*)(g_P + row * (size_t)NN);
#pragma unroll
    for (int i = 0; i < 4; i++) {
        __half2 a, b;
        a.x = __float2half(v[i].x * inv); a.y = __float2half(v[i].y * inv);
        b.x = __float2half(v[i].z * inv); b.y = __float2half(v[i].w * inv);
        uint2 o;
        o.x = *reinterpret_cast<uint32_t*>(&a);
        o.y = *reinterpret_cast<uint32_t*>(&b);
        P[tid + i * 256] = o;
    }
}

// ---------------- BN ---------------------------------------------------------
__global__ void bn_stats(const float* __restrict__ u) {
    __shared__ float rs[8], rs2[8];
    const int c = blockIdx.x;
    const int tid = threadIdx.x;
    float s = 0.f, s2 = 0.f;
    for (int b = 0; b < BB; b++) {
        const float* up = u + ((size_t)b * CC + c) * NN;
        for (int n = tid; n < NN; n += 256) {
            float t = up[n];
            s += t; s2 += t * t;
        }
    }
#pragma unroll
    for (int o = 16; o > 0; o >>= 1) {
        s  += __shfl_xor_sync(0xffffffffu, s, o);
        s2 += __shfl_xor_sync(0xffffffffu, s2, o);
    }
    if ((tid & 31) == 0) { rs[tid >> 5] = s; rs2[tid >> 5] = s2; }
    __syncthreads();
    if (tid == 0) {
        float S = 0.f, S2 = 0.f;
#pragma unroll
        for (int w = 0; w < 8; w++) { S += rs[w]; S2 += rs2[w]; }
        const float cnt = (float)(BB * NN);
        float mean = S / cnt;
        float var = S2 / cnt - mean * mean;
        g_mean[c] = mean;
        g_rstd[c] = rsqrtf(var + 1e-5f);
    }
}

__global__ void bn_relu_kernel(const float* __restrict__ u, const float* __restrict__ x,
                               const float* __restrict__ gamma, const float* __restrict__ beta,
                               float* __restrict__ out) {
    size_t i4 = (size_t)blockIdx.x * blockDim.x + threadIdx.x;
    int c = (int)((i4 * 4 / NN) % CC);
    float m = g_mean[c];
    float r = g_rstd[c] * gamma[c];
    float bt = beta[c];
    float4 uu = ((const float4*)u)[i4];
    float4 xx = ((const float4*)x)[i4];
    float4 o;
    o.x = fmaxf((uu.x - m) * r + bt + xx.x, 0.f);
    o.y = fmaxf((uu.y - m) * r + bt + xx.y, 0.f);
    o.z = fmaxf((uu.z - m) * r + bt + xx.z, 0.f);
    o.w = fmaxf((uu.w - m) * r + bt + xx.w, 0.f);
    ((float4*)out)[i4] = o;
}

// ---------------- launch ------------------------------------------------------
extern "C" void kernel_launch(void* const* d_in, const int* in_sizes, int n_in,
                              void* d_out, int out_size)
{
    const float* x     = (const float*)d_in[0];
    const float* Wv    = (const float*)d_in[1];
    const float* Wq    = (const float*)d_in[2];
    const float* Wk    = (const float*)d_in[3];
    const float* Wu    = (const float*)d_in[4];
    const float* gamma = (const float*)d_in[5];
    const float* beta  = (const float*)d_in[6];
    float* out = (float*)d_out;

    __half *xs_h, *xs_l, *wv, *wqk_h, *wqk_l, *wu;
    __half *qk_h, *qk_l, *vT, *P, *y;
    float *rel, *u;
    cudaGetSymbolAddress((void**)&xs_h,  g_xs_h);  cudaGetSymbolAddress((void**)&xs_l,  g_xs_l);
    cudaGetSymbolAddress((void**)&wv,    g_wv);
    cudaGetSymbolAddress((void**)&wqk_h, g_wqk_h); cudaGetSymbolAddress((void**)&wqk_l, g_wqk_l);
    cudaGetSymbolAddress((void**)&wu,    g_wu);
    cudaGetSymbolAddress((void**)&qk_h,  g_qk_h);  cudaGetSymbolAddress((void**)&qk_l,  g_qk_l);
    cudaGetSymbolAddress((void**)&vT,    g_vT);
    cudaGetSymbolAddress((void**)&P,     g_P);
    cudaGetSymbolAddress((void**)&y,     g_y);
    cudaGetSymbolAddress((void**)&rel,   g_rel);
    cudaGetSymbolAddress((void**)&u,     g_u);

    // smem per CTA per instantiation
    const int SMEM_V  = 3 * (A_ARR + 2 * 128 * ROWB);          // 92160  (<128,true,2,2>)
    const int SMEM_P1 = 3 * (A_ARR + 128 * ROWB);              // 61440  (<128,true,2,1>)
    const int SMEM_QK = 3 * (2 * A_ARR + 2 * 256 * ROWB);      // 184320 (<256,false,1,3>)
    const int SMEM_Q1 = 3 * (2 * A_ARR + 2 * 128 * ROWB);      // 122880 (<128,false,1,3>)
    cudaFuncSetAttribute(gemm_mma<128, true, 2, 2>,  cudaFuncAttributeMaxDynamicSharedMemorySize, SMEM_V);
    cudaFuncSetAttribute(gemm_mma<128, true, 2, 1>,  cudaFuncAttributeMaxDynamicSharedMemorySize, SMEM_P1);
    cudaFuncSetAttribute(gemm_mma<256, false, 1, 3>, cudaFuncAttributeMaxDynamicSharedMemorySize, SMEM_QK);
    cudaFuncSetAttribute(gemm_mma<128, false, 1, 3>, cudaFuncAttributeMaxDynamicSharedMemorySize, SMEM_Q1);

    // ---- prep, ordered so the ncu capture (0-based launch #3) hits v-GEMM ----
    split_transpose<<<dim3(NN / 32, CC / 32, BB), dim3(32, 8)>>>(x);        // 0
    cvt_w<<<(CC * CC + 255) / 256, 256>>>(Wv, wv, CC * CC);                 // 1
    init_rdist<<<32, 256>>>();                                              // 2

    // 3: vT[b][o][m] = Wv[o][:] . xs[m][:]   M=CC, N=NN, K=CC
    //    (2-product internal accuracy, single fp16 out)            <- ncu target
    gemm_mma<128, true, 2, 2><<<dim3(NN / 128, CC / 128, BB), 256, SMEM_V>>>(
        wv, wv, xs_h, xs_l, CC, CC, CC, 0L, (long)NN * CC,
        nullptr, vT, vT, (long)CC * NN, NN, 3);

    split_w<<<(II * CC + 255) / 256, 256>>>(Wq, wqk_h, wqk_l, II * CC);
    split_w<<<(II * CC + 255) / 256, 256>>>(Wk, wqk_h + II * CC, wqk_l + II * CC, II * CC);
    cvt_w<<<(CC * CC + 255) / 256, 256>>>(Wu, wu, CC * CC);

    // qk[b][n][0:128]=q, [128:256]=k   M=NN, N=256, K=CC  (3-product fp32)
    gemm_mma<128, false, 1, 3><<<dim3(2, NN / 128, BB), 256, SMEM_Q1>>>(
        xs_h, xs_l, wqk_h, wqk_l, CC, CC, CC, (long)NN * CC, 0L,
        nullptr, qk_h, qk_l, (long)NN * 256, 256, 2);

    // rel[b][n][m] = (q[n].k[m]) / dist   M=NN, N=NN, K=II  (3-product fp32)
    gemm_mma<256, false, 1, 3><<<dim3(NN / 256, NN / 128, BB), 256, SMEM_QK>>>(
        qk_h, qk_l, qk_h + II, qk_l + II, II, 256, 256,
        (long)NN * 256, (long)NN * 256,
        rel, nullptr, nullptr, (long)NN * NN, NN, 1);

    // softmax rows -> P (single fp16)
    softmax_f16<<<BB * NN, 256>>>(rel);

    // y[b][n][o] = P[n][:] . vT[o][:]   M=NN, N=CC, K=NN  (single product, fp16 out)
    gemm_mma<128, true, 2, 1><<<dim3(CC / 128, NN / 128, BB), 256, SMEM_P1>>>(
        P, P, vT, vT, NN, NN, NN, (long)NN * NN, (long)CC * NN,
        nullptr, y, y, (long)NN * CC, CC, 3);

    // u[b][o][n] = Wu[o][:] . y[n][:]   M=CC, N=NN, K=CC  (single product, fp32 out)
    gemm_mma<128, true, 2, 1><<<dim3(NN / 128, CC / 128, BB), 256, SMEM_P1>>>(
        wu, wu, y, y, CC, CC, CC, 0L, (long)NN * CC,
        u, nullptr, nullptr, (long)CC * NN, NN, 0);

    bn_stats<<<CC, 256>>>(u);
    bn_relu_kernel<<<(int)(((size_t)BB * CC * NN / 4) / 256), 256>>>(u, x, gamma, beta, out);
}

// round 13
// speedup vs baseline: 2.1016x; 1.1660x over previous
#include <cuda_runtime.h>
#include <cuda_fp16.h>
#include <stdint.h>

#define BB 8
#define CC 512
#define NN 4096
#define II 128

// ---------------- scratch (__device__ globals; no allocation allowed) -------
__device__ __half g_xs_h[(size_t)BB * NN * CC];
__device__ __half g_xs_l[(size_t)BB * NN * CC];
__device__ __half g_wv[CC * CC];                       // single fp16
__device__ __half g_wqk_h[2 * II * CC], g_wqk_l[2 * II * CC];  // Wq rows 0..127, Wk 128..255
__device__ __half g_wu[CC * CC];                       // single fp16
__device__ __half g_qk_h[(size_t)BB * NN * 256], g_qk_l[(size_t)BB * NN * 256];
__device__ __half g_vT[(size_t)BB * CC * NN];          // single fp16
__device__ float  g_rel[(size_t)BB * NN * NN];
__device__ __half g_P[(size_t)BB * NN * NN];           // single fp16 probabilities
__device__ __half g_y[(size_t)BB * NN * CC];           // single fp16
__device__ float  g_u[(size_t)BB * CC * NN];
__device__ float g_mean[CC], g_rstd[CC];
__device__ float g_rdist[8192];   // 1/(sqrt(d2)+1), d2 <= 2*63^2

// ---------------- PTX helpers (portable, non-'a' features only) -------------
__device__ __forceinline__ uint32_t s2u(const void* p) {
    uint32_t a;
    asm("{ .reg .u64 t; cvta.to.shared.u64 t, %1; cvt.u32.u64 %0, t; }" : "=r"(a) : "l"(p));
    return a;
}
__device__ __forceinline__ void cpa16(uint32_t s, const void* g) {
    asm volatile("cp.async.cg.shared.global [%0], [%1], 16;" :: "r"(s), "l"(g) : "memory");
}
__device__ __forceinline__ void cpa_commit() { asm volatile("cp.async.commit_group;" ::: "memory"); }
template <int W> __device__ __forceinline__ void cpa_wait() {
    asm volatile("cp.async.wait_group %0;" :: "n"(W) : "memory");
}
__device__ __forceinline__ void ldsm4(uint32_t* r, uint32_t addr) {
    asm volatile("ldmatrix.sync.aligned.m8n8.x4.shared.b16 {%0,%1,%2,%3}, [%4];"
                 : "=r"(r[0]), "=r"(r[1]), "=r"(r[2]), "=r"(r[3]) : "r"(addr));
}
__device__ __forceinline__ void mma_f16(float* d, const uint32_t* a, const uint32_t* b) {
    asm volatile(
        "mma.sync.aligned.m16n8k16.row.col.f32.f16.f16.f32 "
        "{%0,%1,%2,%3}, {%4,%5,%6,%7}, {%8,%9}, {%0,%1,%2,%3};"
        : "+f"(d[0]), "+f"(d[1]), "+f"(d[2]), "+f"(d[3])
        : "r"(a[0]), "r"(a[1]), "r"(a[2]), "r"(a[3]), "r"(b[0]), "r"(b[1]));
}
// fp16-accumulator MMA for correction products
__device__ __forceinline__ void mma_f16acc(uint32_t* d, const uint32_t* a, const uint32_t* b) {
    asm volatile(
        "mma.sync.aligned.m16n8k16.row.col.f16.f16.f16.f16 "
        "{%0,%1}, {%2,%3,%4,%5}, {%6,%7}, {%0,%1};"
        : "+r"(d[0]), "+r"(d[1])
        : "r"(a[0]), "r"(a[1]), "r"(a[2]), "r"(a[3]), "r"(b[0]), "r"(b[1]));
}
__device__ __forceinline__ void split_pk(float a, float b, uint32_t& hi, uint32_t& lo) {
    __half2 h, l;
    h.x = __float2half(a); h.y = __float2half(b);
    l.x = __float2half(a - __half2float(h.x));
    l.y = __float2half(b - __half2float(h.y));
    hi = *reinterpret_cast<uint32_t*>(&h);
    lo = *reinterpret_cast<uint32_t*>(&l);
}

// ---------------- split-fp16 HMMA GEMM ---------------------------------------
// C[M,N] = A[M,K] * B[N,K]^T ; operands fp16, K-major, leading dims lda/ldb.
// CTA tile 128 x TN, 8 warps (2m x 4n), warp tile 64 x TN/4.
// NPROD==3 (!F16C): aH*bH + aL*bH + aH*bL, all fp32-acc (A,B are hi/lo pairs)
// NPROD==2 (F16C) : aH*bH fp32-acc + aH*bL fp16-acc correction (A single)
// NPROD==1        : aH*bH only (single x single)
// MINB: min blocks/SM for launch_bounds (occupancy control).
// 3-stage cp.async pipeline, wait_group<1>.
// modes: 0 = fp32, 1 = fp32 * (1/dist), 2 = fp16 (hi,lo) pair, 3 = fp16 single.
#define ROWB 80                      // padded row stride (32 fp16 = 64B -> 80B)
#define A_ARR (128 * ROWB)           // 10240

template <int TN, bool F16C, int MINB, int NPROD>
__global__ void __launch_bounds__(256, MINB)
gemm_mma(const __half* __restrict__ Ah_, const __half* __restrict__ Al_,
         const __half* __restrict__ Bh_, const __half* __restrict__ Bl_,
         int K, int lda, int ldb, long a_batch, long b_batch,
         float* __restrict__ Cf,
         __half* __restrict__ Chi, __half* __restrict__ Clo,
         long c_batch, int Nld, int mode)
{
    constexpr int B_ARR = TN * ROWB;
    constexpr int BH_OFF = A_ARR * ((!F16C && NPROD == 3) ? 2 : 1);
    constexpr int BL_OFF = BH_OFF + B_ARR;
    constexpr int STGB = BH_OFF + B_ARR * (NPROD >= 2 ? 2 : 1);  // bytes per stage
    constexpr int NT = TN / 32;                   // 8-col n-tiles per warp
    constexpr int NB = TN / 64;                   // B ldsm.x4 loads per warp

    extern __shared__ char smem[];
    const uint32_t sb = s2u(smem);
    const int tid = threadIdx.x;
    const int wid = tid >> 5;
    const int lane = tid & 31;
    const int bz = blockIdx.z;
    const int m0 = blockIdx.y * 128;
    const int n0 = blockIdx.x * TN;
    const int warp_m = wid >> 2;     // 0..1 -> 64 rows each
    const int warp_n = wid & 3;      // 0..3 -> TN/4 cols each

    const __half* Ah = Ah_ + (size_t)bz * a_batch + (size_t)m0 * lda;
    const __half* Al = Al_ + (size_t)bz * a_batch + (size_t)m0 * lda;
    const __half* Bh = Bh_ + (size_t)bz * b_batch + (size_t)n0 * ldb;
    const __half* Bl = Bl_ + (size_t)bz * b_batch + (size_t)n0 * ldb;

    const int nch = K >> 5;

    auto load_chunk = [&](int ci, int stg) {
        const uint32_t st = sb + stg * STGB;
        const size_t k0 = (size_t)ci * 32;
#pragma unroll
        for (int p = 0; p < 2; p++) {            // A: 128 rows x 4 sectors
            int f = tid + p * 256;
            int r = f >> 2, s = f & 3;
            uint32_t so = (uint32_t)r * ROWB + s * 16;
            size_t go = (size_t)r * lda + k0 + s * 8;
            cpa16(st + so, Ah + go);
            if (!F16C && NPROD == 3) cpa16(st + A_ARR + so, Al + go);
        }
#pragma unroll
        for (int p = 0; p < TN / 64; p++) {      // B: TN rows x 4 sectors
            int f = tid + p * 256;
            int r = f >> 2, s = f & 3;
            uint32_t so = (uint32_t)r * ROWB + s * 16;
            size_t go = (size_t)r * ldb + k0 + s * 8;
            cpa16(st + BH_OFF + so, Bh + go);
            if (NPROD >= 2) cpa16(st + BL_OFF + so, Bl + go);
        }
        cpa_commit();
    };

    load_chunk(0, 0);
    load_chunk(1, 1);      // nch >= 4 for all our shapes

    // lane offsets for ldmatrix (bytes)
    const int lt = lane & 7, ltile = lane >> 3;
    const uint32_t aLane = (uint32_t)(lt + ((ltile & 1) << 3)) * ROWB + ((ltile >> 1) << 4);
    const uint32_t bLane = (uint32_t)(lt + ((ltile >> 1) << 3)) * ROWB + ((ltile & 1) << 4);

    float acc[4][NT][4];
#pragma unroll
    for (int i = 0; i < 4; i++)
#pragma unroll
        for (int j = 0; j < NT; j++)
#pragma unroll
            for (int c = 0; c < 4; c++) acc[i][j][c] = 0.f;

    uint32_t acc16[4][NT][2];
    if (F16C && NPROD >= 2) {
#pragma unroll
        for (int i = 0; i < 4; i++)
#pragma unroll
            for (int j = 0; j < NT; j++) { acc16[i][j][0] = 0u; acc16[i][j][1] = 0u; }
    }

    for (int i = 0; i < nch; i++) {
        const uint32_t st = sb + (i % 3) * STGB;
        if (i + 1 < nch) cpa_wait<1>(); else cpa_wait<0>();
        __syncthreads();
        if (i + 2 < nch) load_chunk(i + 2, (i + 2) % 3);

        const uint32_t aBh = st +          (uint32_t)warp_m * 64 * ROWB + aLane;
        const uint32_t aBl = st + A_ARR +  (uint32_t)warp_m * 64 * ROWB + aLane;
        const uint32_t bBh = st + BH_OFF + (uint32_t)(warp_n * (TN / 4)) * ROWB + bLane;
        const uint32_t bBl = st + BL_OFF + (uint32_t)(warp_n * (TN / 4)) * ROWB + bLane;

#pragma unroll
        for (int ks = 0; ks < 2; ks++) {
            const uint32_t ko = ks * 32;
            uint32_t aH[4][4], bH[NB][4];
#pragma unroll
            for (int mt = 0; mt < 4; mt++) ldsm4(aH[mt], aBh + mt * 16 * ROWB + ko);
#pragma unroll
            for (int np = 0; np < NB; np++) ldsm4(bH[np], bBh + np * 16 * ROWB + ko);
#pragma unroll
            for (int mt = 0; mt < 4; mt++)
#pragma unroll
                for (int nt = 0; nt < NT; nt++)
                    mma_f16(acc[mt][nt], aH[mt], &bH[nt >> 1][(nt & 1) * 2]);
            if (!F16C && NPROD == 3) {
                uint32_t aL[4][4];
#pragma unroll
                for (int mt = 0; mt < 4; mt++) ldsm4(aL[mt], aBl + mt * 16 * ROWB + ko);
#pragma unroll
                for (int mt = 0; mt < 4; mt++)
#pragma unroll
                    for (int nt = 0; nt < NT; nt++)
                        mma_f16(acc[mt][nt], aL[mt], &bH[nt >> 1][(nt & 1) * 2]);
            }
            if (NPROD >= 2) {
                uint32_t bL[NB][4];
#pragma unroll
                for (int np = 0; np < NB; np++) ldsm4(bL[np], bBl + np * 16 * ROWB + ko);
                if (F16C) {
#pragma unroll
                    for (int mt = 0; mt < 4; mt++)
#pragma unroll
                        for (int nt = 0; nt < NT; nt++)
                            mma_f16acc(acc16[mt][nt], aH[mt], &bL[nt >> 1][(nt & 1) * 2]);
                } else {
#pragma unroll
                    for (int mt = 0; mt < 4; mt++)
#pragma unroll
                        for (int nt = 0; nt < NT; nt++)
                            mma_f16(acc[mt][nt], aH[mt], &bL[nt >> 1][(nt & 1) * 2]);
                }
            }
        }
    }

    // ---- epilogue ----
    const int gp = lane >> 2, tq = lane & 3;
    const int mbase = m0 + warp_m * 64;
    const int nbase = n0 + warp_n * (TN / 4);

#pragma unroll
    for (int mt = 0; mt < 4; mt++) {
#pragma unroll
        for (int half = 0; half < 2; half++) {
            const int r = mbase + mt * 16 + half * 8 + gp;
            if (mode >= 2) {
                __half* oh = Chi + (size_t)bz * c_batch + (size_t)r * Nld;
                __half* ol = Clo + (size_t)bz * c_batch + (size_t)r * Nld;
#pragma unroll
                for (int nt = 0; nt < NT; nt++) {
                    const int col = nbase + nt * 8 + 2 * tq;
                    float v0 = acc[mt][nt][half * 2];
                    float v1 = acc[mt][nt][half * 2 + 1];
                    if (F16C && NPROD >= 2) {
                        __half2 c = *reinterpret_cast<__half2*>(&acc16[mt][nt][half]);
                        v0 += __half2float(c.x);
                        v1 += __half2float(c.y);
                    }
                    uint32_t hi, lo;
                    split_pk(v0, v1, hi, lo);
                    *(uint32_t*)(oh + col) = hi;
                    if (mode == 2) *(uint32_t*)(ol + col) = lo;
                }
            } else {
                float* oc = Cf + (size_t)bz * c_batch + (size_t)r * Nld;
                if (mode == 1) {
                    const int ri = r >> 6, rj = r & 63;
#pragma unroll
                    for (int nt = 0; nt < NT; nt++) {
                        const int col = nbase + nt * 8 + 2 * tq;
                        float v0 = acc[mt][nt][half * 2];
                        float v1 = acc[mt][nt][half * 2 + 1];
                        if (F16C && NPROD >= 2) {
                            __half2 c = *reinterpret_cast<__half2*>(&acc16[mt][nt][half]);
                            v0 += __half2float(c.x);
                            v1 += __half2float(c.y);
                        }
                        int di0 = ri - (col >> 6);
                        int j0 = rj - (col & 63);
                        int j1 = rj - ((col + 1) & 63);
                        float2 o;
                        o.x = v0 * g_rdist[di0 * di0 + j0 * j0];
                        o.y = v1 * g_rdist[di0 * di0 + j1 * j1];
                        *(float2*)(oc + col) = o;
                    }
                } else {
#pragma unroll
                    for (int nt = 0; nt < NT; nt++) {
                        const int col = nbase + nt * 8 + 2 * tq;
                        float v0 = acc[mt][nt][half * 2];
                        float v1 = acc[mt][nt][half * 2 + 1];
                        if (F16C && NPROD >= 2) {
                            __half2 c = *reinterpret_cast<__half2*>(&acc16[mt][nt][half]);
                            v0 += __half2float(c.x);
                            v1 += __half2float(c.y);
                        }
                        float2 o; o.x = v0; o.y = v1;
                        *(float2*)(oc + col) = o;
                    }
                }
            }
        }
    }
}

// ---------------- prep kernels ----------------------------------------------
__global__ void init_rdist() {
    int i = blockIdx.x * 256 + threadIdx.x;
    if (i < 8192) g_rdist[i] = 1.0f / (sqrtf((float)i) + 1.0f);
}

// fp32 -> single fp16
__global__ void cvt_w(const float* __restrict__ w, __half* __restrict__ h, int n) {
    int i = blockIdx.x * 256 + threadIdx.x;
    if (i < n) h[i] = __float2half(w[i]);
}

// fp32 -> fp16 pair
__global__ void split_w(const float* __restrict__ w, __half* __restrict__ h,
                        __half* __restrict__ l, int n) {
    int i = blockIdx.x * 256 + threadIdx.x;
    if (i < n) {
        float v = w[i];
        __half hh = __float2half(v);
        h[i] = hh;
        l[i] = __float2half(v - __half2float(hh));
    }
}

// x[b][c][n] -> xs[b][n][c] as fp16 hi/lo
__global__ void split_transpose(const float* __restrict__ x) {
    __shared__ float t[32][33];
    const int b = blockIdx.z;
    const int n0 = blockIdx.x << 5, c0 = blockIdx.y << 5;
    const int tx = threadIdx.x, ty = threadIdx.y;
    const float* xp = x + ((size_t)b * CC + c0) * NN + n0;
#pragma unroll
    for (int i = 0; i < 4; i++) t[ty + i * 8][tx] = xp[(size_t)(ty + i * 8) * NN + tx];
    __syncthreads();
    const size_t ob = ((size_t)b * NN + n0) * CC + c0;
#pragma unroll
    for (int i = 0; i < 4; i++) {
        float v = t[tx][ty + i * 8];
        __half h = __float2half(v);
        size_t o = ob + (size_t)(ty + i * 8) * CC + tx;
        g_xs_h[o] = h;
        g_xs_l[o] = __float2half(v - __half2float(h));
    }
}

// row softmax, fp32 in -> single fp16 out
__global__ void softmax_f16(const float* __restrict__ rel) {
    __shared__ float red1[8], red2[8];
    const size_t row = blockIdx.x;
    const float4* p = (const float4*)(rel + row * (size_t)NN);
    const int tid = threadIdx.x;

    float4 v[4];
    float mx = -3.0e38f;
#pragma unroll
    for (int i = 0; i < 4; i++) {
        v[i] = p[tid + i * 256];
        mx = fmaxf(mx, fmaxf(fmaxf(v[i].x, v[i].y), fmaxf(v[i].z, v[i].w)));
    }
#pragma unroll
    for (int o = 16; o > 0; o >>= 1) mx = fmaxf(mx, __shfl_xor_sync(0xffffffffu, mx, o));
    if ((tid & 31) == 0) red1[tid >> 5] = mx;
    __syncthreads();
    mx = red1[0];
#pragma unroll
    for (int w = 1; w < 8; w++) mx = fmaxf(mx, red1[w]);

    float s = 0.f;
#pragma unroll
    for (int i = 0; i < 4; i++) {
        v[i].x = __expf(v[i].x - mx); v[i].y = __expf(v[i].y - mx);
        v[i].z = __expf(v[i].z - mx); v[i].w = __expf(v[i].w - mx);
        s += v[i].x + v[i].y + v[i].z + v[i].w;
    }
#pragma unroll
    for (int o = 16; o > 0; o >>= 1) s += __shfl_xor_sync(0xffffffffu, s, o);
    if ((tid & 31) == 0) red2[tid >> 5] = s;
    __syncthreads();
    s = 0.f;
#pragma unroll
    for (int w = 0; w < 8; w++) s += red2[w];
    const float inv = 1.0f / s;

    uint2* P = (uint2*)(g_P + row * (size_t)NN);
#pragma unroll
    for (int i = 0; i < 4; i++) {
        __half2 a, b;
        a.x = __float2half(v[i].x * inv); a.y = __float2half(v[i].y * inv);
        b.x = __float2half(v[i].z * inv); b.y = __float2half(v[i].w * inv);
        uint2 o;
        o.x = *reinterpret_cast<uint32_t*>(&a);
        o.y = *reinterpret_cast<uint32_t*>(&b);
        P[tid + i * 256] = o;
    }
}

// ---------------- BN ---------------------------------------------------------
__global__ void bn_stats(const float* __restrict__ u) {
    __shared__ float rs[8], rs2[8];
    const int c = blockIdx.x;
    const int tid = threadIdx.x;
    float s = 0.f, s2 = 0.f;
    for (int b = 0; b < BB; b++) {
        const float* up = u + ((size_t)b * CC + c) * NN;
        for (int n = tid; n < NN; n += 256) {
            float t = up[n];
            s += t; s2 += t * t;
        }
    }
#pragma unroll
    for (int o = 16; o > 0; o >>= 1) {
        s  += __shfl_xor_sync(0xffffffffu, s, o);
        s2 += __shfl_xor_sync(0xffffffffu, s2, o);
    }
    if ((tid & 31) == 0) { rs[tid >> 5] = s; rs2[tid >> 5] = s2; }
    __syncthreads();
    if (tid == 0) {
        float S = 0.f, S2 = 0.f;
#pragma unroll
        for (int w = 0; w < 8; w++) { S += rs[w]; S2 += rs2[w]; }
        const float cnt = (float)(BB * NN);
        float mean = S / cnt;
        float var = S2 / cnt - mean * mean;
        g_mean[c] = mean;
        g_rstd[c] = rsqrtf(var + 1e-5f);
    }
}

__global__ void bn_relu_kernel(const float* __restrict__ u, const float* __restrict__ x,
                               const float* __restrict__ gamma, const float* __restrict__ beta,
                               float* __restrict__ out) {
    size_t i4 = (size_t)blockIdx.x * blockDim.x + threadIdx.x;
    int c = (int)((i4 * 4 / NN) % CC);
    float m = g_mean[c];
    float r = g_rstd[c] * gamma[c];
    float bt = beta[c];
    float4 uu = ((const float4*)u)[i4];
    float4 xx = ((const float4*)x)[i4];
    float4 o;
    o.x = fmaxf((uu.x - m) * r + bt + xx.x, 0.f);
    o.y = fmaxf((uu.y - m) * r + bt + xx.y, 0.f);
    o.z = fmaxf((uu.z - m) * r + bt + xx.z, 0.f);
    o.w = fmaxf((uu.w - m) * r + bt + xx.w, 0.f);
    ((float4*)out)[i4] = o;
}

// ---------------- launch ------------------------------------------------------
extern "C" void kernel_launch(void* const* d_in, const int* in_sizes, int n_in,
                              void* d_out, int out_size)
{
    const float* x     = (const float*)d_in[0];
    const float* Wv    = (const float*)d_in[1];
    const float* Wq    = (const float*)d_in[2];
    const float* Wk    = (const float*)d_in[3];
    const float* Wu    = (const float*)d_in[4];
    const float* gamma = (const float*)d_in[5];
    const float* beta  = (const float*)d_in[6];
    float* out = (float*)d_out;

    __half *xs_h, *xs_l, *wv, *wqk_h, *wqk_l, *wu;
    __half *qk_h, *qk_l, *vT, *P, *y;
    float *rel, *u;
    cudaGetSymbolAddress((void**)&xs_h,  g_xs_h);  cudaGetSymbolAddress((void**)&xs_l,  g_xs_l);
    cudaGetSymbolAddress((void**)&wv,    g_wv);
    cudaGetSymbolAddress((void**)&wqk_h, g_wqk_h); cudaGetSymbolAddress((void**)&wqk_l, g_wqk_l);
    cudaGetSymbolAddress((void**)&wu,    g_wu);
    cudaGetSymbolAddress((void**)&qk_h,  g_qk_h);  cudaGetSymbolAddress((void**)&qk_l,  g_qk_l);
    cudaGetSymbolAddress((void**)&vT,    g_vT);
    cudaGetSymbolAddress((void**)&P,     g_P);
    cudaGetSymbolAddress((void**)&y,     g_y);
    cudaGetSymbolAddress((void**)&rel,   g_rel);
    cudaGetSymbolAddress((void**)&u,     g_u);

    // smem per CTA per instantiation
    const int SMEM_V  = 3 * (A_ARR + 2 * 128 * ROWB);          // 92160  (<128,true,2,2>)
    const int SMEM_P1 = 3 * (A_ARR + 128 * ROWB);              // 61440  (<128,true,2,1>)
    const int SMEM_Q1 = 3 * (2 * A_ARR + 2 * 128 * ROWB);      // 122880 (<128,false,1,3>)
    cudaFuncSetAttribute(gemm_mma<128, true, 2, 2>,  cudaFuncAttributeMaxDynamicSharedMemorySize, SMEM_V);
    cudaFuncSetAttribute(gemm_mma<128, true, 2, 1>,  cudaFuncAttributeMaxDynamicSharedMemorySize, SMEM_P1);
    cudaFuncSetAttribute(gemm_mma<128, false, 1, 3>, cudaFuncAttributeMaxDynamicSharedMemorySize, SMEM_Q1);

    // ---- prep, ordered so the ncu capture (0-based launch #3) hits v-GEMM ----
    split_transpose<<<dim3(NN / 32, CC / 32, BB), dim3(32, 8)>>>(x);        // 0
    cvt_w<<<(CC * CC + 255) / 256, 256>>>(Wv, wv, CC * CC);                 // 1
    init_rdist<<<32, 256>>>();                                              // 2

    // 3: vT[b][o][m] = Wv[o][:] . xs[m][:]   M=CC, N=NN, K=CC
    //    (2-product internal accuracy, single fp16 out)            <- ncu target
    gemm_mma<128, true, 2, 2><<<dim3(NN / 128, CC / 128, BB), 256, SMEM_V>>>(
        wv, wv, xs_h, xs_l, CC, CC, CC, 0L, (long)NN * CC,
        nullptr, vT, vT, (long)CC * NN, NN, 3);

    split_w<<<(II * CC + 255) / 256, 256>>>(Wq, wqk_h, wqk_l, II * CC);
    split_w<<<(II * CC + 255) / 256, 256>>>(Wk, wqk_h + II * CC, wqk_l + II * CC, II * CC);
    cvt_w<<<(CC * CC + 255) / 256, 256>>>(Wu, wu, CC * CC);

    // qk[b][n][0:128]=q, [128:256]=k   M=NN, N=256, K=CC  (3-product fp32)
    gemm_mma<128, false, 1, 3><<<dim3(2, NN / 128, BB), 256, SMEM_Q1>>>(
        xs_h, xs_l, wqk_h, wqk_l, CC, CC, CC, (long)NN * CC, 0L,
        nullptr, qk_h, qk_l, (long)NN * 256, 256, 2);

    // rel[b][n][m] = (q[n].k[m]) / dist   M=NN, N=NN, K=II
    // 2-product: qh.kh (fp32) + qh.kl (f16 acc); q_l dropped. 2 CTAs/SM.
    gemm_mma<128, true, 2, 2><<<dim3(NN / 128, NN / 128, BB), 256, SMEM_V>>>(
        qk_h, qk_h, qk_h + II, qk_l + II, II, 256, 256,
        (long)NN * 256, (long)NN * 256,
        rel, nullptr, nullptr, (long)NN * NN, NN, 1);

    // softmax rows -> P (single fp16)
    softmax_f16<<<BB * NN, 256>>>(rel);

    // y[b][n][o] = P[n][:] . vT[o][:]   M=NN, N=CC, K=NN  (single product, fp16 out)
    gemm_mma<128, true, 2, 1><<<dim3(CC / 128, NN / 128, BB), 256, SMEM_P1>>>(
        P, P, vT, vT, NN, NN, NN, (long)NN * NN, (long)CC * NN,
        nullptr, y, y, (long)NN * CC, CC, 3);

    // u[b][o][n] = Wu[o][:] . y[n][:]   M=CC, N=NN, K=CC  (single product, fp32 out)
    gemm_mma<128, true, 2, 1><<<dim3(NN / 128, CC / 128, BB), 256, SMEM_P1>>>(
        wu, wu, y, y, CC, CC, CC, 0L, (long)NN * CC,
        u, nullptr, nullptr, (long)CC * NN, NN, 0);

    bn_stats<<<CC, 256>>>(u);
    bn_relu_kernel<<<(int)(((size_t)BB * CC * NN / 4) / 256), 256>>>(u, x, gamma, beta, out);
}

// round 14
// speedup vs baseline: 2.2672x; 1.0788x over previous
#include <cuda_runtime.h>
#include <cuda_fp16.h>
#include <stdint.h>

#define BB 8
#define CC 512
#define NN 4096
#define II 128

// ---------------- scratch (__device__ globals; no allocation allowed) -------
__device__ __half g_xs_h[(size_t)BB * NN * CC];
__device__ __half g_xs_l[(size_t)BB * NN * CC];
__device__ __half g_wv[CC * CC];                       // single fp16
__device__ __half g_wqk_h[2 * II * CC], g_wqk_l[2 * II * CC];  // Wq rows 0..127, Wk 128..255
__device__ __half g_wu[CC * CC];                       // single fp16
__device__ __half g_qk_h[(size_t)BB * NN * 256], g_qk_l[(size_t)BB * NN * 256];
__device__ __half g_vT[(size_t)BB * CC * NN];          // single fp16
__device__ float  g_rel[(size_t)BB * NN * NN];
__device__ __half g_P[(size_t)BB * NN * NN];           // single fp16 probabilities
__device__ __half g_y[(size_t)BB * NN * CC];           // single fp16
__device__ float  g_u[(size_t)BB * CC * NN];
__device__ float g_mean[CC], g_rstd[CC];
__device__ float g_rdist[8192];   // 1/(sqrt(d2)+1), d2 <= 2*63^2

// ---------------- PTX helpers (portable, non-'a' features only) -------------
__device__ __forceinline__ uint32_t s2u(const void* p) {
    uint32_t a;
    asm("{ .reg .u64 t; cvta.to.shared.u64 t, %1; cvt.u32.u64 %0, t; }" : "=r"(a) : "l"(p));
    return a;
}
__device__ __forceinline__ void cpa16(uint32_t s, const void* g) {
    asm volatile("cp.async.cg.shared.global [%0], [%1], 16;" :: "r"(s), "l"(g) : "memory");
}
__device__ __forceinline__ void cpa_commit() { asm volatile("cp.async.commit_group;" ::: "memory"); }
template <int W> __device__ __forceinline__ void cpa_wait() {
    asm volatile("cp.async.wait_group %0;" :: "n"(W) : "memory");
}
__device__ __forceinline__ void ldsm4(uint32_t* r, uint32_t addr) {
    asm volatile("ldmatrix.sync.aligned.m8n8.x4.shared.b16 {%0,%1,%2,%3}, [%4];"
                 : "=r"(r[0]), "=r"(r[1]), "=r"(r[2]), "=r"(r[3]) : "r"(addr));
}
__device__ __forceinline__ void mma_f16(float* d, const uint32_t* a, const uint32_t* b) {
    asm volatile(
        "mma.sync.aligned.m16n8k16.row.col.f32.f16.f16.f32 "
        "{%0,%1,%2,%3}, {%4,%5,%6,%7}, {%8,%9}, {%0,%1,%2,%3};"
        : "+f"(d[0]), "+f"(d[1]), "+f"(d[2]), "+f"(d[3])
        : "r"(a[0]), "r"(a[1]), "r"(a[2]), "r"(a[3]), "r"(b[0]), "r"(b[1]));
}
// fp16-accumulator MMA for correction products
__device__ __forceinline__ void mma_f16acc(uint32_t* d, const uint32_t* a, const uint32_t* b) {
    asm volatile(
        "mma.sync.aligned.m16n8k16.row.col.f16.f16.f16.f16 "
        "{%0,%1}, {%2,%3,%4,%5}, {%6,%7}, {%0,%1};"
        : "+r"(d[0]), "+r"(d[1])
        : "r"(a[0]), "r"(a[1]), "r"(a[2]), "r"(a[3]), "r"(b[0]), "r"(b[1]));
}
__device__ __forceinline__ void split_pk(float a, float b, uint32_t& hi, uint32_t& lo) {
    __half2 h, l;
    h.x = __float2half(a); h.y = __float2half(b);
    l.x = __float2half(a - __half2float(h.x));
    l.y = __float2half(b - __half2float(h.y));
    hi = *reinterpret_cast<uint32_t*>(&h);
    lo = *reinterpret_cast<uint32_t*>(&l);
}

// ---------------- split-fp16 HMMA GEMM ---------------------------------------
// C[M,N] = A[M,K] * B[N,K]^T ; operands fp16, K-major, leading dims lda/ldb.
// CTA tile 128 x TN, 8 warps (2m x 4n), warp tile 64 x TN/4.
// NPROD==3 (!F16C): aH*bH + aL*bH + aH*bL, all fp32-acc (A,B are hi/lo pairs)
// NPROD==2 (F16C) : aH*bH fp32-acc + aH*bL fp16-acc correction (A single)
// NPROD==1        : aH*bH only (single x single)
// MINB: min blocks/SM for launch_bounds.  NSTG: pipeline stages (2 or 3).
// modes: 0 = fp32, 1 = fp32 * (1/dist), 2 = fp16 (hi,lo) pair, 3 = fp16 single.
#define ROWB 80                      // padded row stride (32 fp16 = 64B -> 80B)
#define A_ARR (128 * ROWB)           // 10240

template <int TN, bool F16C, int MINB, int NPROD, int NSTG>
__global__ void __launch_bounds__(256, MINB)
gemm_mma(const __half* __restrict__ Ah_, const __half* __restrict__ Al_,
         const __half* __restrict__ Bh_, const __half* __restrict__ Bl_,
         int K, int lda, int ldb, long a_batch, long b_batch,
         float* __restrict__ Cf,
         __half* __restrict__ Chi, __half* __restrict__ Clo,
         long c_batch, int Nld, int mode)
{
    constexpr int B_ARR = TN * ROWB;
    constexpr int BH_OFF = A_ARR * ((!F16C && NPROD == 3) ? 2 : 1);
    constexpr int BL_OFF = BH_OFF + B_ARR;
    constexpr int STGB = BH_OFF + B_ARR * (NPROD >= 2 ? 2 : 1);  // bytes per stage
    constexpr int NT = TN / 32;                   // 8-col n-tiles per warp
    constexpr int NB = TN / 64;                   // B ldsm.x4 loads per warp

    extern __shared__ char smem[];
    const uint32_t sb = s2u(smem);
    const int tid = threadIdx.x;
    const int wid = tid >> 5;
    const int lane = tid & 31;
    const int bz = blockIdx.z;
    const int m0 = blockIdx.y * 128;
    const int n0 = blockIdx.x * TN;
    const int warp_m = wid >> 2;     // 0..1 -> 64 rows each
    const int warp_n = wid & 3;      // 0..3 -> TN/4 cols each

    const __half* Ah = Ah_ + (size_t)bz * a_batch + (size_t)m0 * lda;
    const __half* Al = Al_ + (size_t)bz * a_batch + (size_t)m0 * lda;
    const __half* Bh = Bh_ + (size_t)bz * b_batch + (size_t)n0 * ldb;
    const __half* Bl = Bl_ + (size_t)bz * b_batch + (size_t)n0 * ldb;

    const int nch = K >> 5;

    auto load_chunk = [&](int ci, int stg) {
        const uint32_t st = sb + stg * STGB;
        const size_t k0 = (size_t)ci * 32;
#pragma unroll
        for (int p = 0; p < 2; p++) {            // A: 128 rows x 4 sectors
            int f = tid + p * 256;
            int r = f >> 2, s = f & 3;
            uint32_t so = (uint32_t)r * ROWB + s * 16;
            size_t go = (size_t)r * lda + k0 + s * 8;
            cpa16(st + so, Ah + go);
            if (!F16C && NPROD == 3) cpa16(st + A_ARR + so, Al + go);
        }
#pragma unroll
        for (int p = 0; p < TN / 64; p++) {      // B: TN rows x 4 sectors
            int f = tid + p * 256;
            int r = f >> 2, s = f & 3;
            uint32_t so = (uint32_t)r * ROWB + s * 16;
            size_t go = (size_t)r * ldb + k0 + s * 8;
            cpa16(st + BH_OFF + so, Bh + go);
            if (NPROD >= 2) cpa16(st + BL_OFF + so, Bl + go);
        }
        cpa_commit();
    };

    // lane offsets for ldmatrix (bytes)
    const int lt = lane & 7, ltile = lane >> 3;
    const uint32_t aLane = (uint32_t)(lt + ((ltile & 1) << 3)) * ROWB + ((ltile >> 1) << 4);
    const uint32_t bLane = (uint32_t)(lt + ((ltile >> 1) << 3)) * ROWB + ((ltile & 1) << 4);

    float acc[4][NT][4];
#pragma unroll
    for (int i = 0; i < 4; i++)
#pragma unroll
        for (int j = 0; j < NT; j++)
#pragma unroll
            for (int c = 0; c < 4; c++) acc[i][j][c] = 0.f;

    uint32_t acc16[4][NT][2];
    if (F16C && NPROD >= 2) {
#pragma unroll
        for (int i = 0; i < 4; i++)
#pragma unroll
            for (int j = 0; j < NT; j++) { acc16[i][j][0] = 0u; acc16[i][j][1] = 0u; }
    }

    auto compute_chunk = [&](uint32_t st) {
        const uint32_t aBh = st +          (uint32_t)warp_m * 64 * ROWB + aLane;
        const uint32_t aBl = st + A_ARR +  (uint32_t)warp_m * 64 * ROWB + aLane;
        const uint32_t bBh = st + BH_OFF + (uint32_t)(warp_n * (TN / 4)) * ROWB + bLane;
        const uint32_t bBl = st + BL_OFF + (uint32_t)(warp_n * (TN / 4)) * ROWB + bLane;
#pragma unroll
        for (int ks = 0; ks < 2; ks++) {
            const uint32_t ko = ks * 32;
            uint32_t aH[4][4], bH[NB][4];
#pragma unroll
            for (int mt = 0; mt < 4; mt++) ldsm4(aH[mt], aBh + mt * 16 * ROWB + ko);
#pragma unroll
            for (int np = 0; np < NB; np++) ldsm4(bH[np], bBh + np * 16 * ROWB + ko);
#pragma unroll
            for (int mt = 0; mt < 4; mt++)
#pragma unroll
                for (int nt = 0; nt < NT; nt++)
                    mma_f16(acc[mt][nt], aH[mt], &bH[nt >> 1][(nt & 1) * 2]);
            if (!F16C && NPROD == 3) {
                uint32_t aL[4][4];
#pragma unroll
                for (int mt = 0; mt < 4; mt++) ldsm4(aL[mt], aBl + mt * 16 * ROWB + ko);
#pragma unroll
                for (int mt = 0; mt < 4; mt++)
#pragma unroll
                    for (int nt = 0; nt < NT; nt++)
                        mma_f16(acc[mt][nt], aL[mt], &bH[nt >> 1][(nt & 1) * 2]);
            }
            if (NPROD >= 2) {
                uint32_t bL[NB][4];
#pragma unroll
                for (int np = 0; np < NB; np++) ldsm4(bL[np], bBl + np * 16 * ROWB + ko);
                if (F16C) {
#pragma unroll
                    for (int mt = 0; mt < 4; mt++)
#pragma unroll
                        for (int nt = 0; nt < NT; nt++)
                            mma_f16acc(acc16[mt][nt], aH[mt], &bL[nt >> 1][(nt & 1) * 2]);
                } else {
#pragma unroll
                    for (int mt = 0; mt < 4; mt++)
#pragma unroll
                        for (int nt = 0; nt < NT; nt++)
                            mma_f16(acc[mt][nt], aH[mt], &bL[nt >> 1][(nt & 1) * 2]);
                }
            }
        }
    };

    if (NSTG == 3) {
        load_chunk(0, 0);
        load_chunk(1, 1);
        for (int i = 0; i < nch; i++) {
            const uint32_t st = sb + (i % 3) * STGB;
            if (i + 1 < nch) cpa_wait<1>(); else cpa_wait<0>();
            __syncthreads();
            if (i + 2 < nch) load_chunk(i + 2, (i + 2) % 3);
            compute_chunk(st);
        }
    } else {
        // 2-stage, single load in flight (R6 structure)
        load_chunk(0, 0);
        for (int i = 0; i < nch; i++) {
            const uint32_t st = sb + (i & 1) * STGB;
            cpa_wait<0>();
            __syncthreads();
            if (i + 1 < nch) load_chunk(i + 1, (i + 1) & 1);
            compute_chunk(st);
        }
    }

    // ---- epilogue ----
    const int gp = lane >> 2, tq = lane & 3;
    const int mbase = m0 + warp_m * 64;
    const int nbase = n0 + warp_n * (TN / 4);

#pragma unroll
    for (int mt = 0; mt < 4; mt++) {
#pragma unroll
        for (int half = 0; half < 2; half++) {
            const int r = mbase + mt * 16 + half * 8 + gp;
            if (mode >= 2) {
                __half* oh = Chi + (size_t)bz * c_batch + (size_t)r * Nld;
                __half* ol = Clo + (size_t)bz * c_batch + (size_t)r * Nld;
#pragma unroll
                for (int nt = 0; nt < NT; nt++) {
                    const int col = nbase + nt * 8 + 2 * tq;
                    float v0 = acc[mt][nt][half * 2];
                    float v1 = acc[mt][nt][half * 2 + 1];
                    if (F16C && NPROD >= 2) {
                        __half2 c = *reinterpret_cast<__half2*>(&acc16[mt][nt][half]);
                        v0 += __half2float(c.x);
                        v1 += __half2float(c.y);
                    }
                    uint32_t hi, lo;
                    split_pk(v0, v1, hi, lo);
                    *(uint32_t*)(oh + col) = hi;
                    if (mode == 2) *(uint32_t*)(ol + col) = lo;
                }
            } else {
                float* oc = Cf + (size_t)bz * c_batch + (size_t)r * Nld;
                if (mode == 1) {
                    const int ri = r >> 6, rj = r & 63;
#pragma unroll
                    for (int nt = 0; nt < NT; nt++) {
                        const int col = nbase + nt * 8 + 2 * tq;
                        float v0 = acc[mt][nt][half * 2];
                        float v1 = acc[mt][nt][half * 2 + 1];
                        if (F16C && NPROD >= 2) {
                            __half2 c = *reinterpret_cast<__half2*>(&acc16[mt][nt][half]);
                            v0 += __half2float(c.x);
                            v1 += __half2float(c.y);
                        }
                        int di0 = ri - (col >> 6);
                        int j0 = rj - (col & 63);
                        int j1 = rj - ((col + 1) & 63);
                        float2 o;
                        o.x = v0 * g_rdist[di0 * di0 + j0 * j0];
                        o.y = v1 * g_rdist[di0 * di0 + j1 * j1];
                        *(float2*)(oc + col) = o;
                    }
                } else {
#pragma unroll
                    for (int nt = 0; nt < NT; nt++) {
                        const int col = nbase + nt * 8 + 2 * tq;
                        float v0 = acc[mt][nt][half * 2];
                        float v1 = acc[mt][nt][half * 2 + 1];
                        if (F16C && NPROD >= 2) {
                            __half2 c = *reinterpret_cast<__half2*>(&acc16[mt][nt][half]);
                            v0 += __half2float(c.x);
                            v1 += __half2float(c.y);
                        }
                        float2 o; o.x = v0; o.y = v1;
                        *(float2*)(oc + col) = o;
                    }
                }
            }
        }
    }
}

// ---------------- prep kernels ----------------------------------------------
__global__ void init_rdist() {
    int i = blockIdx.x * 256 + threadIdx.x;
    if (i < 8192) g_rdist[i] = 1.0f / (sqrtf((float)i) + 1.0f);
}

// fp32 -> single fp16
__global__ void cvt_w(const float* __restrict__ w, __half* __restrict__ h, int n) {
    int i = blockIdx.x * 256 + threadIdx.x;
    if (i < n) h[i] = __float2half(w[i]);
}

// fp32 -> fp16 pair
__global__ void split_w(const float* __restrict__ w, __half* __restrict__ h,
                        __half* __restrict__ l, int n) {
    int i = blockIdx.x * 256 + threadIdx.x;
    if (i < n) {
        float v = w[i];
        __half hh = __float2half(v);
        h[i] = hh;
        l[i] = __float2half(v - __half2float(hh));
    }
}

// x[b][c][n] -> xs[b][n][c] as fp16 hi/lo
__global__ void split_transpose(const float* __restrict__ x) {
    __shared__ float t[32][33];
    const int b = blockIdx.z;
    const int n0 = blockIdx.x << 5, c0 = blockIdx.y << 5;
    const int tx = threadIdx.x, ty = threadIdx.y;
    const float* xp = x + ((size_t)b * CC + c0) * NN + n0;
#pragma unroll
    for (int i = 0; i < 4; i++) t[ty + i * 8][tx] = xp[(size_t)(ty + i * 8) * NN + tx];
    __syncthreads();
    const size_t ob = ((size_t)b * NN + n0) * CC + c0;
#pragma unroll
    for (int i = 0; i < 4; i++) {
        float v = t[tx][ty + i * 8];
        __half h = __float2half(v);
        size_t o = ob + (size_t)(ty + i * 8) * CC + tx;
        g_xs_h[o] = h;
        g_xs_l[o] = __float2half(v - __half2float(h));
    }
}

// row softmax, fp32 in -> single fp16 out
__global__ void softmax_f16(const float* __restrict__ rel) {
    __shared__ float red1[8], red2[8];
    const size_t row = blockIdx.x;
    const float4* p = (const float4*)(rel + row * (size_t)NN);
    const int tid = threadIdx.x;

    float4 v[4];
    float mx = -3.0e38f;
#pragma unroll
    for (int i = 0; i < 4; i++) {
        v[i] = p[tid + i * 256];
        mx = fmaxf(mx, fmaxf(fmaxf(v[i].x, v[i].y), fmaxf(v[i].z, v[i].w)));
    }
#pragma unroll
    for (int o = 16; o > 0; o >>= 1) mx = fmaxf(mx, __shfl_xor_sync(0xffffffffu, mx, o));
    if ((tid & 31) == 0) red1[tid >> 5] = mx;
    __syncthreads();
    mx = red1[0];
#pragma unroll
    for (int w = 1; w < 8; w++) mx = fmaxf(mx, red1[w]);

    float s = 0.f;
#pragma unroll
    for (int i = 0; i < 4; i++) {
        v[i].x = __expf(v[i].x - mx); v[i].y = __expf(v[i].y - mx);
        v[i].z = __expf(v[i].z - mx); v[i].w = __expf(v[i].w - mx);
        s += v[i].x + v[i].y + v[i].z + v[i].w;
    }
#pragma unroll
    for (int o = 16; o > 0; o >>= 1) s += __shfl_xor_sync(0xffffffffu, s, o);
    if ((tid & 31) == 0) red2[tid >> 5] = s;
    __syncthreads();
    s = 0.f;
#pragma unroll
    for (int w = 0; w < 8; w++) s += red2[w];
    const float inv = 1.0f / s;

    uint2* P = (uint2*)(g_P + row * (size_t)NN);
#pragma unroll
    for (int i = 0; i < 4; i++) {
        __half2 a, b;
        a.x = __float2half(v[i].x * inv); a.y = __float2half(v[i].y * inv);
        b.x = __float2half(v[i].z * inv); b.y = __float2half(v[i].w * inv);
        uint2 o;
        o.x = *reinterpret_cast<uint32_t*>(&a);
        o.y = *reinterpret_cast<uint32_t*>(&b);
        P[tid + i * 256] = o;
    }
}

// ---------------- BN ---------------------------------------------------------
__global__ void bn_stats(const float* __restrict__ u) {
    __shared__ float rs[8], rs2[8];
    const int c = blockIdx.x;
    const int tid = threadIdx.x;
    float s = 0.f, s2 = 0.f;
    for (int b = 0; b < BB; b++) {
        const float* up = u + ((size_t)b * CC + c) * NN;
        for (int n = tid; n < NN; n += 256) {
            float t = up[n];
            s += t; s2 += t * t;
        }
    }
#pragma unroll
    for (int o = 16; o > 0; o >>= 1) {
        s  += __shfl_xor_sync(0xffffffffu, s, o);
        s2 += __shfl_xor_sync(0xffffffffu, s2, o);
    }
    if ((tid & 31) == 0) { rs[tid >> 5] = s; rs2[tid >> 5] = s2; }
    __syncthreads();
    if (tid == 0) {
        float S = 0.f, S2 = 0.f;
#pragma unroll
        for (int w = 0; w < 8; w++) { S += rs[w]; S2 += rs2[w]; }
        const float cnt = (float)(BB * NN);
        float mean = S / cnt;
        float var = S2 / cnt - mean * mean;
        g_mean[c] = mean;
        g_rstd[c] = rsqrtf(var + 1e-5f);
    }
}

__global__ void bn_relu_kernel(const float* __restrict__ u, const float* __restrict__ x,
                               const float* __restrict__ gamma, const float* __restrict__ beta,
                               float* __restrict__ out) {
    size_t i4 = (size_t)blockIdx.x * blockDim.x + threadIdx.x;
    int c = (int)((i4 * 4 / NN) % CC);
    float m = g_mean[c];
    float r = g_rstd[c] * gamma[c];
    float bt = beta[c];
    float4 uu = ((const float4*)u)[i4];
    float4 xx = ((const float4*)x)[i4];
    float4 o;
    o.x = fmaxf((uu.x - m) * r + bt + xx.x, 0.f);
    o.y = fmaxf((uu.y - m) * r + bt + xx.y, 0.f);
    o.z = fmaxf((uu.z - m) * r + bt + xx.z, 0.f);
    o.w = fmaxf((uu.w - m) * r + bt + xx.w, 0.f);
    ((float4*)out)[i4] = o;
}

// ---------------- launch ------------------------------------------------------
extern "C" void kernel_launch(void* const* d_in, const int* in_sizes, int n_in,
                              void* d_out, int out_size)
{
    const float* x     = (const float*)d_in[0];
    const float* Wv    = (const float*)d_in[1];
    const float* Wq    = (const float*)d_in[2];
    const float* Wk    = (const float*)d_in[3];
    const float* Wu    = (const float*)d_in[4];
    const float* gamma = (const float*)d_in[5];
    const float* beta  = (const float*)d_in[6];
    float* out = (float*)d_out;

    __half *xs_h, *xs_l, *wv, *wqk_h, *wqk_l, *wu;
    __half *qk_h, *qk_l, *vT, *P, *y;
    float *rel, *u;
    cudaGetSymbolAddress((void**)&xs_h,  g_xs_h);  cudaGetSymbolAddress((void**)&xs_l,  g_xs_l);
    cudaGetSymbolAddress((void**)&wv,    g_wv);
    cudaGetSymbolAddress((void**)&wqk_h, g_wqk_h); cudaGetSymbolAddress((void**)&wqk_l, g_wqk_l);
    cudaGetSymbolAddress((void**)&wu,    g_wu);
    cudaGetSymbolAddress((void**)&qk_h,  g_qk_h);  cudaGetSymbolAddress((void**)&qk_l,  g_qk_l);
    cudaGetSymbolAddress((void**)&vT,    g_vT);
    cudaGetSymbolAddress((void**)&P,     g_P);
    cudaGetSymbolAddress((void**)&y,     g_y);
    cudaGetSymbolAddress((void**)&rel,   g_rel);
    cudaGetSymbolAddress((void**)&u,     g_u);

    // smem per CTA per instantiation
    const int SMEM_P1 = 3 * (A_ARR + 128 * ROWB);              // 61440  (<128,true,2,1,3>)
    const int SMEM_QKd = 3 * (A_ARR + 2 * 128 * ROWB);         // 92160  (<128,true,2,2,3>)
    const int SMEM_QK2 = 2 * (2 * A_ARR + 2 * 128 * ROWB);     // 81920  (<128,false,2,3,2>)
    cudaFuncSetAttribute(gemm_mma<128, true, 2, 1, 3>,  cudaFuncAttributeMaxDynamicSharedMemorySize, SMEM_P1);
    cudaFuncSetAttribute(gemm_mma<128, true, 2, 2, 3>,  cudaFuncAttributeMaxDynamicSharedMemorySize, SMEM_QKd);
    cudaFuncSetAttribute(gemm_mma<128, false, 2, 3, 2>, cudaFuncAttributeMaxDynamicSharedMemorySize, SMEM_QK2);

    // ---- prep, ordered so the ncu capture (0-based launch #3) hits v-GEMM ----
    split_transpose<<<dim3(NN / 32, CC / 32, BB), dim3(32, 8)>>>(x);        // 0
    cvt_w<<<(CC * CC + 255) / 256, 256>>>(Wv, wv, CC * CC);                 // 1
    init_rdist<<<32, 256>>>();                                              // 2

    // 3: vT[b][o][m] = Wv[o][:] . xs[m][:]   M=CC, N=NN, K=CC
    //    single product, single fp16 out                           <- ncu target
    gemm_mma<128, true, 2, 1, 3><<<dim3(NN / 128, CC / 128, BB), 256, SMEM_P1>>>(
        wv, wv, xs_h, xs_h, CC, CC, CC, 0L, (long)NN * CC,
        nullptr, vT, vT, (long)CC * NN, NN, 3);

    split_w<<<(II * CC + 255) / 256, 256>>>(Wq, wqk_h, wqk_l, II * CC);
    split_w<<<(II * CC + 255) / 256, 256>>>(Wk, wqk_h + II * CC, wqk_l + II * CC, II * CC);
    cvt_w<<<(CC * CC + 255) / 256, 256>>>(Wu, wu, CC * CC);

    // qk[b][n][0:128]=q, [128:256]=k   M=NN, N=256, K=CC
    // 3-product fp32, 2-stage pipeline, 2 CTAs/SM
    gemm_mma<128, false, 2, 3, 2><<<dim3(2, NN / 128, BB), 256, SMEM_QK2>>>(
        xs_h, xs_l, wqk_h, wqk_l, CC, CC, CC, (long)NN * CC, 0L,
        nullptr, qk_h, qk_l, (long)NN * 256, 256, 2);

    // rel[b][n][m] = (q[n].k[m]) / dist   M=NN, N=NN, K=II
    // 2-product: qh.kh (fp32) + qh.kl (f16 acc); q_l dropped. 2 CTAs/SM.
    gemm_mma<128, true, 2, 2, 3><<<dim3(NN / 128, NN / 128, BB), 256, SMEM_QKd>>>(
        qk_h, qk_h, qk_h + II, qk_l + II, II, 256, 256,
        (long)NN * 256, (long)NN * 256,
        rel, nullptr, nullptr, (long)NN * NN, NN, 1);

    // softmax rows -> P (single fp16)
    softmax_f16<<<BB * NN, 256>>>(rel);

    // y[b][n][o] = P[n][:] . vT[o][:]   M=NN, N=CC, K=NN  (single product, fp16 out)
    gemm_mma<128, true, 2, 1, 3><<<dim3(CC / 128, NN / 128, BB), 256, SMEM_P1>>>(
        P, P, vT, vT, NN, NN, NN, (long)NN * NN, (long)CC * NN,
        nullptr, y, y, (long)NN * CC, CC, 3);

    // u[b][o][n] = Wu[o][:] . y[n][:]   M=CC, N=NN, K=CC  (single product, fp32 out)
    gemm_mma<128, true, 2, 1, 3><<<dim3(NN / 128, CC / 128, BB), 256, SMEM_P1>>>(
        wu, wu, y, y, CC, CC, CC, 0L, (long)NN * CC,
        u, nullptr, nullptr, (long)CC * NN, NN, 0);

    bn_stats<<<CC, 256>>>(u);
    bn_relu_kernel<<<(int)(((size_t)BB * CC * NN / 4) / 256), 256>>>(u, x, gamma, beta, out);
}

// round 15
// speedup vs baseline: 2.4040x; 1.0603x over previous
#include <cuda_runtime.h>
#include <cuda_fp16.h>
#include <stdint.h>

#define BB 8
#define CC 512
#define NN 4096
#define II 128

// ---------------- scratch (__device__ globals; no allocation allowed) -------
__device__ __half g_xs_h[(size_t)BB * NN * CC];
__device__ __half g_xs_l[(size_t)BB * NN * CC];
__device__ __half g_wv[CC * CC];                       // single fp16
__device__ __half g_wqk_h[2 * II * CC], g_wqk_l[2 * II * CC];  // Wq rows 0..127, Wk 128..255
__device__ __half g_wu[CC * CC];                       // single fp16
__device__ __half g_qk_h[(size_t)BB * NN * 256], g_qk_l[(size_t)BB * NN * 256];
__device__ __half g_vT[(size_t)BB * CC * NN];          // single fp16
__device__ float  g_rel[(size_t)BB * NN * NN];
__device__ __half g_P[(size_t)BB * NN * NN];           // single fp16 probabilities
__device__ __half g_y[(size_t)BB * NN * CC];           // single fp16
__device__ float  g_u[(size_t)BB * CC * NN];
__device__ float g_mean[CC], g_rstd[CC];
__device__ float g_rdist[8192];   // 1/(sqrt(d2)+1), d2 <= 2*63^2

// ---------------- PTX helpers (portable, non-'a' features only) -------------
__device__ __forceinline__ uint32_t s2u(const void* p) {
    uint32_t a;
    asm("{ .reg .u64 t; cvta.to.shared.u64 t, %1; cvt.u32.u64 %0, t; }" : "=r"(a) : "l"(p));
    return a;
}
__device__ __forceinline__ void cpa16(uint32_t s, const void* g) {
    asm volatile("cp.async.cg.shared.global [%0], [%1], 16;" :: "r"(s), "l"(g) : "memory");
}
__device__ __forceinline__ void cpa_commit() { asm volatile("cp.async.commit_group;" ::: "memory"); }
template <int W> __device__ __forceinline__ void cpa_wait() {
    asm volatile("cp.async.wait_group %0;" :: "n"(W) : "memory");
}
__device__ __forceinline__ void ldsm4(uint32_t* r, uint32_t addr) {
    asm volatile("ldmatrix.sync.aligned.m8n8.x4.shared.b16 {%0,%1,%2,%3}, [%4];"
                 : "=r"(r[0]), "=r"(r[1]), "=r"(r[2]), "=r"(r[3]) : "r"(addr));
}
__device__ __forceinline__ void mma_f16(float* d, const uint32_t* a, const uint32_t* b) {
    asm volatile(
        "mma.sync.aligned.m16n8k16.row.col.f32.f16.f16.f32 "
        "{%0,%1,%2,%3}, {%4,%5,%6,%7}, {%8,%9}, {%0,%1,%2,%3};"
        : "+f"(d[0]), "+f"(d[1]), "+f"(d[2]), "+f"(d[3])
        : "r"(a[0]), "r"(a[1]), "r"(a[2]), "r"(a[3]), "r"(b[0]), "r"(b[1]));
}
// fp16-accumulator MMA for correction products
__device__ __forceinline__ void mma_f16acc(uint32_t* d, const uint32_t* a, const uint32_t* b) {
    asm volatile(
        "mma.sync.aligned.m16n8k16.row.col.f16.f16.f16.f16 "
        "{%0,%1}, {%2,%3,%4,%5}, {%6,%7}, {%0,%1};"
        : "+r"(d[0]), "+r"(d[1])
        : "r"(a[0]), "r"(a[1]), "r"(a[2]), "r"(a[3]), "r"(b[0]), "r"(b[1]));
}
__device__ __forceinline__ void split_pk(float a, float b, uint32_t& hi, uint32_t& lo) {
    __half2 h, l;
    h.x = __float2half(a); h.y = __float2half(b);
    l.x = __float2half(a - __half2float(h.x));
    l.y = __float2half(b - __half2float(h.y));
    hi = *reinterpret_cast<uint32_t*>(&h);
    lo = *reinterpret_cast<uint32_t*>(&l);
}

// ---------------- split-fp16 HMMA GEMM ---------------------------------------
// C[M,N] = A[M,K] * B[N,K]^T ; operands fp16, K-major, leading dims lda/ldb.
// CTA tile 128 x TN, 8 warps (2m x 4n), warp tile 64 x TN/4.
// NPROD==3 (!F16C): aH*bH + aL*bH + aH*bL, all fp32-acc (A,B are hi/lo pairs)
// NPROD==2 (F16C) : aH*bH fp32-acc + aH*bL fp16-acc correction (A single)
// NPROD==1        : aH*bH only (single x single)
// MINB: min blocks/SM.  NSTG: pipeline stages (2 or 3).  KCH: K-chunk (32/64).
// modes: 0 = fp32, 1 = fp32 * (1/dist), 2 = fp16 (hi,lo) pair, 3 = fp16 single.
template <int TN, bool F16C, int MINB, int NPROD, int NSTG, int KCH>
__global__ void __launch_bounds__(256, MINB)
gemm_mma(const __half* __restrict__ Ah_, const __half* __restrict__ Al_,
         const __half* __restrict__ Bh_, const __half* __restrict__ Bl_,
         int K, int lda, int ldb, long a_batch, long b_batch,
         float* __restrict__ Cf,
         __half* __restrict__ Chi, __half* __restrict__ Clo,
         long c_batch, int Nld, int mode)
{
    constexpr int ROWB = (KCH == 32) ? 80 : 144;   // padded row stride bytes
    constexpr int A_ARR = 128 * ROWB;
    constexpr int B_ARR = TN * ROWB;
    constexpr int BH_OFF = A_ARR * ((!F16C && NPROD == 3) ? 2 : 1);
    constexpr int BL_OFF = BH_OFF + B_ARR;
    constexpr int STGB = BH_OFF + B_ARR * (NPROD >= 2 ? 2 : 1);  // bytes per stage
    constexpr int NT = TN / 32;                   // 8-col n-tiles per warp
    constexpr int NB = TN / 64;                   // B ldsm.x4 loads per warp
    constexpr int SEC = KCH / 8;                  // 16B sectors per row

    extern __shared__ char smem[];
    const uint32_t sb = s2u(smem);
    const int tid = threadIdx.x;
    const int wid = tid >> 5;
    const int lane = tid & 31;
    const int bz = blockIdx.z;
    const int m0 = blockIdx.y * 128;
    const int n0 = blockIdx.x * TN;
    const int warp_m = wid >> 2;     // 0..1 -> 64 rows each
    const int warp_n = wid & 3;      // 0..3 -> TN/4 cols each

    const __half* Ah = Ah_ + (size_t)bz * a_batch + (size_t)m0 * lda;
    const __half* Al = Al_ + (size_t)bz * a_batch + (size_t)m0 * lda;
    const __half* Bh = Bh_ + (size_t)bz * b_batch + (size_t)n0 * ldb;
    const __half* Bl = Bl_ + (size_t)bz * b_batch + (size_t)n0 * ldb;

    const int nch = K / KCH;

    auto load_chunk = [&](int ci, int stg) {
        const uint32_t st = sb + stg * STGB;
        const size_t k0 = (size_t)ci * KCH;
#pragma unroll
        for (int p = 0; p < 128 * SEC / 256; p++) {     // A: 128 rows x SEC sectors
            int f = tid + p * 256;
            int r = f / SEC, s = f % SEC;
            uint32_t so = (uint32_t)r * ROWB + s * 16;
            size_t go = (size_t)r * lda + k0 + s * 8;
            cpa16(st + so, Ah + go);
            if (!F16C && NPROD == 3) cpa16(st + A_ARR + so, Al + go);
        }
#pragma unroll
        for (int p = 0; p < TN * SEC / 256; p++) {      // B: TN rows x SEC sectors
            int f = tid + p * 256;
            int r = f / SEC, s = f % SEC;
            uint32_t so = (uint32_t)r * ROWB + s * 16;
            size_t go = (size_t)r * ldb + k0 + s * 8;
            cpa16(st + BH_OFF + so, Bh + go);
            if (NPROD >= 2) cpa16(st + BL_OFF + so, Bl + go);
        }
        cpa_commit();
    };

    // lane offsets for ldmatrix (bytes)
    const int lt = lane & 7, ltile = lane >> 3;
    const uint32_t aLane = (uint32_t)(lt + ((ltile & 1) << 3)) * ROWB + ((ltile >> 1) << 4);
    const uint32_t bLane = (uint32_t)(lt + ((ltile >> 1) << 3)) * ROWB + ((ltile & 1) << 4);

    float acc[4][NT][4];
#pragma unroll
    for (int i = 0; i < 4; i++)
#pragma unroll
        for (int j = 0; j < NT; j++)
#pragma unroll
            for (int c = 0; c < 4; c++) acc[i][j][c] = 0.f;

    uint32_t acc16[4][NT][2];
    if (F16C && NPROD >= 2) {
#pragma unroll
        for (int i = 0; i < 4; i++)
#pragma unroll
            for (int j = 0; j < NT; j++) { acc16[i][j][0] = 0u; acc16[i][j][1] = 0u; }
    }

    auto compute_chunk = [&](uint32_t st) {
        const uint32_t aBh = st +          (uint32_t)warp_m * 64 * ROWB + aLane;
        const uint32_t aBl = st + A_ARR +  (uint32_t)warp_m * 64 * ROWB + aLane;
        const uint32_t bBh = st + BH_OFF + (uint32_t)(warp_n * (TN / 4)) * ROWB + bLane;
        const uint32_t bBl = st + BL_OFF + (uint32_t)(warp_n * (TN / 4)) * ROWB + bLane;
#pragma unroll
        for (int ks = 0; ks < KCH / 16; ks++) {
            const uint32_t ko = ks * 32;
            uint32_t aH[4][4], bH[NB][4];
#pragma unroll
            for (int mt = 0; mt < 4; mt++) ldsm4(aH[mt], aBh + mt * 16 * ROWB + ko);
#pragma unroll
            for (int np = 0; np < NB; np++) ldsm4(bH[np], bBh + np * 16 * ROWB + ko);
#pragma unroll
            for (int mt = 0; mt < 4; mt++)
#pragma unroll
                for (int nt = 0; nt < NT; nt++)
                    mma_f16(acc[mt][nt], aH[mt], &bH[nt >> 1][(nt & 1) * 2]);
            if (!F16C && NPROD == 3) {
                uint32_t aL[4][4];
#pragma unroll
                for (int mt = 0; mt < 4; mt++) ldsm4(aL[mt], aBl + mt * 16 * ROWB + ko);
#pragma unroll
                for (int mt = 0; mt < 4; mt++)
#pragma unroll
                    for (int nt = 0; nt < NT; nt++)
                        mma_f16(acc[mt][nt], aL[mt], &bH[nt >> 1][(nt & 1) * 2]);
            }
            if (NPROD >= 2) {
                uint32_t bL[NB][4];
#pragma unroll
                for (int np = 0; np < NB; np++) ldsm4(bL[np], bBl + np * 16 * ROWB + ko);
                if (F16C) {
#pragma unroll
                    for (int mt = 0; mt < 4; mt++)
#pragma unroll
                        for (int nt = 0; nt < NT; nt++)
                            mma_f16acc(acc16[mt][nt], aH[mt], &bL[nt >> 1][(nt & 1) * 2]);
                } else {
#pragma unroll
                    for (int mt = 0; mt < 4; mt++)
#pragma unroll
                        for (int nt = 0; nt < NT; nt++)
                            mma_f16(acc[mt][nt], aH[mt], &bL[nt >> 1][(nt & 1) * 2]);
                }
            }
        }
    };

    if (NSTG == 3) {
        load_chunk(0, 0);
        load_chunk(1, 1);
        for (int i = 0; i < nch; i++) {
            const uint32_t st = sb + (i % 3) * STGB;
            if (i + 1 < nch) cpa_wait<1>(); else cpa_wait<0>();
            __syncthreads();
            if (i + 2 < nch) load_chunk(i + 2, (i + 2) % 3);
            compute_chunk(st);
        }
    } else {
        load_chunk(0, 0);
        for (int i = 0; i < nch; i++) {
            const uint32_t st = sb + (i & 1) * STGB;
            cpa_wait<0>();
            __syncthreads();
            if (i + 1 < nch) load_chunk(i + 1, (i + 1) & 1);
            compute_chunk(st);
        }
    }

    // ---- epilogue ----
    const int gp = lane >> 2, tq = lane & 3;
    const int mbase = m0 + warp_m * 64;
    const int nbase = n0 + warp_n * (TN / 4);

#pragma unroll
    for (int mt = 0; mt < 4; mt++) {
#pragma unroll
        for (int half = 0; half < 2; half++) {
            const int r = mbase + mt * 16 + half * 8 + gp;
            if (mode >= 2) {
                __half* oh = Chi + (size_t)bz * c_batch + (size_t)r * Nld;
                __half* ol = Clo + (size_t)bz * c_batch + (size_t)r * Nld;
#pragma unroll
                for (int nt = 0; nt < NT; nt++) {
                    const int col = nbase + nt * 8 + 2 * tq;
                    float v0 = acc[mt][nt][half * 2];
                    float v1 = acc[mt][nt][half * 2 + 1];
                    if (F16C && NPROD >= 2) {
                        __half2 c = *reinterpret_cast<__half2*>(&acc16[mt][nt][half]);
                        v0 += __half2float(c.x);
                        v1 += __half2float(c.y);
                    }
                    uint32_t hi, lo;
                    split_pk(v0, v1, hi, lo);
                    *(uint32_t*)(oh + col) = hi;
                    if (mode == 2) *(uint32_t*)(ol + col) = lo;
                }
            } else {
                float* oc = Cf + (size_t)bz * c_batch + (size_t)r * Nld;
                if (mode == 1) {
                    const int ri = r >> 6, rj = r & 63;
#pragma unroll
                    for (int nt = 0; nt < NT; nt++) {
                        const int col = nbase + nt * 8 + 2 * tq;
                        float v0 = acc[mt][nt][half * 2];
                        float v1 = acc[mt][nt][half * 2 + 1];
                        if (F16C && NPROD >= 2) {
                            __half2 c = *reinterpret_cast<__half2*>(&acc16[mt][nt][half]);
                            v0 += __half2float(c.x);
                            v1 += __half2float(c.y);
                        }
                        int di0 = ri - (col >> 6);
                        int j0 = rj - (col & 63);
                        int j1 = rj - ((col + 1) & 63);
                        float2 o;
                        o.x = v0 * g_rdist[di0 * di0 + j0 * j0];
                        o.y = v1 * g_rdist[di0 * di0 + j1 * j1];
                        *(float2*)(oc + col) = o;
                    }
                } else {
#pragma unroll
                    for (int nt = 0; nt < NT; nt++) {
                        const int col = nbase + nt * 8 + 2 * tq;
                        float v0 = acc[mt][nt][half * 2];
                        float v1 = acc[mt][nt][half * 2 + 1];
                        if (F16C && NPROD >= 2) {
                            __half2 c = *reinterpret_cast<__half2*>(&acc16[mt][nt][half]);
                            v0 += __half2float(c.x);
                            v1 += __half2float(c.y);
                        }
                        float2 o; o.x = v0; o.y = v1;
                        *(float2*)(oc + col) = o;
                    }
                }
            }
        }
    }
}

// ---------------- prep kernels ----------------------------------------------
__global__ void init_rdist() {
    int i = blockIdx.x * 256 + threadIdx.x;
    if (i < 8192) g_rdist[i] = 1.0f / (sqrtf((float)i) + 1.0f);
}

// fp32 -> single fp16
__global__ void cvt_w(const float* __restrict__ w, __half* __restrict__ h, int n) {
    int i = blockIdx.x * 256 + threadIdx.x;
    if (i < n) h[i] = __float2half(w[i]);
}

// fp32 -> fp16 pair
__global__ void split_w(const float* __restrict__ w, __half* __restrict__ h,
                        __half* __restrict__ l, int n) {
    int i = blockIdx.x * 256 + threadIdx.x;
    if (i < n) {
        float v = w[i];
        __half hh = __float2half(v);
        h[i] = hh;
        l[i] = __float2half(v - __half2float(hh));
    }
}

// x[b][c][n] -> xs[b][n][c] as fp16 hi/lo
__global__ void split_transpose(const float* __restrict__ x) {
    __shared__ float t[32][33];
    const int b = blockIdx.z;
    const int n0 = blockIdx.x << 5, c0 = blockIdx.y << 5;
    const int tx = threadIdx.x, ty = threadIdx.y;
    const float* xp = x + ((size_t)b * CC + c0) * NN + n0;
#pragma unroll
    for (int i = 0; i < 4; i++) t[ty + i * 8][tx] = xp[(size_t)(ty + i * 8) * NN + tx];
    __syncthreads();
    const size_t ob = ((size_t)b * NN + n0) * CC + c0;
#pragma unroll
    for (int i = 0; i < 4; i++) {
        float v = t[tx][ty + i * 8];
        __half h = __float2half(v);
        size_t o = ob + (size_t)(ty + i * 8) * CC + tx;
        g_xs_h[o] = h;
        g_xs_l[o] = __float2half(v - __half2float(h));
    }
}

// row softmax, fp32 in -> single fp16 out
__global__ void softmax_f16(const float* __restrict__ rel) {
    __shared__ float red1[8], red2[8];
    const size_t row = blockIdx.x;
    const float4* p = (const float4*)(rel + row * (size_t)NN);
    const int tid = threadIdx.x;

    float4 v[4];
    float mx = -3.0e38f;
#pragma unroll
    for (int i = 0; i < 4; i++) {
        v[i] = p[tid + i * 256];
        mx = fmaxf(mx, fmaxf(fmaxf(v[i].x, v[i].y), fmaxf(v[i].z, v[i].w)));
    }
#pragma unroll
    for (int o = 16; o > 0; o >>= 1) mx = fmaxf(mx, __shfl_xor_sync(0xffffffffu, mx, o));
    if ((tid & 31) == 0) red1[tid >> 5] = mx;
    __syncthreads();
    mx = red1[0];
#pragma unroll
    for (int w = 1; w < 8; w++) mx = fmaxf(mx, red1[w]);

    float s = 0.f;
#pragma unroll
    for (int i = 0; i < 4; i++) {
        v[i].x = __expf(v[i].x - mx); v[i].y = __expf(v[i].y - mx);
        v[i].z = __expf(v[i].z - mx); v[i].w = __expf(v[i].w - mx);
        s += v[i].x + v[i].y + v[i].z + v[i].w;
    }
#pragma unroll
    for (int o = 16; o > 0; o >>= 1) s += __shfl_xor_sync(0xffffffffu, s, o);
    if ((tid & 31) == 0) red2[tid >> 5] = s;
    __syncthreads();
    s = 0.f;
#pragma unroll
    for (int w = 0; w < 8; w++) s += red2[w];
    const float inv = 1.0f / s;

    uint2* P = (uint2*)(g_P + row * (size_t)NN);
#pragma unroll
    for (int i = 0; i < 4; i++) {
        __half2 a, b;
        a.x = __float2half(v[i].x * inv); a.y = __float2half(v[i].y * inv);
        b.x = __float2half(v[i].z * inv); b.y = __float2half(v[i].w * inv);
        uint2 o;
        o.x = *reinterpret_cast<uint32_t*>(&a);
        o.y = *reinterpret_cast<uint32_t*>(&b);
        P[tid + i * 256] = o;
    }
}

// ---------------- BN ---------------------------------------------------------
__global__ void bn_stats(const float* __restrict__ u) {
    __shared__ float rs[8], rs2[8];
    const int c = blockIdx.x;
    const int tid = threadIdx.x;
    float s = 0.f, s2 = 0.f;
    for (int b = 0; b < BB; b++) {
        const float* up = u + ((size_t)b * CC + c) * NN;
        for (int n = tid; n < NN; n += 256) {
            float t = up[n];
            s += t; s2 += t * t;
        }
    }
#pragma unroll
    for (int o = 16; o > 0; o >>= 1) {
        s  += __shfl_xor_sync(0xffffffffu, s, o);
        s2 += __shfl_xor_sync(0xffffffffu, s2, o);
    }
    if ((tid & 31) == 0) { rs[tid >> 5] = s; rs2[tid >> 5] = s2; }
    __syncthreads();
    if (tid == 0) {
        float S = 0.f, S2 = 0.f;
#pragma unroll
        for (int w = 0; w < 8; w++) { S += rs[w]; S2 += rs2[w]; }
        const float cnt = (float)(BB * NN);
        float mean = S / cnt;
        float var = S2 / cnt - mean * mean;
        g_mean[c] = mean;
        g_rstd[c] = rsqrtf(var + 1e-5f);
    }
}

__global__ void bn_relu_kernel(const float* __restrict__ u, const float* __restrict__ x,
                               const float* __restrict__ gamma, const float* __restrict__ beta,
                               float* __restrict__ out) {
    size_t i4 = (size_t)blockIdx.x * blockDim.x + threadIdx.x;
    int c = (int)((i4 * 4 / NN) % CC);
    float m = g_mean[c];
    float r = g_rstd[c] * gamma[c];
    float bt = beta[c];
    float4 uu = ((const float4*)u)[i4];
    float4 xx = ((const float4*)x)[i4];
    float4 o;
    o.x = fmaxf((uu.x - m) * r + bt + xx.x, 0.f);
    o.y = fmaxf((uu.y - m) * r + bt + xx.y, 0.f);
    o.z = fmaxf((uu.z - m) * r + bt + xx.z, 0.f);
    o.w = fmaxf((uu.w - m) * r + bt + xx.w, 0.f);
    ((float4*)out)[i4] = o;
}

// ---------------- launch ------------------------------------------------------
extern "C" void kernel_launch(void* const* d_in, const int* in_sizes, int n_in,
                              void* d_out, int out_size)
{
    const float* x     = (const float*)d_in[0];
    const float* Wv    = (const float*)d_in[1];
    const float* Wq    = (const float*)d_in[2];
    const float* Wk    = (const float*)d_in[3];
    const float* Wu    = (const float*)d_in[4];
    const float* gamma = (const float*)d_in[5];
    const float* beta  = (const float*)d_in[6];
    float* out = (float*)d_out;

    __half *xs_h, *xs_l, *wv, *wqk_h, *wqk_l, *wu;
    __half *qk_h, *qk_l, *vT, *P, *y;
    float *rel, *u;
    cudaGetSymbolAddress((void**)&xs_h,  g_xs_h);  cudaGetSymbolAddress((void**)&xs_l,  g_xs_l);
    cudaGetSymbolAddress((void**)&wv,    g_wv);
    cudaGetSymbolAddress((void**)&wqk_h, g_wqk_h); cudaGetSymbolAddress((void**)&wqk_l, g_wqk_l);
    cudaGetSymbolAddress((void**)&wu,    g_wu);
    cudaGetSymbolAddress((void**)&qk_h,  g_qk_h);  cudaGetSymbolAddress((void**)&qk_l,  g_qk_l);
    cudaGetSymbolAddress((void**)&vT,    g_vT);
    cudaGetSymbolAddress((void**)&P,     g_P);
    cudaGetSymbolAddress((void**)&y,     g_y);
    cudaGetSymbolAddress((void**)&rel,   g_rel);
    cudaGetSymbolAddress((void**)&u,     g_u);

    // smem per CTA per instantiation
    const int SMEM_P1  = 3 * (128 * 144 + 128 * 144);          // 110592 (<128,true,2,1,3,64>)
    const int SMEM_QKd = 3 * (128 * 80 + 2 * 128 * 80);        // 92160  (<128,true,2,2,3,32>)
    const int SMEM_QK2 = 2 * (2 * 128 * 80 + 2 * 128 * 80);    // 81920  (<128,false,2,3,2,32>)
    cudaFuncSetAttribute(gemm_mma<128, true, 2, 1, 3, 64>,  cudaFuncAttributeMaxDynamicSharedMemorySize, SMEM_P1);
    cudaFuncSetAttribute(gemm_mma<128, true, 2, 2, 3, 32>,  cudaFuncAttributeMaxDynamicSharedMemorySize, SMEM_QKd);
    cudaFuncSetAttribute(gemm_mma<128, false, 2, 3, 2, 32>, cudaFuncAttributeMaxDynamicSharedMemorySize, SMEM_QK2);

    // ---- prep, ordered so the ncu capture (0-based launch #3) hits v-GEMM ----
    split_transpose<<<dim3(NN / 32, CC / 32, BB), dim3(32, 8)>>>(x);        // 0
    cvt_w<<<(CC * CC + 255) / 256, 256>>>(Wv, wv, CC * CC);                 // 1
    init_rdist<<<32, 256>>>();                                              // 2

    // 3: vT[b][o][m] = Wv[o][:] . xs[m][:]   M=CC, N=NN, K=CC
    //    single product, single fp16 out, K-chunk 64               <- ncu target
    gemm_mma<128, true, 2, 1, 3, 64><<<dim3(NN / 128, CC / 128, BB), 256, SMEM_P1>>>(
        wv, wv, xs_h, xs_h, CC, CC, CC, 0L, (long)NN * CC,
        nullptr, vT, vT, (long)CC * NN, NN, 3);

    split_w<<<(II * CC + 255) / 256, 256>>>(Wq, wqk_h, wqk_l, II * CC);
    split_w<<<(II * CC + 255) / 256, 256>>>(Wk, wqk_h + II * CC, wqk_l + II * CC, II * CC);
    cvt_w<<<(CC * CC + 255) / 256, 256>>>(Wu, wu, CC * CC);

    // qk[b][n][0:128]=q, [128:256]=k   M=NN, N=256, K=CC
    // 3-product fp32, 2-stage pipeline, 2 CTAs/SM
    gemm_mma<128, false, 2, 3, 2, 32><<<dim3(2, NN / 128, BB), 256, SMEM_QK2>>>(
        xs_h, xs_l, wqk_h, wqk_l, CC, CC, CC, (long)NN * CC, 0L,
        nullptr, qk_h, qk_l, (long)NN * 256, 256, 2);

    // rel[b][n][m] = (q[n].k[m]) / dist   M=NN, N=NN, K=II
    // 2-product: qh.kh (fp32) + qh.kl (f16 acc); q_l dropped. 2 CTAs/SM.
    gemm_mma<128, true, 2, 2, 3, 32><<<dim3(NN / 128, NN / 128, BB), 256, SMEM_QKd>>>(
        qk_h, qk_h, qk_h + II, qk_l + II, II, 256, 256,
        (long)NN * 256, (long)NN * 256,
        rel, nullptr, nullptr, (long)NN * NN, NN, 1);

    // softmax rows -> P (single fp16)
    softmax_f16<<<BB * NN, 256>>>(rel);

    // y[b][n][o] = P[n][:] . vT[o][:]   M=NN, N=CC, K=NN  (single product, K-chunk 64)
    gemm_mma<128, true, 2, 1, 3, 64><<<dim3(CC / 128, NN / 128, BB), 256, SMEM_P1>>>(
        P, P, vT, vT, NN, NN, NN, (long)NN * NN, (long)CC * NN,
        nullptr, y, y, (long)NN * CC, CC, 3);

    // u[b][o][n] = Wu[o][:] . y[n][:]   M=CC, N=NN, K=CC  (single product, K-chunk 64)
    gemm_mma<128, true, 2, 1, 3, 64><<<dim3(NN / 128, CC / 128, BB), 256, SMEM_P1>>>(
        wu, wu, y, y, CC, CC, CC, 0L, (long)NN * CC,
        u, nullptr, nullptr, (long)CC * NN, NN, 0);

    bn_stats<<<CC, 256>>>(u);
    bn_relu_kernel<<<(int)(((size_t)BB * CC * NN / 4) / 256), 256>>>(u, x, gamma, beta, out);
}

// round 17
// speedup vs baseline: 2.4891x; 1.0354x over previous
#include <cuda_runtime.h>
#include <cuda_fp16.h>
#include <stdint.h>

#define BB 8
#define CC 512
#define NN 4096
#define II 128

// ---------------- scratch (__device__ globals; no allocation allowed) -------
__device__ __half g_xs_h[(size_t)BB * NN * CC];
__device__ __half g_xs_l[(size_t)BB * NN * CC];
__device__ __half g_wv[CC * CC];                       // single fp16
__device__ __half g_wqk[2 * II * CC];                  // Wq rows 0..127, Wk 128..255 (single fp16)
__device__ __half g_wu[CC * CC];                       // single fp16
__device__ __half g_qk_h[(size_t)BB * NN * 256], g_qk_l[(size_t)BB * NN * 256];
__device__ __half g_vT[(size_t)BB * CC * NN];          // single fp16
__device__ float  g_rel[(size_t)BB * NN * NN];
__device__ __half g_P[(size_t)BB * NN * NN];           // single fp16 probabilities
__device__ __half g_y[(size_t)BB * NN * CC];           // single fp16
__device__ float  g_u[(size_t)BB * CC * NN];
__device__ float g_mean[CC], g_rstd[CC];
__device__ float g_rdist[8192];   // 1/(sqrt(d2)+1), d2 <= 2*63^2

// ---------------- PTX helpers (portable, non-'a' features only) -------------
__device__ __forceinline__ uint32_t s2u(const void* p) {
    uint32_t a;
    asm("{ .reg .u64 t; cvta.to.shared.u64 t, %1; cvt.u32.u64 %0, t; }" : "=r"(a) : "l"(p));
    return a;
}
__device__ __forceinline__ void cpa16(uint32_t s, const void* g) {
    asm volatile("cp.async.cg.shared.global [%0], [%1], 16;" :: "r"(s), "l"(g) : "memory");
}
__device__ __forceinline__ void cpa_commit() { asm volatile("cp.async.commit_group;" ::: "memory"); }
template <int W> __device__ __forceinline__ void cpa_wait() {
    asm volatile("cp.async.wait_group %0;" :: "n"(W) : "memory");
}
__device__ __forceinline__ void ldsm4(uint32_t* r, uint32_t addr) {
    asm volatile("ldmatrix.sync.aligned.m8n8.x4.shared.b16 {%0,%1,%2,%3}, [%4];"
                 : "=r"(r[0]), "=r"(r[1]), "=r"(r[2]), "=r"(r[3]) : "r"(addr));
}
__device__ __forceinline__ void mma_f16(float* d, const uint32_t* a, const uint32_t* b) {
    asm volatile(
        "mma.sync.aligned.m16n8k16.row.col.f32.f16.f16.f32 "
        "{%0,%1,%2,%3}, {%4,%5,%6,%7}, {%8,%9}, {%0,%1,%2,%3};"
        : "+f"(d[0]), "+f"(d[1]), "+f"(d[2]), "+f"(d[3])
        : "r"(a[0]), "r"(a[1]), "r"(a[2]), "r"(a[3]), "r"(b[0]), "r"(b[1]));
}
// fp16-accumulator MMA for correction products
__device__ __forceinline__ void mma_f16acc(uint32_t* d, const uint32_t* a, const uint32_t* b) {
    asm volatile(
        "mma.sync.aligned.m16n8k16.row.col.f16.f16.f16.f16 "
        "{%0,%1}, {%2,%3,%4,%5}, {%6,%7}, {%0,%1};"
        : "+r"(d[0]), "+r"(d[1])
        : "r"(a[0]), "r"(a[1]), "r"(a[2]), "r"(a[3]), "r"(b[0]), "r"(b[1]));
}
__device__ __forceinline__ void split_pk(float a, float b, uint32_t& hi, uint32_t& lo) {
    __half2 h, l;
    h.x = __float2half(a); h.y = __float2half(b);
    l.x = __float2half(a - __half2float(h.x));
    l.y = __float2half(b - __half2float(h.y));
    hi = *reinterpret_cast<uint32_t*>(&h);
    lo = *reinterpret_cast<uint32_t*>(&l);
}

// ---------------- split-fp16 HMMA GEMM ---------------------------------------
// C[M,N] = A[M,K] * B[N,K]^T ; operands fp16, K-major, leading dims lda/ldb.
// CTA tile 128 x TN, 8 warps (2m x 4n), warp tile 64 x TN/4.
// NPROD==3 (!F16C): aH*bH + aL*bH + aH*bL, all fp32-acc (A,B are hi/lo pairs)
// NPROD==2 (F16C) : aH*bH fp32-acc + aH*bL fp16-acc correction (A single)
// NPROD==1        : aH*bH only (single x single)
// MINB: min blocks/SM.  NSTG: pipeline stages (2 or 3).  KCH: K-chunk (32/64).
// modes: 0 = fp32, 1 = fp32 * (1/dist), 2 = fp16 (hi,lo) pair, 3 = fp16 single.
template <int TN, bool F16C, int MINB, int NPROD, int NSTG, int KCH>
__global__ void __launch_bounds__(256, MINB)
gemm_mma(const __half* __restrict__ Ah_, const __half* __restrict__ Al_,
         const __half* __restrict__ Bh_, const __half* __restrict__ Bl_,
         int K, int lda, int ldb, long a_batch, long b_batch,
         float* __restrict__ Cf,
         __half* __restrict__ Chi, __half* __restrict__ Clo,
         long c_batch, int Nld, int mode)
{
    constexpr int ROWB = (KCH == 32) ? 80 : 144;   // padded row stride bytes
    constexpr int A_ARR = 128 * ROWB;
    constexpr int B_ARR = TN * ROWB;
    constexpr int BH_OFF = A_ARR * ((!F16C && NPROD == 3) ? 2 : 1);
    constexpr int BL_OFF = BH_OFF + B_ARR;
    constexpr int STGB = BH_OFF + B_ARR * (NPROD >= 2 ? 2 : 1);  // bytes per stage
    constexpr int NT = TN / 32;                   // 8-col n-tiles per warp
    constexpr int NB = TN / 64;                   // B ldsm.x4 loads per warp
    constexpr int SEC = KCH / 8;                  // 16B sectors per row

    extern __shared__ char smem[];
    const uint32_t sb = s2u(smem);
    const int tid = threadIdx.x;
    const int wid = tid >> 5;
    const int lane = tid & 31;
    const int bz = blockIdx.z;
    const int m0 = blockIdx.y * 128;
    const int n0 = blockIdx.x * TN;
    const int warp_m = wid >> 2;     // 0..1 -> 64 rows each
    const int warp_n = wid & 3;      // 0..3 -> TN/4 cols each

    const __half* Ah = Ah_ + (size_t)bz * a_batch + (size_t)m0 * lda;
    const __half* Al = Al_ + (size_t)bz * a_batch + (size_t)m0 * lda;
    const __half* Bh = Bh_ + (size_t)bz * b_batch + (size_t)n0 * ldb;
    const __half* Bl = Bl_ + (size_t)bz * b_batch + (size_t)n0 * ldb;

    const int nch = K / KCH;

    auto load_chunk = [&](int ci, int stg) {
        const uint32_t st = sb + stg * STGB;
        const size_t k0 = (size_t)ci * KCH;
#pragma unroll
        for (int p = 0; p < 128 * SEC / 256; p++) {     // A: 128 rows x SEC sectors
            int f = tid + p * 256;
            int r = f / SEC, s = f % SEC;
            uint32_t so = (uint32_t)r * ROWB + s * 16;
            size_t go = (size_t)r * lda + k0 + s * 8;
            cpa16(st + so, Ah + go);
            if (!F16C && NPROD == 3) cpa16(st + A_ARR + so, Al + go);
        }
#pragma unroll
        for (int p = 0; p < TN * SEC / 256; p++) {      // B: TN rows x SEC sectors
            int f = tid + p * 256;
            int r = f / SEC, s = f % SEC;
            uint32_t so = (uint32_t)r * ROWB + s * 16;
            size_t go = (size_t)r * ldb + k0 + s * 8;
            cpa16(st + BH_OFF + so, Bh + go);
            if (NPROD >= 2) cpa16(st + BL_OFF + so, Bl + go);
        }
        cpa_commit();
    };

    // lane offsets for ldmatrix (bytes)
    const int lt = lane & 7, ltile = lane >> 3;
    const uint32_t aLane = (uint32_t)(lt + ((ltile & 1) << 3)) * ROWB + ((ltile >> 1) << 4);
    const uint32_t bLane = (uint32_t)(lt + ((ltile >> 1) << 3)) * ROWB + ((ltile & 1) << 4);

    float acc[4][NT][4];
#pragma unroll
    for (int i = 0; i < 4; i++)
#pragma unroll
        for (int j = 0; j < NT; j++)
#pragma unroll
            for (int c = 0; c < 4; c++) acc[i][j][c] = 0.f;

    uint32_t acc16[4][NT][2];
    if (F16C && NPROD >= 2) {
#pragma unroll
        for (int i = 0; i < 4; i++)
#pragma unroll
            for (int j = 0; j < NT; j++) { acc16[i][j][0] = 0u; acc16[i][j][1] = 0u; }
    }

    auto compute_chunk = [&](uint32_t st) {
        const uint32_t aBh = st +          (uint32_t)warp_m * 64 * ROWB + aLane;
        const uint32_t aBl = st + A_ARR +  (uint32_t)warp_m * 64 * ROWB + aLane;
        const uint32_t bBh = st + BH_OFF + (uint32_t)(warp_n * (TN / 4)) * ROWB + bLane;
        const uint32_t bBl = st + BL_OFF + (uint32_t)(warp_n * (TN / 4)) * ROWB + bLane;
#pragma unroll
        for (int ks = 0; ks < KCH / 16; ks++) {
            const uint32_t ko = ks * 32;
            uint32_t aH[4][4], bH[NB][4];
#pragma unroll
            for (int mt = 0; mt < 4; mt++) ldsm4(aH[mt], aBh + mt * 16 * ROWB + ko);
#pragma unroll
            for (int np = 0; np < NB; np++) ldsm4(bH[np], bBh + np * 16 * ROWB + ko);
#pragma unroll
            for (int mt = 0; mt < 4; mt++)
#pragma unroll
                for (int nt = 0; nt < NT; nt++)
                    mma_f16(acc[mt][nt], aH[mt], &bH[nt >> 1][(nt & 1) * 2]);
            if (!F16C && NPROD == 3) {
                uint32_t aL[4][4];
#pragma unroll
                for (int mt = 0; mt < 4; mt++) ldsm4(aL[mt], aBl + mt * 16 * ROWB + ko);
#pragma unroll
                for (int mt = 0; mt < 4; mt++)
#pragma unroll
                    for (int nt = 0; nt < NT; nt++)
                        mma_f16(acc[mt][nt], aL[mt], &bH[nt >> 1][(nt & 1) * 2]);
            }
            if (NPROD >= 2) {
                uint32_t bL[NB][4];
#pragma unroll
                for (int np = 0; np < NB; np++) ldsm4(bL[np], bBl + np * 16 * ROWB + ko);
                if (F16C) {
#pragma unroll
                    for (int mt = 0; mt < 4; mt++)
#pragma unroll
                        for (int nt = 0; nt < NT; nt++)
                            mma_f16acc(acc16[mt][nt], aH[mt], &bL[nt >> 1][(nt & 1) * 2]);
                } else {
#pragma unroll
                    for (int mt = 0; mt < 4; mt++)
#pragma unroll
                        for (int nt = 0; nt < NT; nt++)
                            mma_f16(acc[mt][nt], aH[mt], &bL[nt >> 1][(nt & 1) * 2]);
                }
            }
        }
    };

    if (NSTG == 3) {
        load_chunk(0, 0);
        load_chunk(1, 1);
        for (int i = 0; i < nch; i++) {
            const uint32_t st = sb + (i % 3) * STGB;
            if (i + 1 < nch) cpa_wait<1>(); else cpa_wait<0>();
            __syncthreads();
            if (i + 2 < nch) load_chunk(i + 2, (i + 2) % 3);
            compute_chunk(st);
        }
    } else {
        load_chunk(0, 0);
        for (int i = 0; i < nch; i++) {
            const uint32_t st = sb + (i & 1) * STGB;
            cpa_wait<0>();
            __syncthreads();
            if (i + 1 < nch) load_chunk(i + 1, (i + 1) & 1);
            compute_chunk(st);
        }
    }

    // ---- epilogue ----
    const int gp = lane >> 2, tq = lane & 3;
    const int mbase = m0 + warp_m * 64;
    const int nbase = n0 + warp_n * (TN / 4);

#pragma unroll
    for (int mt = 0; mt < 4; mt++) {
#pragma unroll
        for (int half = 0; half < 2; half++) {
            const int r = mbase + mt * 16 + half * 8 + gp;
            if (mode >= 2) {
                __half* oh = Chi + (size_t)bz * c_batch + (size_t)r * Nld;
                __half* ol = Clo + (size_t)bz * c_batch + (size_t)r * Nld;
#pragma unroll
                for (int nt = 0; nt < NT; nt++) {
                    const int col = nbase + nt * 8 + 2 * tq;
                    float v0 = acc[mt][nt][half * 2];
                    float v1 = acc[mt][nt][half * 2 + 1];
                    if (F16C && NPROD >= 2) {
                        __half2 c = *reinterpret_cast<__half2*>(&acc16[mt][nt][half]);
                        v0 += __half2float(c.x);
                        v1 += __half2float(c.y);
                    }
                    uint32_t hi, lo;
                    split_pk(v0, v1, hi, lo);
                    *(uint32_t*)(oh + col) = hi;
                    if (mode == 2) *(uint32_t*)(ol + col) = lo;
                }
            } else {
                float* oc = Cf + (size_t)bz * c_batch + (size_t)r * Nld;
                if (mode == 1) {
                    const int ri = r >> 6, rj = r & 63;
#pragma unroll
                    for (int nt = 0; nt < NT; nt++) {
                        const int col = nbase + nt * 8 + 2 * tq;
                        float v0 = acc[mt][nt][half * 2];
                        float v1 = acc[mt][nt][half * 2 + 1];
                        if (F16C && NPROD >= 2) {
                            __half2 c = *reinterpret_cast<__half2*>(&acc16[mt][nt][half]);
                            v0 += __half2float(c.x);
                            v1 += __half2float(c.y);
                        }
                        int di0 = ri - (col >> 6);
                        int j0 = rj - (col & 63);
                        int j1 = rj - ((col + 1) & 63);
                        float2 o;
                        o.x = v0 * g_rdist[di0 * di0 + j0 * j0];
                        o.y = v1 * g_rdist[di0 * di0 + j1 * j1];
                        *(float2*)(oc + col) = o;
                    }
                } else {
#pragma unroll
                    for (int nt = 0; nt < NT; nt++) {
                        const int col = nbase + nt * 8 + 2 * tq;
                        float v0 = acc[mt][nt][half * 2];
                        float v1 = acc[mt][nt][half * 2 + 1];
                        if (F16C && NPROD >= 2) {
                            __half2 c = *reinterpret_cast<__half2*>(&acc16[mt][nt][half]);
                            v0 += __half2float(c.x);
                            v1 += __half2float(c.y);
                        }
                        float2 o; o.x = v0; o.y = v1;
                        *(float2*)(oc + col) = o;
                    }
                }
            }
        }
    }
}

// ---------------- prep kernels ----------------------------------------------
__global__ void init_rdist() {
    int i = blockIdx.x * 256 + threadIdx.x;
    if (i < 8192) g_rdist[i] = 1.0f / (sqrtf((float)i) + 1.0f);
}

// fp32 -> single fp16
__global__ void cvt_w(const float* __restrict__ w, __half* __restrict__ h, int n) {
    int i = blockIdx.x * 256 + threadIdx.x;
    if (i < n) h[i] = __float2half(w[i]);
}

// x[b][c][n] -> xs[b][n][c] as fp16 hi/lo
__global__ void split_transpose(const float* __restrict__ x) {
    __shared__ float t[32][33];
    const int b = blockIdx.z;
    const int n0 = blockIdx.x << 5, c0 = blockIdx.y << 5;
    const int tx = threadIdx.x, ty = threadIdx.y;
    const float* xp = x + ((size_t)b * CC + c0) * NN + n0;
#pragma unroll
    for (int i = 0; i < 4; i++) t[ty + i * 8][tx] = xp[(size_t)(ty + i * 8) * NN + tx];
    __syncthreads();
    const size_t ob = ((size_t)b * NN + n0) * CC + c0;
#pragma unroll
    for (int i = 0; i < 4; i++) {
        float v = t[tx][ty + i * 8];
        __half h = __float2half(v);
        size_t o = ob + (size_t)(ty + i * 8) * CC + tx;
        g_xs_h[o] = h;
        g_xs_l[o] = __float2half(v - __half2float(h));
    }
}

// row softmax, fp32 in -> single fp16 out
__global__ void softmax_f16(const float* __restrict__ rel) {
    __shared__ float red1[8], red2[8];
    const size_t row = blockIdx.x;
    const float4* p = (const float4*)(rel + row * (size_t)NN);
    const int tid = threadIdx.x;

    float4 v[4];
    float mx = -3.0e38f;
#pragma unroll
    for (int i = 0; i < 4; i++) {
        v[i] = p[tid + i * 256];
        mx = fmaxf(mx, fmaxf(fmaxf(v[i].x, v[i].y), fmaxf(v[i].z, v[i].w)));
    }
#pragma unroll
    for (int o = 16; o > 0; o >>= 1) mx = fmaxf(mx, __shfl_xor_sync(0xffffffffu, mx, o));
    if ((tid & 31) == 0) red1[tid >> 5] = mx;
    __syncthreads();
    mx = red1[0];
#pragma unroll
    for (int w = 1; w < 8; w++) mx = fmaxf(mx, red1[w]);

    float s = 0.f;
#pragma unroll
    for (int i = 0; i < 4; i++) {
        v[i].x = __expf(v[i].x - mx); v[i].y = __expf(v[i].y - mx);
        v[i].z = __expf(v[i].z - mx); v[i].w = __expf(v[i].w - mx);
        s += v[i].x + v[i].y + v[i].z + v[i].w;
    }
#pragma unroll
    for (int o = 16; o > 0; o >>= 1) s += __shfl_xor_sync(0xffffffffu, s, o);
    if ((tid & 31) == 0) red2[tid >> 5] = s;
    __syncthreads();
    s = 0.f;
#pragma unroll
    for (int w = 0; w < 8; w++) s += red2[w];
    const float inv = 1.0f / s;

    uint2* P = (uint2*)(g_P + row * (size_t)NN);
#pragma unroll
    for (int i = 0; i < 4; i++) {
        __half2 a, b;
        a.x = __float2half(v[i].x * inv); a.y = __float2half(v[i].y * inv);
        b.x = __float2half(v[i].z * inv); b.y = __float2half(v[i].w * inv);
        uint2 o;
        o.x = *reinterpret_cast<uint32_t*>(&a);
        o.y = *reinterpret_cast<uint32_t*>(&b);
        P[tid + i * 256] = o;
    }
}

// ---------------- BN ---------------------------------------------------------
__global__ void bn_stats(const float* __restrict__ u) {
    __shared__ float rs[8], rs2[8];
    const int c = blockIdx.x;
    const int tid = threadIdx.x;
    float s = 0.f, s2 = 0.f;
    for (int b = 0; b < BB; b++) {
        const float* up = u + ((size_t)b * CC + c) * NN;
        for (int n = tid; n < NN; n += 256) {
            float t = up[n];
            s += t; s2 += t * t;
        }
    }
#pragma unroll
    for (int o = 16; o > 0; o >>= 1) {
        s  += __shfl_xor_sync(0xffffffffu, s, o);
        s2 += __shfl_xor_sync(0xffffffffu, s2, o);
    }
    if ((tid & 31) == 0) { rs[tid >> 5] = s; rs2[tid >> 5] = s2; }
    __syncthreads();
    if (tid == 0) {
        float S = 0.f, S2 = 0.f;
#pragma unroll
        for (int w = 0; w < 8; w++) { S += rs[w]; S2 += rs2[w]; }
        const float cnt = (float)(BB * NN);
        float mean = S / cnt;
        float var = S2 / cnt - mean * mean;
        g_mean[c] = mean;
        g_rstd[c] = rsqrtf(var + 1e-5f);
    }
}

__global__ void bn_relu_kernel(const float* __restrict__ u, const float* __restrict__ x,
                               const float* __restrict__ gamma, const float* __restrict__ beta,
                               float* __restrict__ out) {
    size_t i4 = (size_t)blockIdx.x * blockDim.x + threadIdx.x;
    int c = (int)((i4 * 4 / NN) % CC);
    float m = g_mean[c];
    float r = g_rstd[c] * gamma[c];
    float bt = beta[c];
    float4 uu = ((const float4*)u)[i4];
    float4 xx = ((const float4*)x)[i4];
    float4 o;
    o.x = fmaxf((uu.x - m) * r + bt + xx.x, 0.f);
    o.y = fmaxf((uu.y - m) * r + bt + xx.y, 0.f);
    o.z = fmaxf((uu.z - m) * r + bt + xx.z, 0.f);
    o.w = fmaxf((uu.w - m) * r + bt + xx.w, 0.f);
    ((float4*)out)[i4] = o;
}

// ---------------- launch ------------------------------------------------------
extern "C" void kernel_launch(void* const* d_in, const int* in_sizes, int n_in,
                              void* d_out, int out_size)
{
    const float* x     = (const float*)d_in[0];
    const float* Wv    = (const float*)d_in[1];
    const float* Wq    = (const float*)d_in[2];
    const float* Wk    = (const float*)d_in[3];
    const float* Wu    = (const float*)d_in[4];
    const float* gamma = (const float*)d_in[5];
    const float* beta  = (const float*)d_in[6];
    float* out = (float*)d_out;

    __half *xs_h, *xs_l, *wv, *wqk, *wu;
    __half *qk_h, *qk_l, *vT, *P, *y;
    float *rel, *u;
    cudaGetSymbolAddress((void**)&xs_h,  g_xs_h);  cudaGetSymbolAddress((void**)&xs_l,  g_xs_l);
    cudaGetSymbolAddress((void**)&wv,    g_wv);
    cudaGetSymbolAddress((void**)&wqk,   g_wqk);
    cudaGetSymbolAddress((void**)&wu,    g_wu);
    cudaGetSymbolAddress((void**)&qk_h,  g_qk_h);  cudaGetSymbolAddress((void**)&qk_l,  g_qk_l);
    cudaGetSymbolAddress((void**)&vT,    g_vT);
    cudaGetSymbolAddress((void**)&P,     g_P);
    cudaGetSymbolAddress((void**)&y,     g_y);
    cudaGetSymbolAddress((void**)&rel,   g_rel);
    cudaGetSymbolAddress((void**)&u,     g_u);

    // smem per CTA per instantiation
    const int SMEM_P1  = 3 * (128 * 144 + 128 * 144);          // 110592 (<128,true,2,1,3,64>)
    const int SMEM_QK  = 2 * (128 * 144 + 2 * 128 * 144);      // 110592 (<128,true,2,2,2,64>)
    cudaFuncSetAttribute(gemm_mma<128, true, 2, 1, 3, 64>, cudaFuncAttributeMaxDynamicSharedMemorySize, SMEM_P1);
    cudaFuncSetAttribute(gemm_mma<128, true, 2, 2, 2, 64>, cudaFuncAttributeMaxDynamicSharedMemorySize, SMEM_QK);

    // ---- prep, ordered so the ncu capture (0-based launch #3) hits v-GEMM ----
    split_transpose<<<dim3(NN / 32, CC / 32, BB), dim3(32, 8)>>>(x);        // 0
    cvt_w<<<(CC * CC + 255) / 256, 256>>>(Wv, wv, CC * CC);                 // 1
    init_rdist<<<32, 256>>>();                                              // 2

    // 3: vT[b][o][m] = Wv[o][:] . xs[m][:]   M=CC, N=NN, K=CC
    //    single product, single fp16 out, K-chunk 64               <- ncu target
    gemm_mma<128, true, 2, 1, 3, 64><<<dim3(NN / 128, CC / 128, BB), 256, SMEM_P1>>>(
        wv, wv, xs_h, xs_h, CC, CC, CC, 0L, (long)NN * CC,
        nullptr, vT, vT, (long)CC * NN, NN, 3);

    cvt_w<<<(II * CC + 255) / 256, 256>>>(Wq, wqk, II * CC);
    cvt_w<<<(II * CC + 255) / 256, 256>>>(Wk, wqk + II * CC, II * CC);
    cvt_w<<<(CC * CC + 255) / 256, 256>>>(Wu, wu, CC * CC);

    // qk[b][n][0:128]=q, [128:256]=k   M=NN, N=256, K=CC
    // single product (xs_h . wqk), fp32 acc -> (hi,lo) pair output.
    // The lo output carries the computed q/k's sub-fp16 bits, consumed by QK.
    gemm_mma<128, true, 2, 1, 3, 64><<<dim3(2, NN / 128, BB), 256, SMEM_P1>>>(
        xs_h, xs_h, wqk, wqk, CC, CC, CC, (long)NN * CC, 0L,
        nullptr, qk_h, qk_l, (long)NN * 256, 256, 2);

    // rel[b][n][m] = (q[n].k[m]) / dist   M=NN, N=NN, K=II
    // 2-product: qh.kh (fp32) + qh.kl (f16 acc); q_l dropped. KCH=64, 2-stage.
    gemm_mma<128, true, 2, 2, 2, 64><<<dim3(NN / 128, NN / 128, BB), 256, SMEM_QK>>>(
        qk_h, qk_h, qk_h + II, qk_l + II, II, 256, 256,
        (long)NN * 256, (long)NN * 256,
        rel, nullptr, nullptr, (long)NN * NN, NN, 1);

    // softmax rows -> P (single fp16)
    softmax_f16<<<BB * NN, 256>>>(rel);

    // y[b][n][o] = P[n][:] . vT[o][:]   M=NN, N=CC, K=NN  (single product, K-chunk 64)
    gemm_mma<128, true, 2, 1, 3, 64><<<dim3(CC / 128, NN / 128, BB), 256, SMEM_P1>>>(
        P, P, vT, vT, NN, NN, NN, (long)NN * NN, (long)CC * NN,
        nullptr, y, y, (long)NN * CC, CC, 3);

    // u[b][o][n] = Wu[o][:] . y[n][:]   M=CC, N=NN, K=CC  (single product, K-chunk 64)
    gemm_mma<128, true, 2, 1, 3, 64><<<dim3(NN / 128, CC / 128, BB), 256, SMEM_P1>>>(
        wu, wu, y, y, CC, CC, CC, 0L, (long)NN * CC,
        u, nullptr, nullptr, (long)CC * NN, NN, 0);

    bn_stats<<<CC, 256>>>(u);
    bn_relu_kernel<<<(int)(((size_t)BB * CC * NN / 4) / 256), 256>>>(u, x, gamma, beta, out);
}